// round 9
// baseline (speedup 1.0000x reference)
#include <cuda_runtime.h>
#include <cuda_bf16.h>
#include <math.h>
#include <stdint.h>

// ---------------------------------------------------------------------------
// Problem constants
// ---------------------------------------------------------------------------
#define N_NODES 20000
#define N_EDGES 320000
#define TOT_E   (N_EDGES + N_NODES)
#define N_GRAPHS 128
#define NEG_SLOPE 0.2f
#define EPS_F 1e-16f

#define HC1 320   // H=5, C=64
#define HC2 480   // H=5, C=96
#define HC3 32    // H=1, C=32

#define N_BLK ((N_NODES + 255) / 256)   // 79

// ---------------------------------------------------------------------------
// Device scratch
// ---------------------------------------------------------------------------
__device__ __align__(16) __nv_bfloat16 g_xq[N_NODES * 64];
__device__ __align__(16) __nv_bfloat16 g_w1q[HC1 * 64];
__device__ __align__(16) __nv_bfloat16 g_w2q[HC2 * HC1];
__device__ __align__(16) __nv_bfloat16 g_w3q[HC3 * HC2];
__device__ __align__(16) __nv_bfloat16 g_h1[N_NODES * HC1];
__device__ __align__(16) __nv_bfloat16 g_o1[N_NODES * HC1];
__device__ __align__(16) __nv_bfloat16 g_h2[N_NODES * HC2];
__device__ __align__(16) __nv_bfloat16 g_o2[N_NODES * HC2];
__device__ __align__(16) __nv_bfloat16 g_h3[N_NODES * HC3];
__device__ float g_att[6 * N_NODES * 5];
// contiguous zero region: cnt (N_NODES ints) + pool (N_GRAPHS*32 floats)
__device__ int   g_zero[N_NODES + N_GRAPHS * 32];
__device__ int   g_rowptr[N_NODES + 1];
__device__ int   g_cursor[N_NODES];
__device__ int   g_csrc[TOT_E];
__device__ int   g_bsum[N_BLK];

__device__ __forceinline__ uint32_t pack_bf16x2(float lo, float hi) {
    __nv_bfloat162 h2 = __floats2bfloat162_rn(lo, hi);
    return *(uint32_t*)&h2;
}

// ---------------------------------------------------------------------------
// prep: x -> bf16, W1/2/3 -> bf16, zero att accumulators
// ---------------------------------------------------------------------------
#define W1Q4 (HC1 * 64 / 4)       // 5120
#define W2Q4 (HC2 * HC1 / 4)      // 38400
#define W3Q4 (HC3 * HC2 / 4)      // 3840

__global__ void prep_kernel(const float* __restrict__ x,
                            const float* __restrict__ W1,
                            const float* __restrict__ W2,
                            const float* __restrict__ W3) {
    int i = blockIdx.x * 256 + threadIdx.x;
    if (i < N_NODES * 64 / 4) {
        float4 v = ((const float4*)x)[i];
        uint2 p;
        p.x = pack_bf16x2(v.x, v.y);
        p.y = pack_bf16x2(v.z, v.w);
        ((uint2*)g_xq)[i] = p;
    }
    if (2 * i < 6 * N_NODES * 5) {
        g_att[2 * i] = 0.f;
        if (2 * i + 1 < 6 * N_NODES * 5) g_att[2 * i + 1] = 0.f;
    }
    if (i < W1Q4 + W2Q4 + W3Q4) {
        const float4* src;
        uint2* dst;
        int j = i;
        if (j < W1Q4)                { src = (const float4*)W1; dst = (uint2*)g_w1q; }
        else if ((j -= W1Q4) < W2Q4) { src = (const float4*)W2; dst = (uint2*)g_w2q; }
        else { j -= W2Q4;              src = (const float4*)W3; dst = (uint2*)g_w3q; }
        float4 v = src[j];
        uint2 p;
        p.x = pack_bf16x2(v.x, v.y);
        p.y = pack_bf16x2(v.z, v.w);
        dst[j] = p;
    }
}

// ---------------------------------------------------------------------------
// CSR construction
// ---------------------------------------------------------------------------
__global__ void count_kernel(const int* __restrict__ ei) {
    int i = blockIdx.x * blockDim.x + threadIdx.x;
    if (i < N_EDGES) atomicAdd(&g_zero[ei[N_EDGES + i]], 1);
}

__global__ void scan1_kernel() {
    int i = blockIdx.x * 256 + threadIdx.x;
    int lane = threadIdx.x & 31, w = threadIdx.x >> 5;
    int x = (i < N_NODES) ? (g_zero[i] + 1) : 0;
#pragma unroll
    for (int o = 1; o < 32; o <<= 1) {
        int t = __shfl_up_sync(0xffffffffu, x, o);
        if (lane >= o) x += t;
    }
    __shared__ int wsum[8];
    if (lane == 31) wsum[w] = x;
    __syncthreads();
    if (w == 0) {
        int s = (lane < 8) ? wsum[lane] : 0;
#pragma unroll
        for (int o = 1; o < 8; o <<= 1) {
            int t = __shfl_up_sync(0xffffffffu, s, o);
            if (lane >= o) s += t;
        }
        if (lane < 8) wsum[lane] = s;
    }
    __syncthreads();
    int incl = x + ((w > 0) ? wsum[w - 1] : 0);
    if (i < N_NODES) g_rowptr[i + 1] = incl;
    if (threadIdx.x == 255) g_bsum[blockIdx.x] = incl;
}

__global__ void scan3_kernel() {
    __shared__ int s_off;
    int tid = threadIdx.x, lane = tid & 31;
    if (tid < 32) {
        int off = 0;
        for (int j = lane; j < blockIdx.x; j += 32) off += g_bsum[j];
#pragma unroll
        for (int o = 16; o > 0; o >>= 1)
            off += __shfl_xor_sync(0xffffffffu, off, o);
        if (lane == 0) s_off = off;
    }
    __syncthreads();
    int i = blockIdx.x * 256 + tid;
    if (i == 0) g_rowptr[0] = 0;
    if (i < N_NODES) {
        int incl = g_rowptr[i + 1] + s_off;
        g_rowptr[i + 1] = incl;
        g_cursor[i] = incl - (g_zero[i] + 1);
    }
}

__global__ void scatter_kernel(const int* __restrict__ ei) {
    int i = blockIdx.x * blockDim.x + threadIdx.x;
    if (i >= TOT_E) return;
    int src, dst;
    if (i < N_EDGES) { src = ei[i]; dst = ei[N_EDGES + i]; }
    else             { src = dst = i - N_EDGES; }
    int pos = atomicAdd(&g_cursor[dst], 1);
    g_csrc[pos] = src;
}

// ---------------------------------------------------------------------------
// bf16 GEMM (cp.async pipeline) + fused attention-score epilogue. (unchanged)
// ---------------------------------------------------------------------------
#define SROW 20

__device__ __forceinline__ void cp16(uint32_t dst, const void* src, int bytes) {
    asm volatile("cp.async.cg.shared.global [%0], [%1], 16, %2;"
                 :: "r"(dst), "l"(src), "r"(bytes));
}
__device__ __forceinline__ void cp_commit() {
    asm volatile("cp.async.commit_group;");
}
template<int N>
__device__ __forceinline__ void cp_wait() {
    asm volatile("cp.async.wait_group %0;" :: "n"(N));
}

__global__ void __launch_bounds__(256, 2)
gemm_att(const __nv_bfloat16* __restrict__ A, const __nv_bfloat16* __restrict__ B,
         __nv_bfloat16* __restrict__ C,
         const float* __restrict__ att_src, const float* __restrict__ att_dst,
         float* __restrict__ asrc, float* __restrict__ adst,
         int N, int M, int K, int H, int Cc) {
    const int BM = 128, BN = 128, BK = 32;
    __shared__ uint32_t As[2][BM][SROW];
    __shared__ uint32_t Bs[2][BN][SROW];

    int tid  = threadIdx.x;
    int lane = tid & 31;
    int wid  = tid >> 5;
    int wr = (wid & 3) * 32;
    int wc = (wid >> 2) * 64;
    int gid = lane >> 2;
    int tig = lane & 3;

    int blockRow = blockIdx.y * BM;
    int blockCol = blockIdx.x * BN;

    int r0c = (tid + 0)   >> 2, q0 = (tid + 0)   & 3;
    int r1c = (tid + 256) >> 2, q1 = (tid + 256) & 3;

    uint32_t asm0 = (uint32_t)__cvta_generic_to_shared(&As[0][0][0]);
    uint32_t bsm0 = (uint32_t)__cvta_generic_to_shared(&Bs[0][0][0]);
    const uint32_t stage = BM * SROW * 4;

    auto issue = [&](int k0, int buf) {
        int ba0 = (blockRow + r0c < N) ? 16 : 0;
        int ba1 = (blockRow + r1c < N) ? 16 : 0;
        int bb0 = (blockCol + r0c < M) ? 16 : 0;
        int bb1 = (blockCol + r1c < M) ? 16 : 0;
        cp16(asm0 + buf * stage + (r0c * SROW + q0 * 4) * 4,
             A + (size_t)(blockRow + r0c) * K + k0 + q0 * 8, ba0);
        cp16(asm0 + buf * stage + (r1c * SROW + q1 * 4) * 4,
             A + (size_t)(blockRow + r1c) * K + k0 + q1 * 8, ba1);
        cp16(bsm0 + buf * stage + (r0c * SROW + q0 * 4) * 4,
             B + (size_t)(blockCol + r0c) * K + k0 + q0 * 8, bb0);
        cp16(bsm0 + buf * stage + (r1c * SROW + q1 * 4) * 4,
             B + (size_t)(blockCol + r1c) * K + k0 + q1 * 8, bb1);
        cp_commit();
    };

    float acc[2][8][4];
#pragma unroll
    for (int mt = 0; mt < 2; mt++)
#pragma unroll
        for (int nt = 0; nt < 8; nt++)
#pragma unroll
            for (int i = 0; i < 4; i++) acc[mt][nt][i] = 0.f;

    int nIt = K / BK;
    issue(0, 0);

    int buf = 0;
    for (int it = 0; it < nIt; it++) {
        if (it + 1 < nIt) {
            issue((it + 1) * BK, buf ^ 1);
            cp_wait<1>();
        } else {
            cp_wait<0>();
        }
        __syncthreads();

#pragma unroll
        for (int ks = 0; ks < 2; ks++) {
            int kb = ks * 8;
            uint32_t a[2][4], b[8][2];
#pragma unroll
            for (int mt = 0; mt < 2; mt++) {
                int r0 = wr + mt * 16;
                a[mt][0] = As[buf][r0 + gid    ][kb + tig    ];
                a[mt][1] = As[buf][r0 + gid + 8][kb + tig    ];
                a[mt][2] = As[buf][r0 + gid    ][kb + tig + 4];
                a[mt][3] = As[buf][r0 + gid + 8][kb + tig + 4];
            }
#pragma unroll
            for (int nt = 0; nt < 8; nt++) {
                int n0 = wc + nt * 8 + gid;
                b[nt][0] = Bs[buf][n0][kb + tig    ];
                b[nt][1] = Bs[buf][n0][kb + tig + 4];
            }
#pragma unroll
            for (int mt = 0; mt < 2; mt++)
#pragma unroll
                for (int nt = 0; nt < 8; nt++) {
                    asm volatile(
                        "mma.sync.aligned.m16n8k16.row.col.f32.bf16.bf16.f32 "
                        "{%0,%1,%2,%3}, {%4,%5,%6,%7}, {%8,%9}, {%0,%1,%2,%3};"
                        : "+f"(acc[mt][nt][0]), "+f"(acc[mt][nt][1]),
                          "+f"(acc[mt][nt][2]), "+f"(acc[mt][nt][3])
                        : "r"(a[mt][0]), "r"(a[mt][1]), "r"(a[mt][2]), "r"(a[mt][3]),
                          "r"(b[nt][0]), "r"(b[nt][1]));
                }
        }
        __syncthreads();
        buf ^= 1;
    }

    int h_first = (blockCol + wc) / Cc;
    float psrc[2][2][2] = {};
    float pdst[2][2][2] = {};

#pragma unroll
    for (int mt = 0; mt < 2; mt++) {
#pragma unroll
        for (int nt = 0; nt < 8; nt++) {
            int r0 = blockRow + wr + mt * 16 + gid;
            int c0 = blockCol + wc + nt * 8 + tig * 2;
            if (c0 < M) {
                if (r0 < N)
                    *(uint32_t*)(C + (size_t)r0 * M + c0) =
                        pack_bf16x2(acc[mt][nt][0], acc[mt][nt][1]);
                if (r0 + 8 < N)
                    *(uint32_t*)(C + (size_t)(r0 + 8) * M + c0) =
                        pack_bf16x2(acc[mt][nt][2], acc[mt][nt][3]);
                int hb = (blockCol + wc + nt * 8) / Cc - h_first;
                float a0 = att_src[c0], a1 = att_src[c0 + 1];
                float d0 = att_dst[c0], d1 = att_dst[c0 + 1];
                psrc[mt][0][hb] += acc[mt][nt][0] * a0 + acc[mt][nt][1] * a1;
                psrc[mt][1][hb] += acc[mt][nt][2] * a0 + acc[mt][nt][3] * a1;
                pdst[mt][0][hb] += acc[mt][nt][0] * d0 + acc[mt][nt][1] * d1;
                pdst[mt][1][hb] += acc[mt][nt][2] * d0 + acc[mt][nt][3] * d1;
            }
        }
    }
#pragma unroll
    for (int mt = 0; mt < 2; mt++)
#pragma unroll
        for (int hf = 0; hf < 2; hf++)
#pragma unroll
            for (int bk = 0; bk < 2; bk++) {
                float s = psrc[mt][hf][bk], d = pdst[mt][hf][bk];
                s += __shfl_xor_sync(0xffffffffu, s, 1);
                s += __shfl_xor_sync(0xffffffffu, s, 2);
                d += __shfl_xor_sync(0xffffffffu, d, 1);
                d += __shfl_xor_sync(0xffffffffu, d, 2);
                psrc[mt][hf][bk] = s; pdst[mt][hf][bk] = d;
            }
    if (tig == 0) {
#pragma unroll
        for (int mt = 0; mt < 2; mt++)
#pragma unroll
            for (int hf = 0; hf < 2; hf++) {
                int row = blockRow + wr + mt * 16 + gid + hf * 8;
                if (row >= N) continue;
#pragma unroll
                for (int bk = 0; bk < 2; bk++) {
                    int hidx = h_first + bk;
                    if (hidx < H) {
                        atomicAdd(&asrc[row * H + hidx], psrc[mt][hf][bk]);
                        atomicAdd(&adst[row * H + hidx], pdst[mt][hf][bk]);
                    }
                }
            }
    }
}

// ---------------------------------------------------------------------------
// GAT aggregation, H=5. 256 threads/node; G=256/NC4 groups gather in parallel
// (layer1: G=3 -> serial edge walk /3; layer2: G=2), smem partial reduction.
// ---------------------------------------------------------------------------
template<int C>
__global__ void __launch_bounds__(256)
gat_agg5(const __nv_bfloat16* __restrict__ hfeat,
         const float* __restrict__ asrc,
         const float* __restrict__ adst,
         const float* __restrict__ bias,
         __nv_bfloat16* __restrict__ out) {
    const int HC = 5 * C, NC4 = HC / 4;
    const int G = 256 / NC4;                 // 3 for C=64, 2 for C=96
    const int EMAX = 128;
    __shared__ float  s_e[EMAX * 5];
    __shared__ int    s_src[EMAX];
    __shared__ float  s_m[5], s_iz[5], s_ad[5];
    __shared__ float4 s_part[256];

    int v = blockIdx.x;
    int tid = threadIdx.x, lane = tid & 31, wid = tid >> 5;
    int base = g_rowptr[v];
    int deg = g_rowptr[v + 1] - base;

    if (tid < 5) s_ad[tid] = adst[v * 5 + tid];
    __syncthreads();

    int grp  = tid / NC4;                    // 0..G-1 (or G for leftovers)
    int chan = tid - grp * NC4;
    int head = (chan * 4) / C;

    float4 acc = make_float4(0.f, 0.f, 0.f, 0.f);

    if (deg <= EMAX) {
        // phase 1: leaky e into smem
        for (int idx = tid; idx < deg * 5; idx += 256) {
            int j = idx / 5, hh = idx - j * 5;
            int s = g_csrc[base + j];
            if (hh == 0) s_src[j] = s;
            float e = asrc[s * 5 + hh] + s_ad[hh];
            s_e[idx] = (e > 0.f) ? e : NEG_SLOPE * e;
        }
        __syncthreads();
        // phase 2: per-head softmax (warps 0..4)
        if (wid < 5) {
            int h = wid;
            float m = -INFINITY;
            for (int j = lane; j < deg; j += 32)
                m = fmaxf(m, s_e[j * 5 + h]);
#pragma unroll
            for (int o = 16; o > 0; o >>= 1)
                m = fmaxf(m, __shfl_xor_sync(0xffffffffu, m, o));
            float z = 0.f;
            for (int j = lane; j < deg; j += 32) {
                float ex = __expf(s_e[j * 5 + h] - m);
                s_e[j * 5 + h] = ex;
                z += ex;
            }
#pragma unroll
            for (int o = 16; o > 0; o >>= 1)
                z += __shfl_xor_sync(0xffffffffu, z, o);
            if (lane == 0) s_iz[h] = 1.f / (z + EPS_F);
        }
        __syncthreads();
        // phase 3: normalize
        for (int idx = tid; idx < deg * 5; idx += 256) {
            int hh = idx % 5;
            s_e[idx] *= s_iz[hh];
        }
        __syncthreads();
        // phase 4: group-parallel gather (group g walks edges j = g, g+G, ...)
        if (grp < G) {
            for (int j = grp; j < deg; j += G) {
                const uint2* hp = (const uint2*)(hfeat + (size_t)s_src[j] * HC);
                float w = s_e[j * 5 + head];
                uint2 hv = hp[chan];
                float2 lo = __bfloat1622float2(*(__nv_bfloat162*)&hv.x);
                float2 hi = __bfloat1622float2(*(__nv_bfloat162*)&hv.y);
                acc.x += w * lo.x; acc.y += w * lo.y;
                acc.z += w * hi.x; acc.w += w * hi.y;
            }
        }
    } else {
        // fallback (deg > EMAX): 3-phase global softmax + chunked gather
        if (wid < 5) {
            int h = wid;
            float ad = s_ad[h];
            float m = -INFINITY;
            for (int j = lane; j < deg; j += 32) {
                int s = g_csrc[base + j];
                float e = asrc[s * 5 + h] + ad;
                e = (e > 0.f) ? e : NEG_SLOPE * e;
                m = fmaxf(m, e);
            }
#pragma unroll
            for (int o = 16; o > 0; o >>= 1)
                m = fmaxf(m, __shfl_xor_sync(0xffffffffu, m, o));
            float z = 0.f;
            for (int j = lane; j < deg; j += 32) {
                int s = g_csrc[base + j];
                float e = asrc[s * 5 + h] + ad;
                e = (e > 0.f) ? e : NEG_SLOPE * e;
                z += __expf(e - m);
            }
#pragma unroll
            for (int o = 16; o > 0; o >>= 1)
                z += __shfl_xor_sync(0xffffffffu, z, o);
            if (lane == 0) { s_m[h] = m; s_iz[h] = 1.f / (z + EPS_F); }
        }
        __syncthreads();
        for (int j0 = 0; j0 < deg; j0 += EMAX) {
            int ch = min(EMAX, deg - j0);
            for (int idx = tid; idx < ch * 5; idx += 256) {
                int j = idx / 5, hh = idx - j * 5;
                int s = g_csrc[base + j0 + j];
                if (hh == 0) s_src[j] = s;
                float e = asrc[s * 5 + hh] + s_ad[hh];
                e = (e > 0.f) ? e : NEG_SLOPE * e;
                s_e[j * 5 + hh] = __expf(e - s_m[hh]) * s_iz[hh];
            }
            __syncthreads();
            if (grp < G) {
                for (int j = grp; j < ch; j += G) {
                    const uint2* hp = (const uint2*)(hfeat + (size_t)s_src[j] * HC);
                    float w = s_e[j * 5 + head];
                    uint2 hv = hp[chan];
                    float2 lo = __bfloat1622float2(*(__nv_bfloat162*)&hv.x);
                    float2 hi = __bfloat1622float2(*(__nv_bfloat162*)&hv.y);
                    acc.x += w * lo.x; acc.y += w * lo.y;
                    acc.z += w * hi.x; acc.w += w * hi.y;
                }
            }
            __syncthreads();
        }
    }

    // reduce partials across groups
    s_part[tid] = acc;
    __syncthreads();
    if (tid < NC4) {
        float4 a = s_part[tid];
#pragma unroll
        for (int g = 1; g < G; g++) {
            float4 p = s_part[g * NC4 + tid];
            a.x += p.x; a.y += p.y; a.z += p.z; a.w += p.w;
        }
        float4 b = ((const float4*)bias)[tid];
        uint2 o;
        o.x = pack_bf16x2(fmaxf(a.x + b.x, 0.f), fmaxf(a.y + b.y, 0.f));
        o.y = pack_bf16x2(fmaxf(a.z + b.z, 0.f), fmaxf(a.w + b.w, 0.f));
        ((uint2*)(out + (size_t)v * HC))[tid] = o;
    }
}

// ---------------------------------------------------------------------------
// GAT aggregation, H=1, C=32 + fused global_add_pool. warp per node.
// ---------------------------------------------------------------------------
__global__ void __launch_bounds__(256)
gat_agg1_pool(const __nv_bfloat16* __restrict__ hfeat,
              const float* __restrict__ asrc,
              const float* __restrict__ adst,
              const float* __restrict__ bias,
              const int* __restrict__ batch) {
    int wid = threadIdx.x >> 5, lane = threadIdx.x & 31;
    int v = blockIdx.x * 8 + wid;
    if (v >= N_NODES) return;
    int base = g_rowptr[v];
    int deg = g_rowptr[v + 1] - base;
    float ad = adst[v];
    float* pool = (float*)(g_zero + N_NODES);

    float m = -INFINITY;
    for (int j = lane; j < deg; j += 32) {
        int s = g_csrc[base + j];
        float e = asrc[s] + ad;
        e = (e > 0.f) ? e : NEG_SLOPE * e;
        m = fmaxf(m, e);
    }
#pragma unroll
    for (int o = 16; o > 0; o >>= 1)
        m = fmaxf(m, __shfl_xor_sync(0xffffffffu, m, o));
    float z = 0.f;
    for (int j = lane; j < deg; j += 32) {
        int s = g_csrc[base + j];
        float e = asrc[s] + ad;
        e = (e > 0.f) ? e : NEG_SLOPE * e;
        z += __expf(e - m);
    }
#pragma unroll
    for (int o = 16; o > 0; o >>= 1)
        z += __shfl_xor_sync(0xffffffffu, z, o);
    float iz = 1.f / (z + EPS_F);

    float acc = 0.f;
#pragma unroll 2
    for (int j = 0; j < deg; j++) {
        int s = g_csrc[base + j];
        float e = asrc[s] + ad;
        e = (e > 0.f) ? e : NEG_SLOPE * e;
        float w = __expf(e - m) * iz;
        acc += w * __bfloat162float(hfeat[(size_t)s * 32 + lane]);
    }
    float o = fmaxf(acc + bias[lane], 0.f);
    atomicAdd(&pool[batch[v] * 32 + lane], o);
}

// ---------------------------------------------------------------------------
// MLP head
// ---------------------------------------------------------------------------
__global__ void mlp_kernel(const float* __restrict__ lin_w,
                           const float* __restrict__ lin_b,
                           const float* __restrict__ lin2_w,
                           const float* __restrict__ lin2_b,
                           float* __restrict__ out) {
    int g = blockIdx.x;
    __shared__ float sg[32];
    __shared__ float sred[256];
    int tid = threadIdx.x;
    const float* pool = (const float*)(g_zero + N_NODES);
    if (tid < 32) sg[tid] = pool[g * 32 + tid];
    __syncthreads();
    float partial = 0.f;
    for (int u = tid; u < 1024; u += 256) {
        float d = lin_b[u];
        const float* wr = lin_w + u * 32;
#pragma unroll
        for (int c = 0; c < 32; c++) d += sg[c] * wr[c];
        d = fmaxf(d, 0.f);
        partial += d * lin2_w[u];
    }
    sred[tid] = partial;
    __syncthreads();
    for (int s = 128; s > 0; s >>= 1) {
        if (tid < s) sred[tid] += sred[tid + s];
        __syncthreads();
    }
    if (tid == 0) {
        float v = sred[0] + lin2_b[0];
        out[g] = 1.f / (1.f + __expf(-v));
    }
}

// ---------------------------------------------------------------------------
// launch
// ---------------------------------------------------------------------------
extern "C" void kernel_launch(void* const* d_in, const int* in_sizes, int n_in,
                              void* d_out, int out_size) {
    const float* x        = (const float*)d_in[0];
    const float* W1       = (const float*)d_in[1];
    const float* att_s1   = (const float*)d_in[2];
    const float* att_d1   = (const float*)d_in[3];
    const float* b1       = (const float*)d_in[4];
    const float* W2       = (const float*)d_in[5];
    const float* att_s2   = (const float*)d_in[6];
    const float* att_d2   = (const float*)d_in[7];
    const float* b2       = (const float*)d_in[8];
    const float* W3       = (const float*)d_in[9];
    const float* att_s3   = (const float*)d_in[10];
    const float* att_d3   = (const float*)d_in[11];
    const float* b3       = (const float*)d_in[12];
    const float* lin_w    = (const float*)d_in[13];
    const float* lin_b    = (const float*)d_in[14];
    const float* lin2_w   = (const float*)d_in[15];
    const float* lin2_b   = (const float*)d_in[16];
    const int*   ei       = (const int*)d_in[17];
    const int*   batch    = (const int*)d_in[18];
    float* out = (float*)d_out;

    __nv_bfloat16 *xq, *w1q, *w2q, *w3q, *h1, *o1, *h2, *o2, *h3;
    float *attbuf;
    int *zreg;
    cudaGetSymbolAddress((void**)&xq, g_xq);
    cudaGetSymbolAddress((void**)&w1q, g_w1q);
    cudaGetSymbolAddress((void**)&w2q, g_w2q);
    cudaGetSymbolAddress((void**)&w3q, g_w3q);
    cudaGetSymbolAddress((void**)&h1, g_h1);
    cudaGetSymbolAddress((void**)&o1, g_o1);
    cudaGetSymbolAddress((void**)&h2, g_h2);
    cudaGetSymbolAddress((void**)&o2, g_o2);
    cudaGetSymbolAddress((void**)&h3, g_h3);
    cudaGetSymbolAddress((void**)&attbuf, g_att);
    cudaGetSymbolAddress((void**)&zreg, g_zero);

    float* as1 = attbuf;                    float* ad1 = attbuf + N_NODES * 5;
    float* as2 = attbuf + 2 * N_NODES * 5;  float* ad2 = attbuf + 3 * N_NODES * 5;
    float* as3 = attbuf + 4 * N_NODES * 5;  float* ad3 = attbuf + 5 * N_NODES * 5;

    static cudaStream_t s_cs = nullptr;
    static cudaEvent_t ev_fork = nullptr, ev_join = nullptr;
    if (!s_cs) {
        cudaStreamCreateWithFlags(&s_cs, cudaStreamNonBlocking);
        cudaEventCreateWithFlags(&ev_fork, cudaEventDisableTiming);
        cudaEventCreateWithFlags(&ev_join, cudaEventDisableTiming);
    }

    // ---- fork: CSR build on side stream ----
    cudaEventRecord(ev_fork, 0);
    cudaStreamWaitEvent(s_cs, ev_fork, 0);
    cudaMemsetAsync(zreg, 0, (N_NODES + N_GRAPHS * 32) * sizeof(int), s_cs);
    count_kernel<<<(N_EDGES + 255) / 256, 256, 0, s_cs>>>(ei);
    scan1_kernel<<<N_BLK, 256, 0, s_cs>>>();
    scan3_kernel<<<N_BLK, 256, 0, s_cs>>>();
    scatter_kernel<<<(TOT_E + 255) / 256, 256, 0, s_cs>>>(ei);
    cudaEventRecord(ev_join, s_cs);

    // ---- main: prep (x/W conversion + att zero) + GEMM1 ----
    prep_kernel<<<(N_NODES * 64 / 4 + 255) / 256, 256>>>(x, W1, W2, W3);

    const int GY = (N_NODES + 127) / 128;

    gemm_att<<<dim3((HC1 + 127) / 128, GY), 256>>>(
        xq, w1q, h1, att_s1, att_d1, as1, ad1, N_NODES, HC1, 64, 5, 64);

    // ---- join: aggregation needs CSR ----
    cudaStreamWaitEvent(0, ev_join, 0);
    gat_agg5<64><<<N_NODES, 256>>>(h1, as1, ad1, b1, o1);

    gemm_att<<<dim3((HC2 + 127) / 128, GY), 256>>>(
        o1, w2q, h2, att_s2, att_d2, as2, ad2, N_NODES, HC2, HC1, 5, 96);
    gat_agg5<96><<<N_NODES, 256>>>(h2, as2, ad2, b2, o2);

    gemm_att<<<dim3((HC3 + 127) / 128, GY), 256>>>(
        o2, w3q, h3, att_s3, att_d3, as3, ad3, N_NODES, HC3, HC2, 1, 32);
    gat_agg1_pool<<<(N_NODES + 7) / 8, 256>>>(h3, as3, ad3, b3, batch);

    mlp_kernel<<<N_GRAPHS, 256>>>(lin_w, lin_b, lin2_w, lin2_b, out);
}

// round 10
// speedup vs baseline: 1.0271x; 1.0271x over previous
#include <cuda_runtime.h>
#include <cuda_bf16.h>
#include <math.h>
#include <stdint.h>

// ---------------------------------------------------------------------------
// Problem constants
// ---------------------------------------------------------------------------
#define N_NODES 20000
#define N_EDGES 320000
#define TOT_E   (N_EDGES + N_NODES)
#define N_GRAPHS 128
#define NEG_SLOPE 0.2f
#define EPS_F 1e-16f

#define HC1 320   // H=5, C=64
#define HC2 480   // H=5, C=96
#define HC3 32    // H=1, C=32

#define N_BLK ((N_NODES + 255) / 256)   // 79

// ---------------------------------------------------------------------------
// Device scratch
// ---------------------------------------------------------------------------
__device__ __align__(16) __nv_bfloat16 g_xq[N_NODES * 64];
__device__ __align__(16) __nv_bfloat16 g_w1q[HC1 * 64];
__device__ __align__(16) __nv_bfloat16 g_w2q[HC2 * HC1];
__device__ __align__(16) __nv_bfloat16 g_w3q[HC3 * HC2];
__device__ __align__(16) __nv_bfloat16 g_h1[N_NODES * HC1];
__device__ __align__(16) __nv_bfloat16 g_o1[N_NODES * HC1];
__device__ __align__(16) __nv_bfloat16 g_h2[N_NODES * HC2];
__device__ __align__(16) __nv_bfloat16 g_o2[N_NODES * HC2];
__device__ __align__(16) __nv_bfloat16 g_h3[N_NODES * HC3];
__device__ float g_att[6 * N_NODES * 5];
// contiguous zero region: cnt (N_NODES ints) + pool (N_GRAPHS*32 floats)
__device__ int   g_zero[N_NODES + N_GRAPHS * 32];
__device__ int   g_rowptr[N_NODES + 1];
__device__ int   g_cursor[N_NODES];
__device__ int   g_csrc[TOT_E];
__device__ int   g_bsum[N_BLK];

__device__ __forceinline__ uint32_t pack_bf16x2(float lo, float hi) {
    __nv_bfloat162 h2 = __floats2bfloat162_rn(lo, hi);
    return *(uint32_t*)&h2;
}

// ---------------------------------------------------------------------------
// prep: x -> bf16, W1/2/3 -> bf16, zero att accumulators
// ---------------------------------------------------------------------------
#define W1Q4 (HC1 * 64 / 4)       // 5120
#define W2Q4 (HC2 * HC1 / 4)      // 38400
#define W3Q4 (HC3 * HC2 / 4)      // 3840

__global__ void prep_kernel(const float* __restrict__ x,
                            const float* __restrict__ W1,
                            const float* __restrict__ W2,
                            const float* __restrict__ W3) {
    int i = blockIdx.x * 256 + threadIdx.x;
    if (i < N_NODES * 64 / 4) {
        float4 v = ((const float4*)x)[i];
        uint2 p;
        p.x = pack_bf16x2(v.x, v.y);
        p.y = pack_bf16x2(v.z, v.w);
        ((uint2*)g_xq)[i] = p;
    }
    if (2 * i < 6 * N_NODES * 5) {
        g_att[2 * i] = 0.f;
        if (2 * i + 1 < 6 * N_NODES * 5) g_att[2 * i + 1] = 0.f;
    }
    if (i < W1Q4 + W2Q4 + W3Q4) {
        const float4* src;
        uint2* dst;
        int j = i;
        if (j < W1Q4)                { src = (const float4*)W1; dst = (uint2*)g_w1q; }
        else if ((j -= W1Q4) < W2Q4) { src = (const float4*)W2; dst = (uint2*)g_w2q; }
        else { j -= W2Q4;              src = (const float4*)W3; dst = (uint2*)g_w3q; }
        float4 v = src[j];
        uint2 p;
        p.x = pack_bf16x2(v.x, v.y);
        p.y = pack_bf16x2(v.z, v.w);
        dst[j] = p;
    }
}

// ---------------------------------------------------------------------------
// CSR construction
// ---------------------------------------------------------------------------
__global__ void count_kernel(const int* __restrict__ ei) {
    int i = blockIdx.x * blockDim.x + threadIdx.x;
    if (i < N_EDGES) atomicAdd(&g_zero[ei[N_EDGES + i]], 1);
}

__global__ void scan1_kernel() {
    int i = blockIdx.x * 256 + threadIdx.x;
    int lane = threadIdx.x & 31, w = threadIdx.x >> 5;
    int x = (i < N_NODES) ? (g_zero[i] + 1) : 0;
#pragma unroll
    for (int o = 1; o < 32; o <<= 1) {
        int t = __shfl_up_sync(0xffffffffu, x, o);
        if (lane >= o) x += t;
    }
    __shared__ int wsum[8];
    if (lane == 31) wsum[w] = x;
    __syncthreads();
    if (w == 0) {
        int s = (lane < 8) ? wsum[lane] : 0;
#pragma unroll
        for (int o = 1; o < 8; o <<= 1) {
            int t = __shfl_up_sync(0xffffffffu, s, o);
            if (lane >= o) s += t;
        }
        if (lane < 8) wsum[lane] = s;
    }
    __syncthreads();
    int incl = x + ((w > 0) ? wsum[w - 1] : 0);
    if (i < N_NODES) g_rowptr[i + 1] = incl;
    if (threadIdx.x == 255) g_bsum[blockIdx.x] = incl;
}

__global__ void scan3_kernel() {
    __shared__ int s_off;
    int tid = threadIdx.x, lane = tid & 31;
    if (tid < 32) {
        int off = 0;
        for (int j = lane; j < blockIdx.x; j += 32) off += g_bsum[j];
#pragma unroll
        for (int o = 16; o > 0; o >>= 1)
            off += __shfl_xor_sync(0xffffffffu, off, o);
        if (lane == 0) s_off = off;
    }
    __syncthreads();
    int i = blockIdx.x * 256 + tid;
    if (i == 0) g_rowptr[0] = 0;
    if (i < N_NODES) {
        int incl = g_rowptr[i + 1] + s_off;
        g_rowptr[i + 1] = incl;
        g_cursor[i] = incl - (g_zero[i] + 1);
    }
}

__global__ void scatter_kernel(const int* __restrict__ ei) {
    int i = blockIdx.x * blockDim.x + threadIdx.x;
    if (i >= TOT_E) return;
    int src, dst;
    if (i < N_EDGES) { src = ei[i]; dst = ei[N_EDGES + i]; }
    else             { src = dst = i - N_EDGES; }
    int pos = atomicAdd(&g_cursor[dst], 1);
    g_csrc[pos] = src;
}

// ---------------------------------------------------------------------------
// bf16 GEMM (cp.async pipeline) + fused attention epilogue + PDL entry.
// prefetchB=1: issue B stage-0 cp.asyncs BEFORE grid-dependency sync (weights
// are provably ready: the full-dependency agg1 launch anchors prep completion).
// ---------------------------------------------------------------------------
#define SROW 20

__device__ __forceinline__ void cp16(uint32_t dst, const void* src, int bytes) {
    asm volatile("cp.async.cg.shared.global [%0], [%1], 16, %2;"
                 :: "r"(dst), "l"(src), "r"(bytes));
}
__device__ __forceinline__ void cp_commit() {
    asm volatile("cp.async.commit_group;");
}
template<int N>
__device__ __forceinline__ void cp_wait() {
    asm volatile("cp.async.wait_group %0;" :: "n"(N));
}

__global__ void __launch_bounds__(256, 2)
gemm_att(const __nv_bfloat16* __restrict__ A, const __nv_bfloat16* __restrict__ B,
         __nv_bfloat16* __restrict__ C,
         const float* __restrict__ att_src, const float* __restrict__ att_dst,
         float* __restrict__ asrc, float* __restrict__ adst,
         int N, int M, int K, int H, int Cc, int prefetchB) {
    const int BM = 128, BN = 128, BK = 32;
    __shared__ uint32_t As[2][BM][SROW];
    __shared__ uint32_t Bs[2][BN][SROW];

    int tid  = threadIdx.x;
    int lane = tid & 31;
    int wid  = tid >> 5;
    int wr = (wid & 3) * 32;
    int wc = (wid >> 2) * 64;
    int gid = lane >> 2;
    int tig = lane & 3;

    int blockRow = blockIdx.y * BM;
    int blockCol = blockIdx.x * BN;

    int r0c = (tid + 0)   >> 2, q0 = (tid + 0)   & 3;
    int r1c = (tid + 256) >> 2, q1 = (tid + 256) & 3;

    uint32_t asm0 = (uint32_t)__cvta_generic_to_shared(&As[0][0][0]);
    uint32_t bsm0 = (uint32_t)__cvta_generic_to_shared(&Bs[0][0][0]);
    const uint32_t stage = BM * SROW * 4;

    auto issueA = [&](int k0, int buf) {
        int ba0 = (blockRow + r0c < N) ? 16 : 0;
        int ba1 = (blockRow + r1c < N) ? 16 : 0;
        cp16(asm0 + buf * stage + (r0c * SROW + q0 * 4) * 4,
             A + (size_t)(blockRow + r0c) * K + k0 + q0 * 8, ba0);
        cp16(asm0 + buf * stage + (r1c * SROW + q1 * 4) * 4,
             A + (size_t)(blockRow + r1c) * K + k0 + q1 * 8, ba1);
    };
    auto issueB = [&](int k0, int buf) {
        int bb0 = (blockCol + r0c < M) ? 16 : 0;
        int bb1 = (blockCol + r1c < M) ? 16 : 0;
        cp16(bsm0 + buf * stage + (r0c * SROW + q0 * 4) * 4,
             B + (size_t)(blockCol + r0c) * K + k0 + q0 * 8, bb0);
        cp16(bsm0 + buf * stage + (r1c * SROW + q1 * 4) * 4,
             B + (size_t)(blockCol + r1c) * K + k0 + q1 * 8, bb1);
    };

    // PDL: overlap weight prefetch with predecessor drain, then sync.
    if (prefetchB) issueB(0, 0);
    cudaGridDependencySynchronize();
    issueA(0, 0);
    if (!prefetchB) issueB(0, 0);
    cp_commit();

    float acc[2][8][4];
#pragma unroll
    for (int mt = 0; mt < 2; mt++)
#pragma unroll
        for (int nt = 0; nt < 8; nt++)
#pragma unroll
            for (int i = 0; i < 4; i++) acc[mt][nt][i] = 0.f;

    int nIt = K / BK;
    int buf = 0;
    for (int it = 0; it < nIt; it++) {
        if (it + 1 < nIt) {
            issueA((it + 1) * BK, buf ^ 1);
            issueB((it + 1) * BK, buf ^ 1);
            cp_commit();
            cp_wait<1>();
        } else {
            cp_wait<0>();
        }
        __syncthreads();

#pragma unroll
        for (int ks = 0; ks < 2; ks++) {
            int kb = ks * 8;
            uint32_t a[2][4], b[8][2];
#pragma unroll
            for (int mt = 0; mt < 2; mt++) {
                int r0 = wr + mt * 16;
                a[mt][0] = As[buf][r0 + gid    ][kb + tig    ];
                a[mt][1] = As[buf][r0 + gid + 8][kb + tig    ];
                a[mt][2] = As[buf][r0 + gid    ][kb + tig + 4];
                a[mt][3] = As[buf][r0 + gid + 8][kb + tig + 4];
            }
#pragma unroll
            for (int nt = 0; nt < 8; nt++) {
                int n0 = wc + nt * 8 + gid;
                b[nt][0] = Bs[buf][n0][kb + tig    ];
                b[nt][1] = Bs[buf][n0][kb + tig + 4];
            }
#pragma unroll
            for (int mt = 0; mt < 2; mt++)
#pragma unroll
                for (int nt = 0; nt < 8; nt++) {
                    asm volatile(
                        "mma.sync.aligned.m16n8k16.row.col.f32.bf16.bf16.f32 "
                        "{%0,%1,%2,%3}, {%4,%5,%6,%7}, {%8,%9}, {%0,%1,%2,%3};"
                        : "+f"(acc[mt][nt][0]), "+f"(acc[mt][nt][1]),
                          "+f"(acc[mt][nt][2]), "+f"(acc[mt][nt][3])
                        : "r"(a[mt][0]), "r"(a[mt][1]), "r"(a[mt][2]), "r"(a[mt][3]),
                          "r"(b[nt][0]), "r"(b[nt][1]));
                }
        }
        __syncthreads();
        buf ^= 1;
    }

    int h_first = (blockCol + wc) / Cc;
    float psrc[2][2][2] = {};
    float pdst[2][2][2] = {};

#pragma unroll
    for (int mt = 0; mt < 2; mt++) {
#pragma unroll
        for (int nt = 0; nt < 8; nt++) {
            int r0 = blockRow + wr + mt * 16 + gid;
            int c0 = blockCol + wc + nt * 8 + tig * 2;
            if (c0 < M) {
                if (r0 < N)
                    *(uint32_t*)(C + (size_t)r0 * M + c0) =
                        pack_bf16x2(acc[mt][nt][0], acc[mt][nt][1]);
                if (r0 + 8 < N)
                    *(uint32_t*)(C + (size_t)(r0 + 8) * M + c0) =
                        pack_bf16x2(acc[mt][nt][2], acc[mt][nt][3]);
                int hb = (blockCol + wc + nt * 8) / Cc - h_first;
                float a0 = att_src[c0], a1 = att_src[c0 + 1];
                float d0 = att_dst[c0], d1 = att_dst[c0 + 1];
                psrc[mt][0][hb] += acc[mt][nt][0] * a0 + acc[mt][nt][1] * a1;
                psrc[mt][1][hb] += acc[mt][nt][2] * a0 + acc[mt][nt][3] * a1;
                pdst[mt][0][hb] += acc[mt][nt][0] * d0 + acc[mt][nt][1] * d1;
                pdst[mt][1][hb] += acc[mt][nt][2] * d0 + acc[mt][nt][3] * d1;
            }
        }
    }
#pragma unroll
    for (int mt = 0; mt < 2; mt++)
#pragma unroll
        for (int hf = 0; hf < 2; hf++)
#pragma unroll
            for (int bk = 0; bk < 2; bk++) {
                float s = psrc[mt][hf][bk], d = pdst[mt][hf][bk];
                s += __shfl_xor_sync(0xffffffffu, s, 1);
                s += __shfl_xor_sync(0xffffffffu, s, 2);
                d += __shfl_xor_sync(0xffffffffu, d, 1);
                d += __shfl_xor_sync(0xffffffffu, d, 2);
                psrc[mt][hf][bk] = s; pdst[mt][hf][bk] = d;
            }
    if (tig == 0) {
#pragma unroll
        for (int mt = 0; mt < 2; mt++)
#pragma unroll
            for (int hf = 0; hf < 2; hf++) {
                int row = blockRow + wr + mt * 16 + gid + hf * 8;
                if (row >= N) continue;
#pragma unroll
                for (int bk = 0; bk < 2; bk++) {
                    int hidx = h_first + bk;
                    if (hidx < H) {
                        atomicAdd(&asrc[row * H + hidx], psrc[mt][hf][bk]);
                        atomicAdd(&adst[row * H + hidx], pdst[mt][hf][bk]);
                    }
                }
            }
    }
}

// ---------------------------------------------------------------------------
// GAT aggregation, H=5 (R8 structure). 192 thr/node, single-pass smem softmax.
// ---------------------------------------------------------------------------
template<int C>
__global__ void __launch_bounds__(192)
gat_agg5(const __nv_bfloat16* __restrict__ hfeat,
         const float* __restrict__ asrc,
         const float* __restrict__ adst,
         const float* __restrict__ bias,
         __nv_bfloat16* __restrict__ out) {
    const int HC = 5 * C, NC4 = HC / 4;
    const int EMAX = 128;
    __shared__ float s_e[EMAX * 5];
    __shared__ int   s_src[EMAX];
    __shared__ float s_m[5], s_iz[5], s_ad[5];

    cudaGridDependencySynchronize();

    int v = blockIdx.x;
    int tid = threadIdx.x, lane = tid & 31, wid = tid >> 5;
    int base = g_rowptr[v];
    int deg = g_rowptr[v + 1] - base;

    if (tid < 5) s_ad[tid] = adst[v * 5 + tid];
    __syncthreads();

    float4 acc = make_float4(0.f, 0.f, 0.f, 0.f);
    int head = (tid * 4) / C;

    if (deg <= EMAX) {
        for (int idx = tid; idx < deg * 5; idx += 192) {
            int j = idx / 5, hh = idx - j * 5;
            int s = g_csrc[base + j];
            if (hh == 0) s_src[j] = s;
            float e = asrc[s * 5 + hh] + s_ad[hh];
            s_e[idx] = (e > 0.f) ? e : NEG_SLOPE * e;
        }
        __syncthreads();
        if (wid < 5) {
            int h = wid;
            float m = -INFINITY;
            for (int j = lane; j < deg; j += 32)
                m = fmaxf(m, s_e[j * 5 + h]);
#pragma unroll
            for (int o = 16; o > 0; o >>= 1)
                m = fmaxf(m, __shfl_xor_sync(0xffffffffu, m, o));
            float z = 0.f;
            for (int j = lane; j < deg; j += 32) {
                float ex = __expf(s_e[j * 5 + h] - m);
                s_e[j * 5 + h] = ex;
                z += ex;
            }
#pragma unroll
            for (int o = 16; o > 0; o >>= 1)
                z += __shfl_xor_sync(0xffffffffu, z, o);
            if (lane == 0) s_iz[h] = 1.f / (z + EPS_F);
        }
        __syncthreads();
        for (int idx = tid; idx < deg * 5; idx += 192) {
            int hh = idx % 5;
            s_e[idx] *= s_iz[hh];
        }
        __syncthreads();
        if (tid < NC4) {
#pragma unroll 2
            for (int j = 0; j < deg; j++) {
                const uint2* hp = (const uint2*)(hfeat + (size_t)s_src[j] * HC);
                float w = s_e[j * 5 + head];
                uint2 hv = hp[tid];
                float2 lo = __bfloat1622float2(*(__nv_bfloat162*)&hv.x);
                float2 hi = __bfloat1622float2(*(__nv_bfloat162*)&hv.y);
                acc.x += w * lo.x; acc.y += w * lo.y;
                acc.z += w * hi.x; acc.w += w * hi.y;
            }
        }
    } else {
        if (wid < 5) {
            int h = wid;
            float ad = s_ad[h];
            float m = -INFINITY;
            for (int j = lane; j < deg; j += 32) {
                int s = g_csrc[base + j];
                float e = asrc[s * 5 + h] + ad;
                e = (e > 0.f) ? e : NEG_SLOPE * e;
                m = fmaxf(m, e);
            }
#pragma unroll
            for (int o = 16; o > 0; o >>= 1)
                m = fmaxf(m, __shfl_xor_sync(0xffffffffu, m, o));
            float z = 0.f;
            for (int j = lane; j < deg; j += 32) {
                int s = g_csrc[base + j];
                float e = asrc[s * 5 + h] + ad;
                e = (e > 0.f) ? e : NEG_SLOPE * e;
                z += __expf(e - m);
            }
#pragma unroll
            for (int o = 16; o > 0; o >>= 1)
                z += __shfl_xor_sync(0xffffffffu, z, o);
            if (lane == 0) { s_m[h] = m; s_iz[h] = 1.f / (z + EPS_F); }
        }
        __syncthreads();
        for (int j0 = 0; j0 < deg; j0 += EMAX) {
            int ch = min(EMAX, deg - j0);
            for (int idx = tid; idx < ch * 5; idx += 192) {
                int j = idx / 5, hh = idx - j * 5;
                int s = g_csrc[base + j0 + j];
                if (hh == 0) s_src[j] = s;
                float e = asrc[s * 5 + hh] + s_ad[hh];
                e = (e > 0.f) ? e : NEG_SLOPE * e;
                s_e[j * 5 + hh] = __expf(e - s_m[hh]) * s_iz[hh];
            }
            __syncthreads();
            if (tid < NC4) {
                for (int j = 0; j < ch; j++) {
                    const uint2* hp = (const uint2*)(hfeat + (size_t)s_src[j] * HC);
                    float w = s_e[j * 5 + head];
                    uint2 hv = hp[tid];
                    float2 lo = __bfloat1622float2(*(__nv_bfloat162*)&hv.x);
                    float2 hi = __bfloat1622float2(*(__nv_bfloat162*)&hv.y);
                    acc.x += w * lo.x; acc.y += w * lo.y;
                    acc.z += w * hi.x; acc.w += w * hi.y;
                }
            }
            __syncthreads();
        }
    }

    if (tid < NC4) {
        float4 b = ((const float4*)bias)[tid];
        uint2 o;
        o.x = pack_bf16x2(fmaxf(acc.x + b.x, 0.f), fmaxf(acc.y + b.y, 0.f));
        o.y = pack_bf16x2(fmaxf(acc.z + b.z, 0.f), fmaxf(acc.w + b.w, 0.f));
        ((uint2*)(out + (size_t)v * HC))[tid] = o;
    }
}

// ---------------------------------------------------------------------------
// GAT aggregation, H=1, C=32 + fused global_add_pool. warp per node.
// ---------------------------------------------------------------------------
__global__ void __launch_bounds__(256)
gat_agg1_pool(const __nv_bfloat16* __restrict__ hfeat,
              const float* __restrict__ asrc,
              const float* __restrict__ adst,
              const float* __restrict__ bias,
              const int* __restrict__ batch) {
    cudaGridDependencySynchronize();

    int wid = threadIdx.x >> 5, lane = threadIdx.x & 31;
    int v = blockIdx.x * 8 + wid;
    if (v >= N_NODES) return;
    int base = g_rowptr[v];
    int deg = g_rowptr[v + 1] - base;
    float ad = adst[v];
    float* pool = (float*)(g_zero + N_NODES);

    float m = -INFINITY;
    for (int j = lane; j < deg; j += 32) {
        int s = g_csrc[base + j];
        float e = asrc[s] + ad;
        e = (e > 0.f) ? e : NEG_SLOPE * e;
        m = fmaxf(m, e);
    }
#pragma unroll
    for (int o = 16; o > 0; o >>= 1)
        m = fmaxf(m, __shfl_xor_sync(0xffffffffu, m, o));
    float z = 0.f;
    for (int j = lane; j < deg; j += 32) {
        int s = g_csrc[base + j];
        float e = asrc[s] + ad;
        e = (e > 0.f) ? e : NEG_SLOPE * e;
        z += __expf(e - m);
    }
#pragma unroll
    for (int o = 16; o > 0; o >>= 1)
        z += __shfl_xor_sync(0xffffffffu, z, o);
    float iz = 1.f / (z + EPS_F);

    float acc = 0.f;
#pragma unroll 2
    for (int j = 0; j < deg; j++) {
        int s = g_csrc[base + j];
        float e = asrc[s] + ad;
        e = (e > 0.f) ? e : NEG_SLOPE * e;
        float w = __expf(e - m) * iz;
        acc += w * __bfloat162float(hfeat[(size_t)s * 32 + lane]);
    }
    float o = fmaxf(acc + bias[lane], 0.f);
    atomicAdd(&pool[batch[v] * 32 + lane], o);
}

// ---------------------------------------------------------------------------
// MLP head
// ---------------------------------------------------------------------------
__global__ void mlp_kernel(const float* __restrict__ lin_w,
                           const float* __restrict__ lin_b,
                           const float* __restrict__ lin2_w,
                           const float* __restrict__ lin2_b,
                           float* __restrict__ out) {
    cudaGridDependencySynchronize();

    int g = blockIdx.x;
    __shared__ float sg[32];
    __shared__ float sred[256];
    int tid = threadIdx.x;
    const float* pool = (const float*)(g_zero + N_NODES);
    if (tid < 32) sg[tid] = pool[g * 32 + tid];
    __syncthreads();
    float partial = 0.f;
    for (int u = tid; u < 1024; u += 256) {
        float d = lin_b[u];
        const float* wr = lin_w + u * 32;
#pragma unroll
        for (int c = 0; c < 32; c++) d += sg[c] * wr[c];
        d = fmaxf(d, 0.f);
        partial += d * lin2_w[u];
    }
    sred[tid] = partial;
    __syncthreads();
    for (int s = 128; s > 0; s >>= 1) {
        if (tid < s) sred[tid] += sred[tid + s];
        __syncthreads();
    }
    if (tid == 0) {
        float v = sred[0] + lin2_b[0];
        out[g] = 1.f / (1.f + __expf(-v));
    }
}

// ---------------------------------------------------------------------------
// PDL launch helper
// ---------------------------------------------------------------------------
template<typename Kern, typename... Args>
static inline void launch_pdl(Kern k, dim3 grid, dim3 block, Args... args) {
    cudaLaunchConfig_t cfg = {};
    cfg.gridDim = grid;
    cfg.blockDim = block;
    cfg.stream = 0;
    cudaLaunchAttribute attr[1];
    attr[0].id = cudaLaunchAttributeProgrammaticStreamSerialization;
    attr[0].val.programmaticStreamSerializationAllowed = 1;
    cfg.attrs = attr;
    cfg.numAttrs = 1;
    cudaLaunchKernelEx(&cfg, k, args...);
}

// ---------------------------------------------------------------------------
// launch
// ---------------------------------------------------------------------------
extern "C" void kernel_launch(void* const* d_in, const int* in_sizes, int n_in,
                              void* d_out, int out_size) {
    const float* x        = (const float*)d_in[0];
    const float* W1       = (const float*)d_in[1];
    const float* att_s1   = (const float*)d_in[2];
    const float* att_d1   = (const float*)d_in[3];
    const float* b1       = (const float*)d_in[4];
    const float* W2       = (const float*)d_in[5];
    const float* att_s2   = (const float*)d_in[6];
    const float* att_d2   = (const float*)d_in[7];
    const float* b2       = (const float*)d_in[8];
    const float* W3       = (const float*)d_in[9];
    const float* att_s3   = (const float*)d_in[10];
    const float* att_d3   = (const float*)d_in[11];
    const float* b3       = (const float*)d_in[12];
    const float* lin_w    = (const float*)d_in[13];
    const float* lin_b    = (const float*)d_in[14];
    const float* lin2_w   = (const float*)d_in[15];
    const float* lin2_b   = (const float*)d_in[16];
    const int*   ei       = (const int*)d_in[17];
    const int*   batch    = (const int*)d_in[18];
    float* out = (float*)d_out;

    __nv_bfloat16 *xq, *w1q, *w2q, *w3q, *h1, *o1, *h2, *o2, *h3;
    float *attbuf;
    int *zreg;
    cudaGetSymbolAddress((void**)&xq, g_xq);
    cudaGetSymbolAddress((void**)&w1q, g_w1q);
    cudaGetSymbolAddress((void**)&w2q, g_w2q);
    cudaGetSymbolAddress((void**)&w3q, g_w3q);
    cudaGetSymbolAddress((void**)&h1, g_h1);
    cudaGetSymbolAddress((void**)&o1, g_o1);
    cudaGetSymbolAddress((void**)&h2, g_h2);
    cudaGetSymbolAddress((void**)&o2, g_o2);
    cudaGetSymbolAddress((void**)&h3, g_h3);
    cudaGetSymbolAddress((void**)&attbuf, g_att);
    cudaGetSymbolAddress((void**)&zreg, g_zero);

    float* as1 = attbuf;                    float* ad1 = attbuf + N_NODES * 5;
    float* as2 = attbuf + 2 * N_NODES * 5;  float* ad2 = attbuf + 3 * N_NODES * 5;
    float* as3 = attbuf + 4 * N_NODES * 5;  float* ad3 = attbuf + 5 * N_NODES * 5;

    static cudaStream_t s_cs = nullptr;
    static cudaEvent_t ev_fork = nullptr, ev_join = nullptr;
    if (!s_cs) {
        cudaStreamCreateWithFlags(&s_cs, cudaStreamNonBlocking);
        cudaEventCreateWithFlags(&ev_fork, cudaEventDisableTiming);
        cudaEventCreateWithFlags(&ev_join, cudaEventDisableTiming);
    }

    // ---- fork: CSR build on side stream ----
    cudaEventRecord(ev_fork, 0);
    cudaStreamWaitEvent(s_cs, ev_fork, 0);
    cudaMemsetAsync(zreg, 0, (N_NODES + N_GRAPHS * 32) * sizeof(int), s_cs);
    count_kernel<<<(N_EDGES + 255) / 256, 256, 0, s_cs>>>(ei);
    scan1_kernel<<<N_BLK, 256, 0, s_cs>>>();
    scan3_kernel<<<N_BLK, 256, 0, s_cs>>>();
    scatter_kernel<<<(TOT_E + 255) / 256, 256, 0, s_cs>>>(ei);
    cudaEventRecord(ev_join, s_cs);

    // ---- main chain ----
    prep_kernel<<<(N_NODES * 64 / 4 + 255) / 256, 256>>>(x, W1, W2, W3);

    const int GY = (N_NODES + 127) / 128;

    // gemm1: PDL after prep (no B prefetch — prep may still be running)
    launch_pdl(gemm_att, dim3((HC1 + 127) / 128, GY), dim3(256),
               (const __nv_bfloat16*)xq, (const __nv_bfloat16*)w1q, h1,
               att_s1, att_d1, as1, ad1, N_NODES, HC1, 64, 5, 64, 0);

    // agg1: NORMAL launch (full dependency) — also carries the CSR join.
    // This anchors "prep complete" for all later pre-sync weight prefetches.
    cudaStreamWaitEvent(0, ev_join, 0);
    gat_agg5<64><<<N_NODES, 192>>>(h1, as1, ad1, b1, o1);

    launch_pdl(gemm_att, dim3((HC2 + 127) / 128, GY), dim3(256),
               (const __nv_bfloat16*)o1, (const __nv_bfloat16*)w2q, h2,
               att_s2, att_d2, as2, ad2, N_NODES, HC2, HC1, 5, 96, 1);
    launch_pdl(gat_agg5<96>, dim3(N_NODES), dim3(192), (const __nv_bfloat16*)h2,
               (const float*)as2, (const float*)ad2, b2, o2);

    launch_pdl(gemm_att, dim3((HC3 + 127) / 128, GY), dim3(256),
               (const __nv_bfloat16*)o2, (const __nv_bfloat16*)w3q, h3,
               att_s3, att_d3, as3, ad3, N_NODES, HC3, HC2, 1, 32, 1);
    launch_pdl(gat_agg1_pool, dim3((N_NODES + 7) / 8), dim3(256),
               (const __nv_bfloat16*)h3, (const float*)as3, (const float*)ad3,
               b3, batch);

    launch_pdl(mlp_kernel, dim3(N_GRAPHS), dim3(256),
               lin_w, lin_b, lin2_w, lin2_b, out);
}

// round 11
// speedup vs baseline: 1.0515x; 1.0237x over previous
#include <cuda_runtime.h>
#include <cuda_bf16.h>
#include <math.h>
#include <stdint.h>

// ---------------------------------------------------------------------------
// Problem constants
// ---------------------------------------------------------------------------
#define N_NODES 20000
#define N_EDGES 320000
#define TOT_E   (N_EDGES + N_NODES)
#define N_GRAPHS 128
#define NEG_SLOPE 0.2f
#define EPS_F 1e-16f

#define HC1 320   // H=5, C=64
#define HC2 480   // H=5, C=96
#define HC3 32    // H=1, C=32

#define N_BLK ((N_NODES + 255) / 256)   // 79

// ---------------------------------------------------------------------------
// Device scratch
// ---------------------------------------------------------------------------
__device__ __align__(16) __nv_bfloat16 g_xq[N_NODES * 64];
__device__ __align__(16) __nv_bfloat16 g_w1q[HC1 * 64];
__device__ __align__(16) __nv_bfloat16 g_w2q[HC2 * HC1];
__device__ __align__(16) __nv_bfloat16 g_w3q[HC3 * HC2];
__device__ __align__(16) __nv_bfloat16 g_h1[N_NODES * HC1];
__device__ __align__(16) __nv_bfloat16 g_o1[N_NODES * HC1];
__device__ __align__(16) __nv_bfloat16 g_h2[N_NODES * HC2];
__device__ __align__(16) __nv_bfloat16 g_o2[N_NODES * HC2];
__device__ __align__(16) __nv_bfloat16 g_h3[N_NODES * HC3];
__device__ float g_att[6 * N_NODES * 5];
// contiguous zero region: cnt (N_NODES ints) + pool (N_GRAPHS*32 floats)
__device__ int   g_zero[N_NODES + N_GRAPHS * 32];
__device__ int   g_rowptr[N_NODES + 1];
__device__ int   g_cursor[N_NODES];
__device__ int   g_csrc[TOT_E];
__device__ int   g_bsum[N_BLK];

__device__ __forceinline__ uint32_t pack_bf16x2(float lo, float hi) {
    __nv_bfloat162 h2 = __floats2bfloat162_rn(lo, hi);
    return *(uint32_t*)&h2;
}

// ---------------------------------------------------------------------------
// prep: x -> bf16, W1/2/3 -> bf16, zero att accumulators
// ---------------------------------------------------------------------------
#define W1Q4 (HC1 * 64 / 4)       // 5120
#define W2Q4 (HC2 * HC1 / 4)      // 38400
#define W3Q4 (HC3 * HC2 / 4)      // 3840

__global__ void prep_kernel(const float* __restrict__ x,
                            const float* __restrict__ W1,
                            const float* __restrict__ W2,
                            const float* __restrict__ W3) {
    int i = blockIdx.x * 256 + threadIdx.x;
    if (i < N_NODES * 64 / 4) {
        float4 v = ((const float4*)x)[i];
        uint2 p;
        p.x = pack_bf16x2(v.x, v.y);
        p.y = pack_bf16x2(v.z, v.w);
        ((uint2*)g_xq)[i] = p;
    }
    if (2 * i < 6 * N_NODES * 5) {
        g_att[2 * i] = 0.f;
        if (2 * i + 1 < 6 * N_NODES * 5) g_att[2 * i + 1] = 0.f;
    }
    if (i < W1Q4 + W2Q4 + W3Q4) {
        const float4* src;
        uint2* dst;
        int j = i;
        if (j < W1Q4)                { src = (const float4*)W1; dst = (uint2*)g_w1q; }
        else if ((j -= W1Q4) < W2Q4) { src = (const float4*)W2; dst = (uint2*)g_w2q; }
        else { j -= W2Q4;              src = (const float4*)W3; dst = (uint2*)g_w3q; }
        float4 v = src[j];
        uint2 p;
        p.x = pack_bf16x2(v.x, v.y);
        p.y = pack_bf16x2(v.z, v.w);
        dst[j] = p;
    }
}

// ---------------------------------------------------------------------------
// CSR construction
// ---------------------------------------------------------------------------
__global__ void count_kernel(const int* __restrict__ ei) {
    int i = blockIdx.x * blockDim.x + threadIdx.x;
    if (i < N_EDGES) atomicAdd(&g_zero[ei[N_EDGES + i]], 1);
}

__global__ void scan1_kernel() {
    int i = blockIdx.x * 256 + threadIdx.x;
    int lane = threadIdx.x & 31, w = threadIdx.x >> 5;
    int x = (i < N_NODES) ? (g_zero[i] + 1) : 0;
#pragma unroll
    for (int o = 1; o < 32; o <<= 1) {
        int t = __shfl_up_sync(0xffffffffu, x, o);
        if (lane >= o) x += t;
    }
    __shared__ int wsum[8];
    if (lane == 31) wsum[w] = x;
    __syncthreads();
    if (w == 0) {
        int s = (lane < 8) ? wsum[lane] : 0;
#pragma unroll
        for (int o = 1; o < 8; o <<= 1) {
            int t = __shfl_up_sync(0xffffffffu, s, o);
            if (lane >= o) s += t;
        }
        if (lane < 8) wsum[lane] = s;
    }
    __syncthreads();
    int incl = x + ((w > 0) ? wsum[w - 1] : 0);
    if (i < N_NODES) g_rowptr[i + 1] = incl;
    if (threadIdx.x == 255) g_bsum[blockIdx.x] = incl;
}

__global__ void scan3_kernel() {
    __shared__ int s_off;
    int tid = threadIdx.x, lane = tid & 31;
    if (tid < 32) {
        int off = 0;
        for (int j = lane; j < blockIdx.x; j += 32) off += g_bsum[j];
#pragma unroll
        for (int o = 16; o > 0; o >>= 1)
            off += __shfl_xor_sync(0xffffffffu, off, o);
        if (lane == 0) s_off = off;
    }
    __syncthreads();
    int i = blockIdx.x * 256 + tid;
    if (i == 0) g_rowptr[0] = 0;
    if (i < N_NODES) {
        int incl = g_rowptr[i + 1] + s_off;
        g_rowptr[i + 1] = incl;
        g_cursor[i] = incl - (g_zero[i] + 1);
    }
}

__global__ void scatter_kernel(const int* __restrict__ ei) {
    int i = blockIdx.x * blockDim.x + threadIdx.x;
    if (i >= TOT_E) return;
    int src, dst;
    if (i < N_EDGES) { src = ei[i]; dst = ei[N_EDGES + i]; }
    else             { src = dst = i - N_EDGES; }
    int pos = atomicAdd(&g_cursor[dst], 1);
    g_csrc[pos] = src;
}

// ---------------------------------------------------------------------------
// bf16 GEMM, 3-stage cp.async pipeline (dynamic smem) + fused attention
// epilogue + PDL. Template NSUB: BN = 16*NSUB (NSUB=8 -> BN=128; 2 -> BN=32).
// BM=128, BK=32; 8 warps (4M x 2N), warp tile 32 x (BN/2).
// smem row = 32 bf16 = 16 uint32, padded to 20 (80B).
// ---------------------------------------------------------------------------
#define SROW 20
#define A_STAGE_U32 (128 * SROW)            // uint32 per A stage

__device__ __forceinline__ void cp16(uint32_t dst, const void* src, int bytes) {
    asm volatile("cp.async.cg.shared.global [%0], [%1], 16, %2;"
                 :: "r"(dst), "l"(src), "r"(bytes));
}
__device__ __forceinline__ void cp_commit() {
    asm volatile("cp.async.commit_group;");
}
template<int N>
__device__ __forceinline__ void cp_wait() {
    asm volatile("cp.async.wait_group %0;" :: "n"(N));
}

template<int NSUB>
__global__ void __launch_bounds__(256, 2)
gemm_att(const __nv_bfloat16* __restrict__ A, const __nv_bfloat16* __restrict__ B,
         __nv_bfloat16* __restrict__ C,
         const float* __restrict__ att_src, const float* __restrict__ att_dst,
         float* __restrict__ asrc, float* __restrict__ adst,
         int N, int M, int K, int H, int Cc, int prefetchB) {
    const int BN = NSUB * 16, BK = 32;
    const int B_STAGE_U32 = BN * SROW;
    extern __shared__ uint32_t dynsmem[];
    uint32_t* AsBase = dynsmem;                       // 3 stages of A
    uint32_t* BsBase = dynsmem + 3 * A_STAGE_U32;     // 3 stages of B

    int tid  = threadIdx.x;
    int lane = tid & 31;
    int wid  = tid >> 5;
    int wr = (wid & 3) * 32;
    int wc = (wid >> 2) * (BN / 2);
    int gid = lane >> 2;
    int tig = lane & 3;

    int blockRow = blockIdx.y * 128;
    int blockCol = blockIdx.x * BN;

    int r0c = (tid + 0)   >> 2, q0 = (tid + 0)   & 3;
    int r1c = (tid + 256) >> 2, q1 = (tid + 256) & 3;

    uint32_t asm0 = (uint32_t)__cvta_generic_to_shared(AsBase);
    uint32_t bsm0 = (uint32_t)__cvta_generic_to_shared(BsBase);

    auto issueA = [&](int k0, int st) {
        uint32_t base = asm0 + st * (A_STAGE_U32 * 4);
        int ba0 = (blockRow + r0c < N) ? 16 : 0;
        int ba1 = (blockRow + r1c < N) ? 16 : 0;
        cp16(base + (r0c * SROW + q0 * 4) * 4,
             A + (size_t)(blockRow + r0c) * K + k0 + q0 * 8, ba0);
        cp16(base + (r1c * SROW + q1 * 4) * 4,
             A + (size_t)(blockRow + r1c) * K + k0 + q1 * 8, ba1);
    };
    auto issueB = [&](int k0, int st) {
        uint32_t base = bsm0 + st * (B_STAGE_U32 * 4);
        for (int c = tid; c < BN * 4; c += 256) {
            int row = c >> 2, q = c & 3;
            int bb = (blockCol + row < M) ? 16 : 0;
            cp16(base + (row * SROW + q * 4) * 4,
                 B + (size_t)(blockCol + row) * K + k0 + q * 8, bb);
        }
    };

    float acc[2][NSUB][4];
#pragma unroll
    for (int mt = 0; mt < 2; mt++)
#pragma unroll
        for (int nt = 0; nt < NSUB; nt++)
#pragma unroll
            for (int i = 0; i < 4; i++) acc[mt][nt][i] = 0.f;

    int nIt = K / BK;

    // PDL prologue: weight prefetch pre-sync when provably safe.
    if (prefetchB) issueB(0, 0);
    cudaGridDependencySynchronize();
    issueA(0, 0);
    if (!prefetchB) issueB(0, 0);
    cp_commit();                                    // stage 0
    if (nIt > 1) {
        issueA(BK, 1);
        issueB(BK, 1);
        cp_commit();                                // stage 1
    }

    for (int it = 0; it < nIt; it++) {
        int buf = it % 3;
        if (it + 2 < nIt) {
            issueA((it + 2) * BK, (it + 2) % 3);
            issueB((it + 2) * BK, (it + 2) % 3);
            cp_commit();
            cp_wait<2>();
        } else if (it + 1 < nIt) {
            cp_wait<1>();
        } else {
            cp_wait<0>();
        }
        __syncthreads();

        const uint32_t* As = AsBase + buf * A_STAGE_U32;
        const uint32_t* Bs = BsBase + buf * B_STAGE_U32;

#pragma unroll
        for (int ks = 0; ks < 2; ks++) {
            int kb = ks * 8;
            uint32_t a[2][4], b[NSUB][2];
#pragma unroll
            for (int mt = 0; mt < 2; mt++) {
                int r0 = wr + mt * 16;
                a[mt][0] = As[(r0 + gid    ) * SROW + kb + tig    ];
                a[mt][1] = As[(r0 + gid + 8) * SROW + kb + tig    ];
                a[mt][2] = As[(r0 + gid    ) * SROW + kb + tig + 4];
                a[mt][3] = As[(r0 + gid + 8) * SROW + kb + tig + 4];
            }
#pragma unroll
            for (int nt = 0; nt < NSUB; nt++) {
                int n0 = wc + nt * 8 + gid;
                b[nt][0] = Bs[n0 * SROW + kb + tig    ];
                b[nt][1] = Bs[n0 * SROW + kb + tig + 4];
            }
#pragma unroll
            for (int mt = 0; mt < 2; mt++)
#pragma unroll
                for (int nt = 0; nt < NSUB; nt++) {
                    asm volatile(
                        "mma.sync.aligned.m16n8k16.row.col.f32.bf16.bf16.f32 "
                        "{%0,%1,%2,%3}, {%4,%5,%6,%7}, {%8,%9}, {%0,%1,%2,%3};"
                        : "+f"(acc[mt][nt][0]), "+f"(acc[mt][nt][1]),
                          "+f"(acc[mt][nt][2]), "+f"(acc[mt][nt][3])
                        : "r"(a[mt][0]), "r"(a[mt][1]), "r"(a[mt][2]), "r"(a[mt][3]),
                          "r"(b[nt][0]), "r"(b[nt][1]));
                }
        }
        __syncthreads();
    }

    // ---- store C + att partials ----
    int h_first = (blockCol + wc) / Cc;
    float psrc[2][2][2] = {};
    float pdst[2][2][2] = {};

#pragma unroll
    for (int mt = 0; mt < 2; mt++) {
#pragma unroll
        for (int nt = 0; nt < NSUB; nt++) {
            int r0 = blockRow + wr + mt * 16 + gid;
            int c0 = blockCol + wc + nt * 8 + tig * 2;
            if (c0 < M) {
                if (r0 < N)
                    *(uint32_t*)(C + (size_t)r0 * M + c0) =
                        pack_bf16x2(acc[mt][nt][0], acc[mt][nt][1]);
                if (r0 + 8 < N)
                    *(uint32_t*)(C + (size_t)(r0 + 8) * M + c0) =
                        pack_bf16x2(acc[mt][nt][2], acc[mt][nt][3]);
                int hb = (blockCol + wc + nt * 8) / Cc - h_first;
                float a0 = att_src[c0], a1 = att_src[c0 + 1];
                float d0 = att_dst[c0], d1 = att_dst[c0 + 1];
                psrc[mt][0][hb] += acc[mt][nt][0] * a0 + acc[mt][nt][1] * a1;
                psrc[mt][1][hb] += acc[mt][nt][2] * a0 + acc[mt][nt][3] * a1;
                pdst[mt][0][hb] += acc[mt][nt][0] * d0 + acc[mt][nt][1] * d1;
                pdst[mt][1][hb] += acc[mt][nt][2] * d0 + acc[mt][nt][3] * d1;
            }
        }
    }
#pragma unroll
    for (int mt = 0; mt < 2; mt++)
#pragma unroll
        for (int hf = 0; hf < 2; hf++)
#pragma unroll
            for (int bk = 0; bk < 2; bk++) {
                float s = psrc[mt][hf][bk], d = pdst[mt][hf][bk];
                s += __shfl_xor_sync(0xffffffffu, s, 1);
                s += __shfl_xor_sync(0xffffffffu, s, 2);
                d += __shfl_xor_sync(0xffffffffu, d, 1);
                d += __shfl_xor_sync(0xffffffffu, d, 2);
                psrc[mt][hf][bk] = s; pdst[mt][hf][bk] = d;
            }
    if (tig == 0) {
#pragma unroll
        for (int mt = 0; mt < 2; mt++)
#pragma unroll
            for (int hf = 0; hf < 2; hf++) {
                int row = blockRow + wr + mt * 16 + gid + hf * 8;
                if (row >= N) continue;
#pragma unroll
                for (int bk = 0; bk < 2; bk++) {
                    int hidx = h_first + bk;
                    if (hidx < H) {
                        atomicAdd(&asrc[row * H + hidx], psrc[mt][hf][bk]);
                        atomicAdd(&adst[row * H + hidx], pdst[mt][hf][bk]);
                    }
                }
            }
    }
}

// ---------------------------------------------------------------------------
// GAT aggregation, H=5. 192 thr/node, single-pass smem softmax, PDL entry.
// ---------------------------------------------------------------------------
template<int C>
__global__ void __launch_bounds__(192)
gat_agg5(const __nv_bfloat16* __restrict__ hfeat,
         const float* __restrict__ asrc,
         const float* __restrict__ adst,
         const float* __restrict__ bias,
         __nv_bfloat16* __restrict__ out) {
    const int HC = 5 * C, NC4 = HC / 4;
    const int EMAX = 128;
    __shared__ float s_e[EMAX * 5];
    __shared__ int   s_src[EMAX];
    __shared__ float s_m[5], s_iz[5], s_ad[5];

    cudaGridDependencySynchronize();

    int v = blockIdx.x;
    int tid = threadIdx.x, lane = tid & 31, wid = tid >> 5;
    int base = g_rowptr[v];
    int deg = g_rowptr[v + 1] - base;

    if (tid < 5) s_ad[tid] = adst[v * 5 + tid];
    __syncthreads();

    float4 acc = make_float4(0.f, 0.f, 0.f, 0.f);
    int head = (tid * 4) / C;

    if (deg <= EMAX) {
        for (int idx = tid; idx < deg * 5; idx += 192) {
            int j = idx / 5, hh = idx - j * 5;
            int s = g_csrc[base + j];
            if (hh == 0) s_src[j] = s;
            float e = asrc[s * 5 + hh] + s_ad[hh];
            s_e[idx] = (e > 0.f) ? e : NEG_SLOPE * e;
        }
        __syncthreads();
        if (wid < 5) {
            int h = wid;
            float m = -INFINITY;
            for (int j = lane; j < deg; j += 32)
                m = fmaxf(m, s_e[j * 5 + h]);
#pragma unroll
            for (int o = 16; o > 0; o >>= 1)
                m = fmaxf(m, __shfl_xor_sync(0xffffffffu, m, o));
            float z = 0.f;
            for (int j = lane; j < deg; j += 32) {
                float ex = __expf(s_e[j * 5 + h] - m);
                s_e[j * 5 + h] = ex;
                z += ex;
            }
#pragma unroll
            for (int o = 16; o > 0; o >>= 1)
                z += __shfl_xor_sync(0xffffffffu, z, o);
            if (lane == 0) s_iz[h] = 1.f / (z + EPS_F);
        }
        __syncthreads();
        for (int idx = tid; idx < deg * 5; idx += 192) {
            int hh = idx % 5;
            s_e[idx] *= s_iz[hh];
        }
        __syncthreads();
        if (tid < NC4) {
#pragma unroll 2
            for (int j = 0; j < deg; j++) {
                const uint2* hp = (const uint2*)(hfeat + (size_t)s_src[j] * HC);
                float w = s_e[j * 5 + head];
                uint2 hv = hp[tid];
                float2 lo = __bfloat1622float2(*(__nv_bfloat162*)&hv.x);
                float2 hi = __bfloat1622float2(*(__nv_bfloat162*)&hv.y);
                acc.x += w * lo.x; acc.y += w * lo.y;
                acc.z += w * hi.x; acc.w += w * hi.y;
            }
        }
    } else {
        if (wid < 5) {
            int h = wid;
            float ad = s_ad[h];
            float m = -INFINITY;
            for (int j = lane; j < deg; j += 32) {
                int s = g_csrc[base + j];
                float e = asrc[s * 5 + h] + ad;
                e = (e > 0.f) ? e : NEG_SLOPE * e;
                m = fmaxf(m, e);
            }
#pragma unroll
            for (int o = 16; o > 0; o >>= 1)
                m = fmaxf(m, __shfl_xor_sync(0xffffffffu, m, o));
            float z = 0.f;
            for (int j = lane; j < deg; j += 32) {
                int s = g_csrc[base + j];
                float e = asrc[s * 5 + h] + ad;
                e = (e > 0.f) ? e : NEG_SLOPE * e;
                z += __expf(e - m);
            }
#pragma unroll
            for (int o = 16; o > 0; o >>= 1)
                z += __shfl_xor_sync(0xffffffffu, z, o);
            if (lane == 0) { s_m[h] = m; s_iz[h] = 1.f / (z + EPS_F); }
        }
        __syncthreads();
        for (int j0 = 0; j0 < deg; j0 += EMAX) {
            int ch = min(EMAX, deg - j0);
            for (int idx = tid; idx < ch * 5; idx += 192) {
                int j = idx / 5, hh = idx - j * 5;
                int s = g_csrc[base + j0 + j];
                if (hh == 0) s_src[j] = s;
                float e = asrc[s * 5 + hh] + s_ad[hh];
                e = (e > 0.f) ? e : NEG_SLOPE * e;
                s_e[j * 5 + hh] = __expf(e - s_m[hh]) * s_iz[hh];
            }
            __syncthreads();
            if (tid < NC4) {
                for (int j = 0; j < ch; j++) {
                    const uint2* hp = (const uint2*)(hfeat + (size_t)s_src[j] * HC);
                    float w = s_e[j * 5 + head];
                    uint2 hv = hp[tid];
                    float2 lo = __bfloat1622float2(*(__nv_bfloat162*)&hv.x);
                    float2 hi = __bfloat1622float2(*(__nv_bfloat162*)&hv.y);
                    acc.x += w * lo.x; acc.y += w * lo.y;
                    acc.z += w * hi.x; acc.w += w * hi.y;
                }
            }
            __syncthreads();
        }
    }

    if (tid < NC4) {
        float4 b = ((const float4*)bias)[tid];
        uint2 o;
        o.x = pack_bf16x2(fmaxf(acc.x + b.x, 0.f), fmaxf(acc.y + b.y, 0.f));
        o.y = pack_bf16x2(fmaxf(acc.z + b.z, 0.f), fmaxf(acc.w + b.w, 0.f));
        ((uint2*)(out + (size_t)v * HC))[tid] = o;
    }
}

// ---------------------------------------------------------------------------
// GAT aggregation, H=1, C=32 + fused global_add_pool. warp per node.
// ---------------------------------------------------------------------------
__global__ void __launch_bounds__(256)
gat_agg1_pool(const __nv_bfloat16* __restrict__ hfeat,
              const float* __restrict__ asrc,
              const float* __restrict__ adst,
              const float* __restrict__ bias,
              const int* __restrict__ batch) {
    cudaGridDependencySynchronize();

    int wid = threadIdx.x >> 5, lane = threadIdx.x & 31;
    int v = blockIdx.x * 8 + wid;
    if (v >= N_NODES) return;
    int base = g_rowptr[v];
    int deg = g_rowptr[v + 1] - base;
    float ad = adst[v];
    float* pool = (float*)(g_zero + N_NODES);

    float m = -INFINITY;
    for (int j = lane; j < deg; j += 32) {
        int s = g_csrc[base + j];
        float e = asrc[s] + ad;
        e = (e > 0.f) ? e : NEG_SLOPE * e;
        m = fmaxf(m, e);
    }
#pragma unroll
    for (int o = 16; o > 0; o >>= 1)
        m = fmaxf(m, __shfl_xor_sync(0xffffffffu, m, o));
    float z = 0.f;
    for (int j = lane; j < deg; j += 32) {
        int s = g_csrc[base + j];
        float e = asrc[s] + ad;
        e = (e > 0.f) ? e : NEG_SLOPE * e;
        z += __expf(e - m);
    }
#pragma unroll
    for (int o = 16; o > 0; o >>= 1)
        z += __shfl_xor_sync(0xffffffffu, z, o);
    float iz = 1.f / (z + EPS_F);

    float acc = 0.f;
#pragma unroll 2
    for (int j = 0; j < deg; j++) {
        int s = g_csrc[base + j];
        float e = asrc[s] + ad;
        e = (e > 0.f) ? e : NEG_SLOPE * e;
        float w = __expf(e - m) * iz;
        acc += w * __bfloat162float(hfeat[(size_t)s * 32 + lane]);
    }
    float o = fmaxf(acc + bias[lane], 0.f);
    atomicAdd(&pool[batch[v] * 32 + lane], o);
}

// ---------------------------------------------------------------------------
// MLP head
// ---------------------------------------------------------------------------
__global__ void mlp_kernel(const float* __restrict__ lin_w,
                           const float* __restrict__ lin_b,
                           const float* __restrict__ lin2_w,
                           const float* __restrict__ lin2_b,
                           float* __restrict__ out) {
    cudaGridDependencySynchronize();

    int g = blockIdx.x;
    __shared__ float sg[32];
    __shared__ float sred[256];
    int tid = threadIdx.x;
    const float* pool = (const float*)(g_zero + N_NODES);
    if (tid < 32) sg[tid] = pool[g * 32 + tid];
    __syncthreads();
    float partial = 0.f;
    for (int u = tid; u < 1024; u += 256) {
        float d = lin_b[u];
        const float* wr = lin_w + u * 32;
#pragma unroll
        for (int c = 0; c < 32; c++) d += sg[c] * wr[c];
        d = fmaxf(d, 0.f);
        partial += d * lin2_w[u];
    }
    sred[tid] = partial;
    __syncthreads();
    for (int s = 128; s > 0; s >>= 1) {
        if (tid < s) sred[tid] += sred[tid + s];
        __syncthreads();
    }
    if (tid == 0) {
        float v = sred[0] + lin2_b[0];
        out[g] = 1.f / (1.f + __expf(-v));
    }
}

// ---------------------------------------------------------------------------
// PDL launch helper (with optional dynamic smem)
// ---------------------------------------------------------------------------
template<typename Kern, typename... Args>
static inline void launch_pdl(Kern k, dim3 grid, dim3 block, size_t smem,
                              Args... args) {
    cudaLaunchConfig_t cfg = {};
    cfg.gridDim = grid;
    cfg.blockDim = block;
    cfg.dynamicSmemBytes = smem;
    cfg.stream = 0;
    cudaLaunchAttribute attr[1];
    attr[0].id = cudaLaunchAttributeProgrammaticStreamSerialization;
    attr[0].val.programmaticStreamSerializationAllowed = 1;
    cfg.attrs = attr;
    cfg.numAttrs = 1;
    cudaLaunchKernelEx(&cfg, k, args...);
}

#define GEMM_SMEM(NSUB) ((3 * A_STAGE_U32 + 3 * (NSUB) * 16 * SROW) * 4)

// ---------------------------------------------------------------------------
// launch
// ---------------------------------------------------------------------------
extern "C" void kernel_launch(void* const* d_in, const int* in_sizes, int n_in,
                              void* d_out, int out_size) {
    const float* x        = (const float*)d_in[0];
    const float* W1       = (const float*)d_in[1];
    const float* att_s1   = (const float*)d_in[2];
    const float* att_d1   = (const float*)d_in[3];
    const float* b1       = (const float*)d_in[4];
    const float* W2       = (const float*)d_in[5];
    const float* att_s2   = (const float*)d_in[6];
    const float* att_d2   = (const float*)d_in[7];
    const float* b2       = (const float*)d_in[8];
    const float* W3       = (const float*)d_in[9];
    const float* att_s3   = (const float*)d_in[10];
    const float* att_d3   = (const float*)d_in[11];
    const float* b3       = (const float*)d_in[12];
    const float* lin_w    = (const float*)d_in[13];
    const float* lin_b    = (const float*)d_in[14];
    const float* lin2_w   = (const float*)d_in[15];
    const float* lin2_b   = (const float*)d_in[16];
    const int*   ei       = (const int*)d_in[17];
    const int*   batch    = (const int*)d_in[18];
    float* out = (float*)d_out;

    __nv_bfloat16 *xq, *w1q, *w2q, *w3q, *h1, *o1, *h2, *o2, *h3;
    float *attbuf;
    int *zreg;
    cudaGetSymbolAddress((void**)&xq, g_xq);
    cudaGetSymbolAddress((void**)&w1q, g_w1q);
    cudaGetSymbolAddress((void**)&w2q, g_w2q);
    cudaGetSymbolAddress((void**)&w3q, g_w3q);
    cudaGetSymbolAddress((void**)&h1, g_h1);
    cudaGetSymbolAddress((void**)&o1, g_o1);
    cudaGetSymbolAddress((void**)&h2, g_h2);
    cudaGetSymbolAddress((void**)&o2, g_o2);
    cudaGetSymbolAddress((void**)&h3, g_h3);
    cudaGetSymbolAddress((void**)&attbuf, g_att);
    cudaGetSymbolAddress((void**)&zreg, g_zero);

    float* as1 = attbuf;                    float* ad1 = attbuf + N_NODES * 5;
    float* as2 = attbuf + 2 * N_NODES * 5;  float* ad2 = attbuf + 3 * N_NODES * 5;
    float* as3 = attbuf + 4 * N_NODES * 5;  float* ad3 = attbuf + 5 * N_NODES * 5;

    static cudaStream_t s_cs = nullptr;
    static cudaEvent_t ev_fork = nullptr, ev_join = nullptr;
    if (!s_cs) {
        cudaStreamCreateWithFlags(&s_cs, cudaStreamNonBlocking);
        cudaEventCreateWithFlags(&ev_fork, cudaEventDisableTiming);
        cudaEventCreateWithFlags(&ev_join, cudaEventDisableTiming);
        cudaFuncSetAttribute(gemm_att<8>,
                             cudaFuncAttributeMaxDynamicSharedMemorySize,
                             GEMM_SMEM(8));
        cudaFuncSetAttribute(gemm_att<2>,
                             cudaFuncAttributeMaxDynamicSharedMemorySize,
                             GEMM_SMEM(2));
    }

    // ---- fork: CSR build on side stream ----
    cudaEventRecord(ev_fork, 0);
    cudaStreamWaitEvent(s_cs, ev_fork, 0);
    cudaMemsetAsync(zreg, 0, (N_NODES + N_GRAPHS * 32) * sizeof(int), s_cs);
    count_kernel<<<(N_EDGES + 255) / 256, 256, 0, s_cs>>>(ei);
    scan1_kernel<<<N_BLK, 256, 0, s_cs>>>();
    scan3_kernel<<<N_BLK, 256, 0, s_cs>>>();
    scatter_kernel<<<(TOT_E + 255) / 256, 256, 0, s_cs>>>(ei);
    cudaEventRecord(ev_join, s_cs);

    // ---- main chain ----
    prep_kernel<<<(N_NODES * 64 / 4 + 255) / 256, 256>>>(x, W1, W2, W3);

    const int GY = (N_NODES + 127) / 128;

    // gemm1: PDL after prep (no B prefetch — prep may still be running)
    launch_pdl(gemm_att<8>, dim3((HC1 + 127) / 128, GY), dim3(256), GEMM_SMEM(8),
               (const __nv_bfloat16*)xq, (const __nv_bfloat16*)w1q, h1,
               att_s1, att_d1, as1, ad1, N_NODES, HC1, 64, 5, 64, 0);

    // agg1: NORMAL launch (full dependency) — also carries the CSR join.
    // This anchors "prep complete" for all later pre-sync weight prefetches.
    cudaStreamWaitEvent(0, ev_join, 0);
    gat_agg5<64><<<N_NODES, 192>>>(h1, as1, ad1, b1, o1);

    launch_pdl(gemm_att<8>, dim3((HC2 + 127) / 128, GY), dim3(256), GEMM_SMEM(8),
               (const __nv_bfloat16*)o1, (const __nv_bfloat16*)w2q, h2,
               att_s2, att_d2, as2, ad2, N_NODES, HC2, HC1, 5, 96, 1);
    launch_pdl(gat_agg5<96>, dim3(N_NODES), dim3(192), (size_t)0,
               (const __nv_bfloat16*)h2,
               (const float*)as2, (const float*)ad2, b2, o2);

    // layer 3: BN=32 exact-fit GEMM (no masked mma waste)
    launch_pdl(gemm_att<2>, dim3(1, GY), dim3(256), GEMM_SMEM(2),
               (const __nv_bfloat16*)o2, (const __nv_bfloat16*)w3q, h3,
               att_s3, att_d3, as3, ad3, N_NODES, HC3, HC2, 1, 32, 1);
    launch_pdl(gat_agg1_pool, dim3((N_NODES + 7) / 8), dim3(256), (size_t)0,
               (const __nv_bfloat16*)h3, (const float*)as3, (const float*)ad3,
               b3, batch);

    launch_pdl(mlp_kernel, dim3(N_GRAPHS), dim3(256), (size_t)0,
               lin_w, lin_b, lin2_w, lin2_b, out);
}

// round 12
// speedup vs baseline: 1.2036x; 1.1447x over previous
#include <cuda_runtime.h>
#include <cuda_bf16.h>
#include <math.h>
#include <stdint.h>

// ---------------------------------------------------------------------------
// Problem constants
// ---------------------------------------------------------------------------
#define N_NODES 20000
#define N_EDGES 320000
#define TOT_E   (N_EDGES + N_NODES)
#define N_GRAPHS 128
#define NEG_SLOPE 0.2f
#define EPS_F 1e-16f

#define HC1 320   // H=5, C=64
#define HC2 480   // H=5, C=96
#define HC3 32    // H=1, C=32

#define N_BLK ((N_NODES + 255) / 256)   // 79

// ---------------------------------------------------------------------------
// Device scratch
// ---------------------------------------------------------------------------
__device__ __align__(16) __nv_bfloat16 g_xq[N_NODES * 64];
__device__ __align__(16) __nv_bfloat16 g_w1q[HC1 * 64];
__device__ __align__(16) __nv_bfloat16 g_w2q[HC2 * HC1];
__device__ __align__(16) __nv_bfloat16 g_w3q[HC3 * HC2];
__device__ __align__(16) __nv_bfloat16 g_h1[N_NODES * HC1];
__device__ __align__(16) __nv_bfloat16 g_o1[N_NODES * HC1];
__device__ __align__(16) __nv_bfloat16 g_h2[N_NODES * HC2];
__device__ __align__(16) __nv_bfloat16 g_o2[N_NODES * HC2];
__device__ __align__(16) __nv_bfloat16 g_h3[N_NODES * HC3];
__device__ float g_att[6 * N_NODES * 5];
// contiguous zero region: cnt (N_NODES ints) + pool (N_GRAPHS*32 floats)
__device__ int   g_zero[N_NODES + N_GRAPHS * 32];
__device__ int   g_rowptr[N_NODES + 1];
__device__ int   g_cursor[N_NODES];
__device__ int   g_csrc[TOT_E];
__device__ int   g_bsum[N_BLK];

__device__ __forceinline__ uint32_t pack_bf16x2(float lo, float hi) {
    __nv_bfloat162 h2 = __floats2bfloat162_rn(lo, hi);
    return *(uint32_t*)&h2;
}

// ---------------------------------------------------------------------------
// prep: x -> bf16, W1/2/3 -> bf16, zero att accumulators
// ---------------------------------------------------------------------------
#define W1Q4 (HC1 * 64 / 4)       // 5120
#define W2Q4 (HC2 * HC1 / 4)      // 38400
#define W3Q4 (HC3 * HC2 / 4)      // 3840

__global__ void prep_kernel(const float* __restrict__ x,
                            const float* __restrict__ W1,
                            const float* __restrict__ W2,
                            const float* __restrict__ W3) {
    int i = blockIdx.x * 256 + threadIdx.x;
    if (i < N_NODES * 64 / 4) {
        float4 v = ((const float4*)x)[i];
        uint2 p;
        p.x = pack_bf16x2(v.x, v.y);
        p.y = pack_bf16x2(v.z, v.w);
        ((uint2*)g_xq)[i] = p;
    }
    if (2 * i < 6 * N_NODES * 5) {
        g_att[2 * i] = 0.f;
        if (2 * i + 1 < 6 * N_NODES * 5) g_att[2 * i + 1] = 0.f;
    }
    if (i < W1Q4 + W2Q4 + W3Q4) {
        const float4* src;
        uint2* dst;
        int j = i;
        if (j < W1Q4)                { src = (const float4*)W1; dst = (uint2*)g_w1q; }
        else if ((j -= W1Q4) < W2Q4) { src = (const float4*)W2; dst = (uint2*)g_w2q; }
        else { j -= W2Q4;              src = (const float4*)W3; dst = (uint2*)g_w3q; }
        float4 v = src[j];
        uint2 p;
        p.x = pack_bf16x2(v.x, v.y);
        p.y = pack_bf16x2(v.z, v.w);
        dst[j] = p;
    }
}

// ---------------------------------------------------------------------------
// CSR construction
// ---------------------------------------------------------------------------
__global__ void count_kernel(const int* __restrict__ ei) {
    int i = blockIdx.x * blockDim.x + threadIdx.x;
    if (i < N_EDGES) atomicAdd(&g_zero[ei[N_EDGES + i]], 1);
}

__global__ void scan1_kernel() {
    int i = blockIdx.x * 256 + threadIdx.x;
    int lane = threadIdx.x & 31, w = threadIdx.x >> 5;
    int x = (i < N_NODES) ? (g_zero[i] + 1) : 0;
#pragma unroll
    for (int o = 1; o < 32; o <<= 1) {
        int t = __shfl_up_sync(0xffffffffu, x, o);
        if (lane >= o) x += t;
    }
    __shared__ int wsum[8];
    if (lane == 31) wsum[w] = x;
    __syncthreads();
    if (w == 0) {
        int s = (lane < 8) ? wsum[lane] : 0;
#pragma unroll
        for (int o = 1; o < 8; o <<= 1) {
            int t = __shfl_up_sync(0xffffffffu, s, o);
            if (lane >= o) s += t;
        }
        if (lane < 8) wsum[lane] = s;
    }
    __syncthreads();
    int incl = x + ((w > 0) ? wsum[w - 1] : 0);
    if (i < N_NODES) g_rowptr[i + 1] = incl;
    if (threadIdx.x == 255) g_bsum[blockIdx.x] = incl;
}

__global__ void scan3_kernel() {
    __shared__ int s_off;
    int tid = threadIdx.x, lane = tid & 31;
    if (tid < 32) {
        int off = 0;
        for (int j = lane; j < blockIdx.x; j += 32) off += g_bsum[j];
#pragma unroll
        for (int o = 16; o > 0; o >>= 1)
            off += __shfl_xor_sync(0xffffffffu, off, o);
        if (lane == 0) s_off = off;
    }
    __syncthreads();
    int i = blockIdx.x * 256 + tid;
    if (i == 0) g_rowptr[0] = 0;
    if (i < N_NODES) {
        int incl = g_rowptr[i + 1] + s_off;
        g_rowptr[i + 1] = incl;
        g_cursor[i] = incl - (g_zero[i] + 1);
    }
}

__global__ void scatter_kernel(const int* __restrict__ ei) {
    int i = blockIdx.x * blockDim.x + threadIdx.x;
    if (i >= TOT_E) return;
    int src, dst;
    if (i < N_EDGES) { src = ei[i]; dst = ei[N_EDGES + i]; }
    else             { src = dst = i - N_EDGES; }
    int pos = atomicAdd(&g_cursor[dst], 1);
    g_csrc[pos] = src;
}

// ---------------------------------------------------------------------------
// bf16 GEMM, 3-stage cp.async pipeline (dynamic smem) + fused attention
// epilogue + PDL. Template NSUB: BN = 16*NSUB (NSUB=8 -> BN=128; 2 -> BN=32).
// ---------------------------------------------------------------------------
#define SROW 20
#define A_STAGE_U32 (128 * SROW)

__device__ __forceinline__ void cp16(uint32_t dst, const void* src, int bytes) {
    asm volatile("cp.async.cg.shared.global [%0], [%1], 16, %2;"
                 :: "r"(dst), "l"(src), "r"(bytes));
}
__device__ __forceinline__ void cp_commit() {
    asm volatile("cp.async.commit_group;");
}
template<int N>
__device__ __forceinline__ void cp_wait() {
    asm volatile("cp.async.wait_group %0;" :: "n"(N));
}

template<int NSUB>
__global__ void __launch_bounds__(256, 2)
gemm_att(const __nv_bfloat16* __restrict__ A, const __nv_bfloat16* __restrict__ B,
         __nv_bfloat16* __restrict__ C,
         const float* __restrict__ att_src, const float* __restrict__ att_dst,
         float* __restrict__ asrc, float* __restrict__ adst,
         int N, int M, int K, int H, int Cc, int prefetchB) {
    const int BN = NSUB * 16, BK = 32;
    const int B_STAGE_U32 = BN * SROW;
    extern __shared__ uint32_t dynsmem[];
    uint32_t* AsBase = dynsmem;
    uint32_t* BsBase = dynsmem + 3 * A_STAGE_U32;

    int tid  = threadIdx.x;
    int lane = tid & 31;
    int wid  = tid >> 5;
    int wr = (wid & 3) * 32;
    int wc = (wid >> 2) * (BN / 2);
    int gid = lane >> 2;
    int tig = lane & 3;

    int blockRow = blockIdx.y * 128;
    int blockCol = blockIdx.x * BN;

    int r0c = (tid + 0)   >> 2, q0 = (tid + 0)   & 3;
    int r1c = (tid + 256) >> 2, q1 = (tid + 256) & 3;

    uint32_t asm0 = (uint32_t)__cvta_generic_to_shared(AsBase);
    uint32_t bsm0 = (uint32_t)__cvta_generic_to_shared(BsBase);

    auto issueA = [&](int k0, int st) {
        uint32_t base = asm0 + st * (A_STAGE_U32 * 4);
        int ba0 = (blockRow + r0c < N) ? 16 : 0;
        int ba1 = (blockRow + r1c < N) ? 16 : 0;
        cp16(base + (r0c * SROW + q0 * 4) * 4,
             A + (size_t)(blockRow + r0c) * K + k0 + q0 * 8, ba0);
        cp16(base + (r1c * SROW + q1 * 4) * 4,
             A + (size_t)(blockRow + r1c) * K + k0 + q1 * 8, ba1);
    };
    auto issueB = [&](int k0, int st) {
        uint32_t base = bsm0 + st * (B_STAGE_U32 * 4);
        for (int c = tid; c < BN * 4; c += 256) {
            int row = c >> 2, q = c & 3;
            int bb = (blockCol + row < M) ? 16 : 0;
            cp16(base + (row * SROW + q * 4) * 4,
                 B + (size_t)(blockCol + row) * K + k0 + q * 8, bb);
        }
    };

    float acc[2][NSUB][4];
#pragma unroll
    for (int mt = 0; mt < 2; mt++)
#pragma unroll
        for (int nt = 0; nt < NSUB; nt++)
#pragma unroll
            for (int i = 0; i < 4; i++) acc[mt][nt][i] = 0.f;

    int nIt = K / BK;

    if (prefetchB) issueB(0, 0);
    cudaGridDependencySynchronize();
    issueA(0, 0);
    if (!prefetchB) issueB(0, 0);
    cp_commit();
    if (nIt > 1) {
        issueA(BK, 1);
        issueB(BK, 1);
        cp_commit();
    }

    for (int it = 0; it < nIt; it++) {
        int buf = it % 3;
        if (it + 2 < nIt) {
            issueA((it + 2) * BK, (it + 2) % 3);
            issueB((it + 2) * BK, (it + 2) % 3);
            cp_commit();
            cp_wait<2>();
        } else if (it + 1 < nIt) {
            cp_wait<1>();
        } else {
            cp_wait<0>();
        }
        __syncthreads();

        const uint32_t* As = AsBase + buf * A_STAGE_U32;
        const uint32_t* Bs = BsBase + buf * B_STAGE_U32;

#pragma unroll
        for (int ks = 0; ks < 2; ks++) {
            int kb = ks * 8;
            uint32_t a[2][4], b[NSUB][2];
#pragma unroll
            for (int mt = 0; mt < 2; mt++) {
                int r0 = wr + mt * 16;
                a[mt][0] = As[(r0 + gid    ) * SROW + kb + tig    ];
                a[mt][1] = As[(r0 + gid + 8) * SROW + kb + tig    ];
                a[mt][2] = As[(r0 + gid    ) * SROW + kb + tig + 4];
                a[mt][3] = As[(r0 + gid + 8) * SROW + kb + tig + 4];
            }
#pragma unroll
            for (int nt = 0; nt < NSUB; nt++) {
                int n0 = wc + nt * 8 + gid;
                b[nt][0] = Bs[n0 * SROW + kb + tig    ];
                b[nt][1] = Bs[n0 * SROW + kb + tig + 4];
            }
#pragma unroll
            for (int mt = 0; mt < 2; mt++)
#pragma unroll
                for (int nt = 0; nt < NSUB; nt++) {
                    asm volatile(
                        "mma.sync.aligned.m16n8k16.row.col.f32.bf16.bf16.f32 "
                        "{%0,%1,%2,%3}, {%4,%5,%6,%7}, {%8,%9}, {%0,%1,%2,%3};"
                        : "+f"(acc[mt][nt][0]), "+f"(acc[mt][nt][1]),
                          "+f"(acc[mt][nt][2]), "+f"(acc[mt][nt][3])
                        : "r"(a[mt][0]), "r"(a[mt][1]), "r"(a[mt][2]), "r"(a[mt][3]),
                          "r"(b[nt][0]), "r"(b[nt][1]));
                }
        }
        __syncthreads();
    }

    int h_first = (blockCol + wc) / Cc;
    float psrc[2][2][2] = {};
    float pdst[2][2][2] = {};

#pragma unroll
    for (int mt = 0; mt < 2; mt++) {
#pragma unroll
        for (int nt = 0; nt < NSUB; nt++) {
            int r0 = blockRow + wr + mt * 16 + gid;
            int c0 = blockCol + wc + nt * 8 + tig * 2;
            if (c0 < M) {
                if (r0 < N)
                    *(uint32_t*)(C + (size_t)r0 * M + c0) =
                        pack_bf16x2(acc[mt][nt][0], acc[mt][nt][1]);
                if (r0 + 8 < N)
                    *(uint32_t*)(C + (size_t)(r0 + 8) * M + c0) =
                        pack_bf16x2(acc[mt][nt][2], acc[mt][nt][3]);
                int hb = (blockCol + wc + nt * 8) / Cc - h_first;
                float a0 = att_src[c0], a1 = att_src[c0 + 1];
                float d0 = att_dst[c0], d1 = att_dst[c0 + 1];
                psrc[mt][0][hb] += acc[mt][nt][0] * a0 + acc[mt][nt][1] * a1;
                psrc[mt][1][hb] += acc[mt][nt][2] * a0 + acc[mt][nt][3] * a1;
                pdst[mt][0][hb] += acc[mt][nt][0] * d0 + acc[mt][nt][1] * d1;
                pdst[mt][1][hb] += acc[mt][nt][2] * d0 + acc[mt][nt][3] * d1;
            }
        }
    }
#pragma unroll
    for (int mt = 0; mt < 2; mt++)
#pragma unroll
        for (int hf = 0; hf < 2; hf++)
#pragma unroll
            for (int bk = 0; bk < 2; bk++) {
                float s = psrc[mt][hf][bk], d = pdst[mt][hf][bk];
                s += __shfl_xor_sync(0xffffffffu, s, 1);
                s += __shfl_xor_sync(0xffffffffu, s, 2);
                d += __shfl_xor_sync(0xffffffffu, d, 1);
                d += __shfl_xor_sync(0xffffffffu, d, 2);
                psrc[mt][hf][bk] = s; pdst[mt][hf][bk] = d;
            }
    if (tig == 0) {
#pragma unroll
        for (int mt = 0; mt < 2; mt++)
#pragma unroll
            for (int hf = 0; hf < 2; hf++) {
                int row = blockRow + wr + mt * 16 + gid + hf * 8;
                if (row >= N) continue;
#pragma unroll
                for (int bk = 0; bk < 2; bk++) {
                    int hidx = h_first + bk;
                    if (hidx < H) {
                        atomicAdd(&asrc[row * H + hidx], psrc[mt][hf][bk]);
                        atomicAdd(&adst[row * H + hidx], pdst[mt][hf][bk]);
                    }
                }
            }
    }
}

// ---------------------------------------------------------------------------
// GAT aggregation, H=5. 192 thr/node. Fast path (deg<=32): 5 softmax warps,
// lane = edge, register shuffle reduction, ONE sync. Fallback = R8 path.
// ---------------------------------------------------------------------------
template<int C>
__global__ void __launch_bounds__(192)
gat_agg5(const __nv_bfloat16* __restrict__ hfeat,
         const float* __restrict__ asrc,
         const float* __restrict__ adst,
         const float* __restrict__ bias,
         __nv_bfloat16* __restrict__ out) {
    const int HC = 5 * C, NC4 = HC / 4;
    const int EMAX = 128;
    __shared__ float s_e[EMAX * 5];
    __shared__ int   s_src[EMAX];
    __shared__ float s_m[5], s_iz[5];

    cudaGridDependencySynchronize();

    int v = blockIdx.x;
    int tid = threadIdx.x, lane = tid & 31, wid = tid >> 5;
    int base = g_rowptr[v];
    int deg = g_rowptr[v + 1] - base;

    float4 acc = make_float4(0.f, 0.f, 0.f, 0.f);
    int head = (tid * 4) / C;

    if (deg <= 32) {
        // single-phase softmax: warp h computes head h, lane = edge
        if (wid < 5) {
            int h = wid;
            float ad = adst[v * 5 + h];          // broadcast load
            int s = 0;
            float e = -INFINITY;
            if (lane < deg) {
                s = g_csrc[base + lane];
                if (h == 0) s_src[lane] = s;
                e = asrc[s * 5 + h] + ad;
                e = (e > 0.f) ? e : NEG_SLOPE * e;
            }
            float m = e;
#pragma unroll
            for (int o = 16; o > 0; o >>= 1)
                m = fmaxf(m, __shfl_xor_sync(0xffffffffu, m, o));
            float ex = (lane < deg) ? __expf(e - m) : 0.f;
            float z = ex;
#pragma unroll
            for (int o = 16; o > 0; o >>= 1)
                z += __shfl_xor_sync(0xffffffffu, z, o);
            if (lane < deg) s_e[lane * 5 + h] = ex / (z + EPS_F);
        }
        __syncthreads();
        if (tid < NC4) {
#pragma unroll 2
            for (int j = 0; j < deg; j++) {
                const uint2* hp = (const uint2*)(hfeat + (size_t)s_src[j] * HC);
                float w = s_e[j * 5 + head];
                uint2 hv = hp[tid];
                float2 lo = __bfloat1622float2(*(__nv_bfloat162*)&hv.x);
                float2 hi = __bfloat1622float2(*(__nv_bfloat162*)&hv.y);
                acc.x += w * lo.x; acc.y += w * lo.y;
                acc.z += w * hi.x; acc.w += w * hi.y;
            }
        }
    } else {
        // fallback: R8 3-phase with global reads + chunked gather
        if (wid < 5) {
            int h = wid;
            float ad = adst[v * 5 + h];
            float m = -INFINITY;
            for (int j = lane; j < deg; j += 32) {
                int s = g_csrc[base + j];
                float e = asrc[s * 5 + h] + ad;
                e = (e > 0.f) ? e : NEG_SLOPE * e;
                m = fmaxf(m, e);
            }
#pragma unroll
            for (int o = 16; o > 0; o >>= 1)
                m = fmaxf(m, __shfl_xor_sync(0xffffffffu, m, o));
            float z = 0.f;
            for (int j = lane; j < deg; j += 32) {
                int s = g_csrc[base + j];
                float e = asrc[s * 5 + h] + ad;
                e = (e > 0.f) ? e : NEG_SLOPE * e;
                z += __expf(e - m);
            }
#pragma unroll
            for (int o = 16; o > 0; o >>= 1)
                z += __shfl_xor_sync(0xffffffffu, z, o);
            if (lane == 0) { s_m[h] = m; s_iz[h] = 1.f / (z + EPS_F); }
        }
        __syncthreads();
        for (int j0 = 0; j0 < deg; j0 += EMAX) {
            int ch = min(EMAX, deg - j0);
            for (int idx = tid; idx < ch * 5; idx += 192) {
                int j = idx / 5, hh = idx - j * 5;
                int s = g_csrc[base + j0 + j];
                if (hh == 0) s_src[j] = s;
                float e = asrc[s * 5 + hh] + adst[v * 5 + hh];
                e = (e > 0.f) ? e : NEG_SLOPE * e;
                s_e[j * 5 + hh] = __expf(e - s_m[hh]) * s_iz[hh];
            }
            __syncthreads();
            if (tid < NC4) {
                for (int j = 0; j < ch; j++) {
                    const uint2* hp = (const uint2*)(hfeat + (size_t)s_src[j] * HC);
                    float w = s_e[j * 5 + head];
                    uint2 hv = hp[tid];
                    float2 lo = __bfloat1622float2(*(__nv_bfloat162*)&hv.x);
                    float2 hi = __bfloat1622float2(*(__nv_bfloat162*)&hv.y);
                    acc.x += w * lo.x; acc.y += w * lo.y;
                    acc.z += w * hi.x; acc.w += w * hi.y;
                }
            }
            __syncthreads();
        }
    }

    if (tid < NC4) {
        float4 b = ((const float4*)bias)[tid];
        uint2 o;
        o.x = pack_bf16x2(fmaxf(acc.x + b.x, 0.f), fmaxf(acc.y + b.y, 0.f));
        o.y = pack_bf16x2(fmaxf(acc.z + b.z, 0.f), fmaxf(acc.w + b.w, 0.f));
        ((uint2*)(out + (size_t)v * HC))[tid] = o;
    }
}

// ---------------------------------------------------------------------------
// GAT aggregation, H=1, C=32 + fused pool. warp per node.
// Fast path deg<=32: lane=edge softmax in registers, weights shuffled to
// the gather loop (no global reloads, no exp recompute).
// ---------------------------------------------------------------------------
__global__ void __launch_bounds__(256)
gat_agg1_pool(const __nv_bfloat16* __restrict__ hfeat,
              const float* __restrict__ asrc,
              const float* __restrict__ adst,
              const float* __restrict__ bias,
              const int* __restrict__ batch) {
    cudaGridDependencySynchronize();

    int wid = threadIdx.x >> 5, lane = threadIdx.x & 31;
    int v = blockIdx.x * 8 + wid;
    if (v >= N_NODES) return;
    int base = g_rowptr[v];
    int deg = g_rowptr[v + 1] - base;
    float ad = adst[v];
    float* pool = (float*)(g_zero + N_NODES);
    float acc = 0.f;

    if (deg <= 32) {
        int s_j = 0;
        float e = -INFINITY;
        if (lane < deg) {
            s_j = g_csrc[base + lane];
            e = asrc[s_j] + ad;
            e = (e > 0.f) ? e : NEG_SLOPE * e;
        }
        float m = e;
#pragma unroll
        for (int o = 16; o > 0; o >>= 1)
            m = fmaxf(m, __shfl_xor_sync(0xffffffffu, m, o));
        float ex = (lane < deg) ? __expf(e - m) : 0.f;
        float z = ex;
#pragma unroll
        for (int o = 16; o > 0; o >>= 1)
            z += __shfl_xor_sync(0xffffffffu, z, o);
        float wn = ex / (z + EPS_F);

        for (int j = 0; j < deg; j++) {
            float w = __shfl_sync(0xffffffffu, wn, j);
            int s  = __shfl_sync(0xffffffffu, s_j, j);
            acc += w * __bfloat162float(hfeat[(size_t)s * 32 + lane]);
        }
    } else {
        float m = -INFINITY;
        for (int j = lane; j < deg; j += 32) {
            int s = g_csrc[base + j];
            float e = asrc[s] + ad;
            e = (e > 0.f) ? e : NEG_SLOPE * e;
            m = fmaxf(m, e);
        }
#pragma unroll
        for (int o = 16; o > 0; o >>= 1)
            m = fmaxf(m, __shfl_xor_sync(0xffffffffu, m, o));
        float z = 0.f;
        for (int j = lane; j < deg; j += 32) {
            int s = g_csrc[base + j];
            float e = asrc[s] + ad;
            e = (e > 0.f) ? e : NEG_SLOPE * e;
            z += __expf(e - m);
        }
#pragma unroll
        for (int o = 16; o > 0; o >>= 1)
            z += __shfl_xor_sync(0xffffffffu, z, o);
        float iz = 1.f / (z + EPS_F);

#pragma unroll 2
        for (int j = 0; j < deg; j++) {
            int s = g_csrc[base + j];
            float e = asrc[s] + ad;
            e = (e > 0.f) ? e : NEG_SLOPE * e;
            float w = __expf(e - m) * iz;
            acc += w * __bfloat162float(hfeat[(size_t)s * 32 + lane]);
        }
    }

    float o = fmaxf(acc + bias[lane], 0.f);
    atomicAdd(&pool[batch[v] * 32 + lane], o);
}

// ---------------------------------------------------------------------------
// MLP head
// ---------------------------------------------------------------------------
__global__ void mlp_kernel(const float* __restrict__ lin_w,
                           const float* __restrict__ lin_b,
                           const float* __restrict__ lin2_w,
                           const float* __restrict__ lin2_b,
                           float* __restrict__ out) {
    cudaGridDependencySynchronize();

    int g = blockIdx.x;
    __shared__ float sg[32];
    __shared__ float sred[256];
    int tid = threadIdx.x;
    const float* pool = (const float*)(g_zero + N_NODES);
    if (tid < 32) sg[tid] = pool[g * 32 + tid];
    __syncthreads();
    float partial = 0.f;
    for (int u = tid; u < 1024; u += 256) {
        float d = lin_b[u];
        const float* wr = lin_w + u * 32;
#pragma unroll
        for (int c = 0; c < 32; c++) d += sg[c] * wr[c];
        d = fmaxf(d, 0.f);
        partial += d * lin2_w[u];
    }
    sred[tid] = partial;
    __syncthreads();
    for (int s = 128; s > 0; s >>= 1) {
        if (tid < s) sred[tid] += sred[tid + s];
        __syncthreads();
    }
    if (tid == 0) {
        float v = sred[0] + lin2_b[0];
        out[g] = 1.f / (1.f + __expf(-v));
    }
}

// ---------------------------------------------------------------------------
// PDL launch helper
// ---------------------------------------------------------------------------
template<typename Kern, typename... Args>
static inline void launch_pdl(Kern k, dim3 grid, dim3 block, size_t smem,
                              Args... args) {
    cudaLaunchConfig_t cfg = {};
    cfg.gridDim = grid;
    cfg.blockDim = block;
    cfg.dynamicSmemBytes = smem;
    cfg.stream = 0;
    cudaLaunchAttribute attr[1];
    attr[0].id = cudaLaunchAttributeProgrammaticStreamSerialization;
    attr[0].val.programmaticStreamSerializationAllowed = 1;
    cfg.attrs = attr;
    cfg.numAttrs = 1;
    cudaLaunchKernelEx(&cfg, k, args...);
}

#define GEMM_SMEM(NSUB) ((3 * A_STAGE_U32 + 3 * (NSUB) * 16 * SROW) * 4)

// ---------------------------------------------------------------------------
// launch
// ---------------------------------------------------------------------------
extern "C" void kernel_launch(void* const* d_in, const int* in_sizes, int n_in,
                              void* d_out, int out_size) {
    const float* x        = (const float*)d_in[0];
    const float* W1       = (const float*)d_in[1];
    const float* att_s1   = (const float*)d_in[2];
    const float* att_d1   = (const float*)d_in[3];
    const float* b1       = (const float*)d_in[4];
    const float* W2       = (const float*)d_in[5];
    const float* att_s2   = (const float*)d_in[6];
    const float* att_d2   = (const float*)d_in[7];
    const float* b2       = (const float*)d_in[8];
    const float* W3       = (const float*)d_in[9];
    const float* att_s3   = (const float*)d_in[10];
    const float* att_d3   = (const float*)d_in[11];
    const float* b3       = (const float*)d_in[12];
    const float* lin_w    = (const float*)d_in[13];
    const float* lin_b    = (const float*)d_in[14];
    const float* lin2_w   = (const float*)d_in[15];
    const float* lin2_b   = (const float*)d_in[16];
    const int*   ei       = (const int*)d_in[17];
    const int*   batch    = (const int*)d_in[18];
    float* out = (float*)d_out;

    __nv_bfloat16 *xq, *w1q, *w2q, *w3q, *h1, *o1, *h2, *o2, *h3;
    float *attbuf;
    int *zreg;
    cudaGetSymbolAddress((void**)&xq, g_xq);
    cudaGetSymbolAddress((void**)&w1q, g_w1q);
    cudaGetSymbolAddress((void**)&w2q, g_w2q);
    cudaGetSymbolAddress((void**)&w3q, g_w3q);
    cudaGetSymbolAddress((void**)&h1, g_h1);
    cudaGetSymbolAddress((void**)&o1, g_o1);
    cudaGetSymbolAddress((void**)&h2, g_h2);
    cudaGetSymbolAddress((void**)&o2, g_o2);
    cudaGetSymbolAddress((void**)&h3, g_h3);
    cudaGetSymbolAddress((void**)&attbuf, g_att);
    cudaGetSymbolAddress((void**)&zreg, g_zero);

    float* as1 = attbuf;                    float* ad1 = attbuf + N_NODES * 5;
    float* as2 = attbuf + 2 * N_NODES * 5;  float* ad2 = attbuf + 3 * N_NODES * 5;
    float* as3 = attbuf + 4 * N_NODES * 5;  float* ad3 = attbuf + 5 * N_NODES * 5;

    static cudaStream_t s_cs = nullptr;
    static cudaEvent_t ev_fork = nullptr, ev_join = nullptr;
    if (!s_cs) {
        cudaStreamCreateWithFlags(&s_cs, cudaStreamNonBlocking);
        cudaEventCreateWithFlags(&ev_fork, cudaEventDisableTiming);
        cudaEventCreateWithFlags(&ev_join, cudaEventDisableTiming);
        cudaFuncSetAttribute(gemm_att<8>,
                             cudaFuncAttributeMaxDynamicSharedMemorySize,
                             GEMM_SMEM(8));
        cudaFuncSetAttribute(gemm_att<2>,
                             cudaFuncAttributeMaxDynamicSharedMemorySize,
                             GEMM_SMEM(2));
    }

    // ---- fork: CSR build on side stream ----
    cudaEventRecord(ev_fork, 0);
    cudaStreamWaitEvent(s_cs, ev_fork, 0);
    cudaMemsetAsync(zreg, 0, (N_NODES + N_GRAPHS * 32) * sizeof(int), s_cs);
    count_kernel<<<(N_EDGES + 255) / 256, 256, 0, s_cs>>>(ei);
    scan1_kernel<<<N_BLK, 256, 0, s_cs>>>();
    scan3_kernel<<<N_BLK, 256, 0, s_cs>>>();
    scatter_kernel<<<(TOT_E + 255) / 256, 256, 0, s_cs>>>(ei);
    cudaEventRecord(ev_join, s_cs);

    // ---- main chain ----
    prep_kernel<<<(N_NODES * 64 / 4 + 255) / 256, 256>>>(x, W1, W2, W3);

    const int GY = (N_NODES + 127) / 128;

    launch_pdl(gemm_att<8>, dim3((HC1 + 127) / 128, GY), dim3(256), GEMM_SMEM(8),
               (const __nv_bfloat16*)xq, (const __nv_bfloat16*)w1q, h1,
               att_s1, att_d1, as1, ad1, N_NODES, HC1, 64, 5, 64, 0);

    // agg1: NORMAL launch (full dependency) — anchors prep + carries CSR join.
    cudaStreamWaitEvent(0, ev_join, 0);
    gat_agg5<64><<<N_NODES, 192>>>(h1, as1, ad1, b1, o1);

    launch_pdl(gemm_att<8>, dim3((HC2 + 127) / 128, GY), dim3(256), GEMM_SMEM(8),
               (const __nv_bfloat16*)o1, (const __nv_bfloat16*)w2q, h2,
               att_s2, att_d2, as2, ad2, N_NODES, HC2, HC1, 5, 96, 1);
    launch_pdl(gat_agg5<96>, dim3(N_NODES), dim3(192), (size_t)0,
               (const __nv_bfloat16*)h2,
               (const float*)as2, (const float*)ad2, b2, o2);

    launch_pdl(gemm_att<2>, dim3(1, GY), dim3(256), GEMM_SMEM(2),
               (const __nv_bfloat16*)o2, (const __nv_bfloat16*)w3q, h3,
               att_s3, att_d3, as3, ad3, N_NODES, HC3, HC2, 1, 32, 1);
    launch_pdl(gat_agg1_pool, dim3((N_NODES + 7) / 8), dim3(256), (size_t)0,
               (const __nv_bfloat16*)h3, (const float*)as3, (const float*)ad3,
               b3, batch);

    launch_pdl(mlp_kernel, dim3(N_GRAPHS), dim3(256), (size_t)0,
               lin_w, lin_b, lin2_w, lin2_b, out);
}

// round 13
// speedup vs baseline: 1.2094x; 1.0048x over previous
#include <cuda_runtime.h>
#include <cuda_bf16.h>
#include <math.h>
#include <stdint.h>

// ---------------------------------------------------------------------------
// Problem constants
// ---------------------------------------------------------------------------
#define N_NODES 20000
#define N_EDGES 320000
#define TOT_E   (N_EDGES + N_NODES)
#define N_GRAPHS 128
#define NEG_SLOPE 0.2f
#define EPS_F 1e-16f

#define HC1 320   // H=5, C=64
#define HC2 480   // H=5, C=96
#define HC3 32    // H=1, C=32

#define N_BLK ((N_NODES + 255) / 256)   // 79

// ---------------------------------------------------------------------------
// Device scratch. g_zero (cnt+pool) is SELF-CLEANING: statically zero-init,
// scan3 re-zeroes cnt after use, mlp re-zeroes pool after use.
// ---------------------------------------------------------------------------
__device__ __align__(16) __nv_bfloat16 g_xq[N_NODES * 64];
__device__ __align__(16) __nv_bfloat16 g_w1q[HC1 * 64];
__device__ __align__(16) __nv_bfloat16 g_w2q[HC2 * HC1];
__device__ __align__(16) __nv_bfloat16 g_w3q[HC3 * HC2];
__device__ __align__(16) __nv_bfloat16 g_h1[N_NODES * HC1];
__device__ __align__(16) __nv_bfloat16 g_o1[N_NODES * HC1];
__device__ __align__(16) __nv_bfloat16 g_h2[N_NODES * HC2];
__device__ __align__(16) __nv_bfloat16 g_o2[N_NODES * HC2];
__device__ __align__(16) __nv_bfloat16 g_h3[N_NODES * HC3];
__device__ float g_att[6 * N_NODES * 5];
__device__ int   g_zero[N_NODES + N_GRAPHS * 32];   // cnt | pool
__device__ int   g_rowptr[N_NODES + 1];
__device__ int   g_cursor[N_NODES];
__device__ int   g_csrc[TOT_E];
__device__ int   g_bsum[N_BLK];

__device__ __forceinline__ uint32_t pack_bf16x2(float lo, float hi) {
    __nv_bfloat162 h2 = __floats2bfloat162_rn(lo, hi);
    return *(uint32_t*)&h2;
}

// ---------------------------------------------------------------------------
// prep: x -> bf16, W1/2/3 -> bf16, zero att accumulators
// ---------------------------------------------------------------------------
#define W1Q4 (HC1 * 64 / 4)
#define W2Q4 (HC2 * HC1 / 4)
#define W3Q4 (HC3 * HC2 / 4)

__global__ void prep_kernel(const float* __restrict__ x,
                            const float* __restrict__ W1,
                            const float* __restrict__ W2,
                            const float* __restrict__ W3) {
    int i = blockIdx.x * 256 + threadIdx.x;
    if (i < N_NODES * 64 / 4) {
        float4 v = ((const float4*)x)[i];
        uint2 p;
        p.x = pack_bf16x2(v.x, v.y);
        p.y = pack_bf16x2(v.z, v.w);
        ((uint2*)g_xq)[i] = p;
    }
    if (2 * i < 6 * N_NODES * 5) {
        g_att[2 * i] = 0.f;
        if (2 * i + 1 < 6 * N_NODES * 5) g_att[2 * i + 1] = 0.f;
    }
    if (i < W1Q4 + W2Q4 + W3Q4) {
        const float4* src;
        uint2* dst;
        int j = i;
        if (j < W1Q4)                { src = (const float4*)W1; dst = (uint2*)g_w1q; }
        else if ((j -= W1Q4) < W2Q4) { src = (const float4*)W2; dst = (uint2*)g_w2q; }
        else { j -= W2Q4;              src = (const float4*)W3; dst = (uint2*)g_w3q; }
        float4 v = src[j];
        uint2 p;
        p.x = pack_bf16x2(v.x, v.y);
        p.y = pack_bf16x2(v.z, v.w);
        dst[j] = p;
    }
}

// ---------------------------------------------------------------------------
// CSR construction (cnt arrives zeroed — self-cleaning invariant)
// ---------------------------------------------------------------------------
__global__ void count_kernel(const int* __restrict__ ei) {
    int i = blockIdx.x * blockDim.x + threadIdx.x;
    if (i < N_EDGES) atomicAdd(&g_zero[ei[N_EDGES + i]], 1);
}

__global__ void scan1_kernel() {
    int i = blockIdx.x * 256 + threadIdx.x;
    int lane = threadIdx.x & 31, w = threadIdx.x >> 5;
    int x = (i < N_NODES) ? (g_zero[i] + 1) : 0;
#pragma unroll
    for (int o = 1; o < 32; o <<= 1) {
        int t = __shfl_up_sync(0xffffffffu, x, o);
        if (lane >= o) x += t;
    }
    __shared__ int wsum[8];
    if (lane == 31) wsum[w] = x;
    __syncthreads();
    if (w == 0) {
        int s = (lane < 8) ? wsum[lane] : 0;
#pragma unroll
        for (int o = 1; o < 8; o <<= 1) {
            int t = __shfl_up_sync(0xffffffffu, s, o);
            if (lane >= o) s += t;
        }
        if (lane < 8) wsum[lane] = s;
    }
    __syncthreads();
    int incl = x + ((w > 0) ? wsum[w - 1] : 0);
    if (i < N_NODES) g_rowptr[i + 1] = incl;
    if (threadIdx.x == 255) g_bsum[blockIdx.x] = incl;
}

// applies offsets, writes cursor, and RE-ZEROES cnt for the next call
__global__ void scan3_kernel() {
    __shared__ int s_off;
    int tid = threadIdx.x, lane = tid & 31;
    if (tid < 32) {
        int off = 0;
        for (int j = lane; j < blockIdx.x; j += 32) off += g_bsum[j];
#pragma unroll
        for (int o = 16; o > 0; o >>= 1)
            off += __shfl_xor_sync(0xffffffffu, off, o);
        if (lane == 0) s_off = off;
    }
    __syncthreads();
    int i = blockIdx.x * 256 + tid;
    if (i == 0) g_rowptr[0] = 0;
    if (i < N_NODES) {
        int incl = g_rowptr[i + 1] + s_off;
        g_rowptr[i + 1] = incl;
        g_cursor[i] = incl - (g_zero[i] + 1);
        g_zero[i] = 0;                       // self-clean for next launch
    }
}

__global__ void scatter_kernel(const int* __restrict__ ei) {
    int i = blockIdx.x * blockDim.x + threadIdx.x;
    if (i >= TOT_E) return;
    int src, dst;
    if (i < N_EDGES) { src = ei[i]; dst = ei[N_EDGES + i]; }
    else             { src = dst = i - N_EDGES; }
    int pos = atomicAdd(&g_cursor[dst], 1);
    g_csrc[pos] = src;
}

// ---------------------------------------------------------------------------
// bf16 GEMM, 3-stage cp.async pipeline + fused attention epilogue + PDL.
// ---------------------------------------------------------------------------
#define SROW 20
#define A_STAGE_U32 (128 * SROW)

__device__ __forceinline__ void cp16(uint32_t dst, const void* src, int bytes) {
    asm volatile("cp.async.cg.shared.global [%0], [%1], 16, %2;"
                 :: "r"(dst), "l"(src), "r"(bytes));
}
__device__ __forceinline__ void cp_commit() {
    asm volatile("cp.async.commit_group;");
}
template<int N>
__device__ __forceinline__ void cp_wait() {
    asm volatile("cp.async.wait_group %0;" :: "n"(N));
}

template<int NSUB>
__global__ void __launch_bounds__(256, 2)
gemm_att(const __nv_bfloat16* __restrict__ A, const __nv_bfloat16* __restrict__ B,
         __nv_bfloat16* __restrict__ C,
         const float* __restrict__ att_src, const float* __restrict__ att_dst,
         float* __restrict__ asrc, float* __restrict__ adst,
         int N, int M, int K, int H, int Cc, int prefetchB) {
    const int BN = NSUB * 16, BK = 32;
    const int B_STAGE_U32 = BN * SROW;
    extern __shared__ uint32_t dynsmem[];
    uint32_t* AsBase = dynsmem;
    uint32_t* BsBase = dynsmem + 3 * A_STAGE_U32;

    int tid  = threadIdx.x;
    int lane = tid & 31;
    int wid  = tid >> 5;
    int wr = (wid & 3) * 32;
    int wc = (wid >> 2) * (BN / 2);
    int gid = lane >> 2;
    int tig = lane & 3;

    int blockRow = blockIdx.y * 128;
    int blockCol = blockIdx.x * BN;

    int r0c = (tid + 0)   >> 2, q0 = (tid + 0)   & 3;
    int r1c = (tid + 256) >> 2, q1 = (tid + 256) & 3;

    uint32_t asm0 = (uint32_t)__cvta_generic_to_shared(AsBase);
    uint32_t bsm0 = (uint32_t)__cvta_generic_to_shared(BsBase);

    auto issueA = [&](int k0, int st) {
        uint32_t base = asm0 + st * (A_STAGE_U32 * 4);
        int ba0 = (blockRow + r0c < N) ? 16 : 0;
        int ba1 = (blockRow + r1c < N) ? 16 : 0;
        cp16(base + (r0c * SROW + q0 * 4) * 4,
             A + (size_t)(blockRow + r0c) * K + k0 + q0 * 8, ba0);
        cp16(base + (r1c * SROW + q1 * 4) * 4,
             A + (size_t)(blockRow + r1c) * K + k0 + q1 * 8, ba1);
    };
    auto issueB = [&](int k0, int st) {
        uint32_t base = bsm0 + st * (B_STAGE_U32 * 4);
        for (int c = tid; c < BN * 4; c += 256) {
            int row = c >> 2, q = c & 3;
            int bb = (blockCol + row < M) ? 16 : 0;
            cp16(base + (row * SROW + q * 4) * 4,
                 B + (size_t)(blockCol + row) * K + k0 + q * 8, bb);
        }
    };

    float acc[2][NSUB][4];
#pragma unroll
    for (int mt = 0; mt < 2; mt++)
#pragma unroll
        for (int nt = 0; nt < NSUB; nt++)
#pragma unroll
            for (int i = 0; i < 4; i++) acc[mt][nt][i] = 0.f;

    int nIt = K / BK;

    if (prefetchB) issueB(0, 0);
    cudaGridDependencySynchronize();
    issueA(0, 0);
    if (!prefetchB) issueB(0, 0);
    cp_commit();
    if (nIt > 1) {
        issueA(BK, 1);
        issueB(BK, 1);
        cp_commit();
    }

    for (int it = 0; it < nIt; it++) {
        int buf = it % 3;
        if (it + 2 < nIt) {
            issueA((it + 2) * BK, (it + 2) % 3);
            issueB((it + 2) * BK, (it + 2) % 3);
            cp_commit();
            cp_wait<2>();
        } else if (it + 1 < nIt) {
            cp_wait<1>();
        } else {
            cp_wait<0>();
        }
        __syncthreads();

        const uint32_t* As = AsBase + buf * A_STAGE_U32;
        const uint32_t* Bs = BsBase + buf * B_STAGE_U32;

#pragma unroll
        for (int ks = 0; ks < 2; ks++) {
            int kb = ks * 8;
            uint32_t a[2][4], b[NSUB][2];
#pragma unroll
            for (int mt = 0; mt < 2; mt++) {
                int r0 = wr + mt * 16;
                a[mt][0] = As[(r0 + gid    ) * SROW + kb + tig    ];
                a[mt][1] = As[(r0 + gid + 8) * SROW + kb + tig    ];
                a[mt][2] = As[(r0 + gid    ) * SROW + kb + tig + 4];
                a[mt][3] = As[(r0 + gid + 8) * SROW + kb + tig + 4];
            }
#pragma unroll
            for (int nt = 0; nt < NSUB; nt++) {
                int n0 = wc + nt * 8 + gid;
                b[nt][0] = Bs[n0 * SROW + kb + tig    ];
                b[nt][1] = Bs[n0 * SROW + kb + tig + 4];
            }
#pragma unroll
            for (int mt = 0; mt < 2; mt++)
#pragma unroll
                for (int nt = 0; nt < NSUB; nt++) {
                    asm volatile(
                        "mma.sync.aligned.m16n8k16.row.col.f32.bf16.bf16.f32 "
                        "{%0,%1,%2,%3}, {%4,%5,%6,%7}, {%8,%9}, {%0,%1,%2,%3};"
                        : "+f"(acc[mt][nt][0]), "+f"(acc[mt][nt][1]),
                          "+f"(acc[mt][nt][2]), "+f"(acc[mt][nt][3])
                        : "r"(a[mt][0]), "r"(a[mt][1]), "r"(a[mt][2]), "r"(a[mt][3]),
                          "r"(b[nt][0]), "r"(b[nt][1]));
                }
        }
        __syncthreads();
    }

    int h_first = (blockCol + wc) / Cc;
    float psrc[2][2][2] = {};
    float pdst[2][2][2] = {};

#pragma unroll
    for (int mt = 0; mt < 2; mt++) {
#pragma unroll
        for (int nt = 0; nt < NSUB; nt++) {
            int r0 = blockRow + wr + mt * 16 + gid;
            int c0 = blockCol + wc + nt * 8 + tig * 2;
            if (c0 < M) {
                if (r0 < N)
                    *(uint32_t*)(C + (size_t)r0 * M + c0) =
                        pack_bf16x2(acc[mt][nt][0], acc[mt][nt][1]);
                if (r0 + 8 < N)
                    *(uint32_t*)(C + (size_t)(r0 + 8) * M + c0) =
                        pack_bf16x2(acc[mt][nt][2], acc[mt][nt][3]);
                int hb = (blockCol + wc + nt * 8) / Cc - h_first;
                float a0 = att_src[c0], a1 = att_src[c0 + 1];
                float d0 = att_dst[c0], d1 = att_dst[c0 + 1];
                psrc[mt][0][hb] += acc[mt][nt][0] * a0 + acc[mt][nt][1] * a1;
                psrc[mt][1][hb] += acc[mt][nt][2] * a0 + acc[mt][nt][3] * a1;
                pdst[mt][0][hb] += acc[mt][nt][0] * d0 + acc[mt][nt][1] * d1;
                pdst[mt][1][hb] += acc[mt][nt][2] * d0 + acc[mt][nt][3] * d1;
            }
        }
    }
#pragma unroll
    for (int mt = 0; mt < 2; mt++)
#pragma unroll
        for (int hf = 0; hf < 2; hf++)
#pragma unroll
            for (int bk = 0; bk < 2; bk++) {
                float s = psrc[mt][hf][bk], d = pdst[mt][hf][bk];
                s += __shfl_xor_sync(0xffffffffu, s, 1);
                s += __shfl_xor_sync(0xffffffffu, s, 2);
                d += __shfl_xor_sync(0xffffffffu, d, 1);
                d += __shfl_xor_sync(0xffffffffu, d, 2);
                psrc[mt][hf][bk] = s; pdst[mt][hf][bk] = d;
            }
    if (tig == 0) {
#pragma unroll
        for (int mt = 0; mt < 2; mt++)
#pragma unroll
            for (int hf = 0; hf < 2; hf++) {
                int row = blockRow + wr + mt * 16 + gid + hf * 8;
                if (row >= N) continue;
#pragma unroll
                for (int bk = 0; bk < 2; bk++) {
                    int hidx = h_first + bk;
                    if (hidx < H) {
                        atomicAdd(&asrc[row * H + hidx], psrc[mt][hf][bk]);
                        atomicAdd(&adst[row * H + hidx], pdst[mt][hf][bk]);
                    }
                }
            }
    }
}

// ---------------------------------------------------------------------------
// GAT aggregation, H=5. Block = round32(NC4) threads (96 for C=64, 128 for
// C=96). Warp 0 computes ALL 5 heads' softmax (scores contiguous per edge).
// ---------------------------------------------------------------------------
template<int C>
__global__ void __launch_bounds__(128)
gat_agg5(const __nv_bfloat16* __restrict__ hfeat,
         const float* __restrict__ asrc,
         const float* __restrict__ adst,
         const float* __restrict__ bias,
         __nv_bfloat16* __restrict__ out) {
    const int HC = 5 * C, NC4 = HC / 4;
    const int EMAX = 128;
    __shared__ float s_e[EMAX * 5];
    __shared__ int   s_src[EMAX];
    __shared__ float s_m[5], s_iz[5];

    cudaGridDependencySynchronize();

    int v = blockIdx.x;
    int tid = threadIdx.x, lane = tid & 31, wid = tid >> 5;
    int base = g_rowptr[v];
    int deg = g_rowptr[v + 1] - base;

    float4 acc = make_float4(0.f, 0.f, 0.f, 0.f);
    int head = (tid * 4) / C;

    if (deg <= 32) {
        // warp 0: lane = edge, all 5 heads
        if (wid == 0) {
            int s = 0;
            float e[5];
            if (lane < deg) {
                s = g_csrc[base + lane];
                s_src[lane] = s;
#pragma unroll
                for (int h = 0; h < 5; h++) {
                    float t = asrc[s * 5 + h] + adst[v * 5 + h];
                    e[h] = (t > 0.f) ? t : NEG_SLOPE * t;
                }
            } else {
#pragma unroll
                for (int h = 0; h < 5; h++) e[h] = -INFINITY;
            }
#pragma unroll
            for (int h = 0; h < 5; h++) {
                float m = e[h];
#pragma unroll
                for (int o = 16; o > 0; o >>= 1)
                    m = fmaxf(m, __shfl_xor_sync(0xffffffffu, m, o));
                float ex = (lane < deg) ? __expf(e[h] - m) : 0.f;
                float z = ex;
#pragma unroll
                for (int o = 16; o > 0; o >>= 1)
                    z += __shfl_xor_sync(0xffffffffu, z, o);
                if (lane < deg) s_e[lane * 5 + h] = ex / (z + EPS_F);
            }
        }
        __syncthreads();
        if (tid < NC4) {
#pragma unroll 2
            for (int j = 0; j < deg; j++) {
                const uint2* hp = (const uint2*)(hfeat + (size_t)s_src[j] * HC);
                float w = s_e[j * 5 + head];
                uint2 hv = hp[tid];
                float2 lo = __bfloat1622float2(*(__nv_bfloat162*)&hv.x);
                float2 hi = __bfloat1622float2(*(__nv_bfloat162*)&hv.y);
                acc.x += w * lo.x; acc.y += w * lo.y;
                acc.z += w * hi.x; acc.w += w * hi.y;
            }
        }
    } else {
        // fallback (rare): warp 0 computes m/z per head, strided over edges
        if (wid == 0) {
#pragma unroll
            for (int h = 0; h < 5; h++) {
                float ad = adst[v * 5 + h];
                float m = -INFINITY;
                for (int j = lane; j < deg; j += 32) {
                    int s = g_csrc[base + j];
                    float e = asrc[s * 5 + h] + ad;
                    e = (e > 0.f) ? e : NEG_SLOPE * e;
                    m = fmaxf(m, e);
                }
#pragma unroll
                for (int o = 16; o > 0; o >>= 1)
                    m = fmaxf(m, __shfl_xor_sync(0xffffffffu, m, o));
                float z = 0.f;
                for (int j = lane; j < deg; j += 32) {
                    int s = g_csrc[base + j];
                    float e = asrc[s * 5 + h] + ad;
                    e = (e > 0.f) ? e : NEG_SLOPE * e;
                    z += __expf(e - m);
                }
#pragma unroll
                for (int o = 16; o > 0; o >>= 1)
                    z += __shfl_xor_sync(0xffffffffu, z, o);
                if (lane == 0) { s_m[h] = m; s_iz[h] = 1.f / (z + EPS_F); }
            }
        }
        __syncthreads();
        for (int j0 = 0; j0 < deg; j0 += EMAX) {
            int ch = min(EMAX, deg - j0);
            for (int idx = tid; idx < ch * 5; idx += blockDim.x) {
                int j = idx / 5, hh = idx - j * 5;
                int s = g_csrc[base + j0 + j];
                if (hh == 0) s_src[j] = s;
                float e = asrc[s * 5 + hh] + adst[v * 5 + hh];
                e = (e > 0.f) ? e : NEG_SLOPE * e;
                s_e[j * 5 + hh] = __expf(e - s_m[hh]) * s_iz[hh];
            }
            __syncthreads();
            if (tid < NC4) {
                for (int j = 0; j < ch; j++) {
                    const uint2* hp = (const uint2*)(hfeat + (size_t)s_src[j] * HC);
                    float w = s_e[j * 5 + head];
                    uint2 hv = hp[tid];
                    float2 lo = __bfloat1622float2(*(__nv_bfloat162*)&hv.x);
                    float2 hi = __bfloat1622float2(*(__nv_bfloat162*)&hv.y);
                    acc.x += w * lo.x; acc.y += w * lo.y;
                    acc.z += w * hi.x; acc.w += w * hi.y;
                }
            }
            __syncthreads();
        }
    }

    if (tid < NC4) {
        float4 b = ((const float4*)bias)[tid];
        uint2 o;
        o.x = pack_bf16x2(fmaxf(acc.x + b.x, 0.f), fmaxf(acc.y + b.y, 0.f));
        o.y = pack_bf16x2(fmaxf(acc.z + b.z, 0.f), fmaxf(acc.w + b.w, 0.f));
        ((uint2*)(out + (size_t)v * HC))[tid] = o;
    }
}

// ---------------------------------------------------------------------------
// GAT aggregation, H=1, C=32 + fused pool. warp per node.
// ---------------------------------------------------------------------------
__global__ void __launch_bounds__(256)
gat_agg1_pool(const __nv_bfloat16* __restrict__ hfeat,
              const float* __restrict__ asrc,
              const float* __restrict__ adst,
              const float* __restrict__ bias,
              const int* __restrict__ batch) {
    cudaGridDependencySynchronize();

    int wid = threadIdx.x >> 5, lane = threadIdx.x & 31;
    int v = blockIdx.x * 8 + wid;
    if (v >= N_NODES) return;
    int base = g_rowptr[v];
    int deg = g_rowptr[v + 1] - base;
    float ad = adst[v];
    float* pool = (float*)(g_zero + N_NODES);
    float acc = 0.f;

    if (deg <= 32) {
        int s_j = 0;
        float e = -INFINITY;
        if (lane < deg) {
            s_j = g_csrc[base + lane];
            e = asrc[s_j] + ad;
            e = (e > 0.f) ? e : NEG_SLOPE * e;
        }
        float m = e;
#pragma unroll
        for (int o = 16; o > 0; o >>= 1)
            m = fmaxf(m, __shfl_xor_sync(0xffffffffu, m, o));
        float ex = (lane < deg) ? __expf(e - m) : 0.f;
        float z = ex;
#pragma unroll
        for (int o = 16; o > 0; o >>= 1)
            z += __shfl_xor_sync(0xffffffffu, z, o);
        float wn = ex / (z + EPS_F);

        for (int j = 0; j < deg; j++) {
            float w = __shfl_sync(0xffffffffu, wn, j);
            int s  = __shfl_sync(0xffffffffu, s_j, j);
            acc += w * __bfloat162float(hfeat[(size_t)s * 32 + lane]);
        }
    } else {
        float m = -INFINITY;
        for (int j = lane; j < deg; j += 32) {
            int s = g_csrc[base + j];
            float e = asrc[s] + ad;
            e = (e > 0.f) ? e : NEG_SLOPE * e;
            m = fmaxf(m, e);
        }
#pragma unroll
        for (int o = 16; o > 0; o >>= 1)
            m = fmaxf(m, __shfl_xor_sync(0xffffffffu, m, o));
        float z = 0.f;
        for (int j = lane; j < deg; j += 32) {
            int s = g_csrc[base + j];
            float e = asrc[s] + ad;
            e = (e > 0.f) ? e : NEG_SLOPE * e;
            z += __expf(e - m);
        }
#pragma unroll
        for (int o = 16; o > 0; o >>= 1)
            z += __shfl_xor_sync(0xffffffffu, z, o);
        float iz = 1.f / (z + EPS_F);

#pragma unroll 2
        for (int j = 0; j < deg; j++) {
            int s = g_csrc[base + j];
            float e = asrc[s] + ad;
            e = (e > 0.f) ? e : NEG_SLOPE * e;
            float w = __expf(e - m) * iz;
            acc += w * __bfloat162float(hfeat[(size_t)s * 32 + lane]);
        }
    }

    float o = fmaxf(acc + bias[lane], 0.f);
    atomicAdd(&pool[batch[v] * 32 + lane], o);
}

// ---------------------------------------------------------------------------
// MLP head (re-zeroes pool after reading — self-cleaning invariant)
// ---------------------------------------------------------------------------
__global__ void mlp_kernel(const float* __restrict__ lin_w,
                           const float* __restrict__ lin_b,
                           const float* __restrict__ lin2_w,
                           const float* __restrict__ lin2_b,
                           float* __restrict__ out) {
    cudaGridDependencySynchronize();

    int g = blockIdx.x;
    __shared__ float sg[32];
    __shared__ float sred[256];
    int tid = threadIdx.x;
    float* pool = (float*)(g_zero + N_NODES);
    if (tid < 32) {
        sg[tid] = pool[g * 32 + tid];
        pool[g * 32 + tid] = 0.f;            // self-clean for next launch
    }
    __syncthreads();
    float partial = 0.f;
    for (int u = tid; u < 1024; u += 256) {
        float d = lin_b[u];
        const float* wr = lin_w + u * 32;
#pragma unroll
        for (int c = 0; c < 32; c++) d += sg[c] * wr[c];
        d = fmaxf(d, 0.f);
        partial += d * lin2_w[u];
    }
    sred[tid] = partial;
    __syncthreads();
    for (int s = 128; s > 0; s >>= 1) {
        if (tid < s) sred[tid] += sred[tid + s];
        __syncthreads();
    }
    if (tid == 0) {
        float v = sred[0] + lin2_b[0];
        out[g] = 1.f / (1.f + __expf(-v));
    }
}

// ---------------------------------------------------------------------------
// PDL launch helper
// ---------------------------------------------------------------------------
template<typename Kern, typename... Args>
static inline void launch_pdl(Kern k, dim3 grid, dim3 block, size_t smem,
                              Args... args) {
    cudaLaunchConfig_t cfg = {};
    cfg.gridDim = grid;
    cfg.blockDim = block;
    cfg.dynamicSmemBytes = smem;
    cfg.stream = 0;
    cudaLaunchAttribute attr[1];
    attr[0].id = cudaLaunchAttributeProgrammaticStreamSerialization;
    attr[0].val.programmaticStreamSerializationAllowed = 1;
    cfg.attrs = attr;
    cfg.numAttrs = 1;
    cudaLaunchKernelEx(&cfg, k, args...);
}

#define GEMM_SMEM(NSUB) ((3 * A_STAGE_U32 + 3 * (NSUB) * 16 * SROW) * 4)

// ---------------------------------------------------------------------------
// launch
// ---------------------------------------------------------------------------
extern "C" void kernel_launch(void* const* d_in, const int* in_sizes, int n_in,
                              void* d_out, int out_size) {
    const float* x        = (const float*)d_in[0];
    const float* W1       = (const float*)d_in[1];
    const float* att_s1   = (const float*)d_in[2];
    const float* att_d1   = (const float*)d_in[3];
    const float* b1       = (const float*)d_in[4];
    const float* W2       = (const float*)d_in[5];
    const float* att_s2   = (const float*)d_in[6];
    const float* att_d2   = (const float*)d_in[7];
    const float* b2       = (const float*)d_in[8];
    const float* W3       = (const float*)d_in[9];
    const float* att_s3   = (const float*)d_in[10];
    const float* att_d3   = (const float*)d_in[11];
    const float* b3       = (const float*)d_in[12];
    const float* lin_w    = (const float*)d_in[13];
    const float* lin_b    = (const float*)d_in[14];
    const float* lin2_w   = (const float*)d_in[15];
    const float* lin2_b   = (const float*)d_in[16];
    const int*   ei       = (const int*)d_in[17];
    const int*   batch    = (const int*)d_in[18];
    float* out = (float*)d_out;

    __nv_bfloat16 *xq, *w1q, *w2q, *w3q, *h1, *o1, *h2, *o2, *h3;
    float *attbuf;
    cudaGetSymbolAddress((void**)&xq, g_xq);
    cudaGetSymbolAddress((void**)&w1q, g_w1q);
    cudaGetSymbolAddress((void**)&w2q, g_w2q);
    cudaGetSymbolAddress((void**)&w3q, g_w3q);
    cudaGetSymbolAddress((void**)&h1, g_h1);
    cudaGetSymbolAddress((void**)&o1, g_o1);
    cudaGetSymbolAddress((void**)&h2, g_h2);
    cudaGetSymbolAddress((void**)&o2, g_o2);
    cudaGetSymbolAddress((void**)&h3, g_h3);
    cudaGetSymbolAddress((void**)&attbuf, g_att);

    float* as1 = attbuf;                    float* ad1 = attbuf + N_NODES * 5;
    float* as2 = attbuf + 2 * N_NODES * 5;  float* ad2 = attbuf + 3 * N_NODES * 5;
    float* as3 = attbuf + 4 * N_NODES * 5;  float* ad3 = attbuf + 5 * N_NODES * 5;

    static cudaStream_t s_cs = nullptr;
    static cudaEvent_t ev_fork = nullptr, ev_join = nullptr;
    if (!s_cs) {
        cudaStreamCreateWithFlags(&s_cs, cudaStreamNonBlocking);
        cudaEventCreateWithFlags(&ev_fork, cudaEventDisableTiming);
        cudaEventCreateWithFlags(&ev_join, cudaEventDisableTiming);
        cudaFuncSetAttribute(gemm_att<8>,
                             cudaFuncAttributeMaxDynamicSharedMemorySize,
                             GEMM_SMEM(8));
        cudaFuncSetAttribute(gemm_att<2>,
                             cudaFuncAttributeMaxDynamicSharedMemorySize,
                             GEMM_SMEM(2));
    }

    // ---- fork: CSR build on side stream (no memset — self-cleaning cnt) ----
    cudaEventRecord(ev_fork, 0);
    cudaStreamWaitEvent(s_cs, ev_fork, 0);
    count_kernel<<<(N_EDGES + 255) / 256, 256, 0, s_cs>>>(ei);
    scan1_kernel<<<N_BLK, 256, 0, s_cs>>>();
    scan3_kernel<<<N_BLK, 256, 0, s_cs>>>();
    scatter_kernel<<<(TOT_E + 255) / 256, 256, 0, s_cs>>>(ei);
    cudaEventRecord(ev_join, s_cs);

    // ---- main chain ----
    prep_kernel<<<(N_NODES * 64 / 4 + 255) / 256, 256>>>(x, W1, W2, W3);

    const int GY = (N_NODES + 127) / 128;

    launch_pdl(gemm_att<8>, dim3((HC1 + 127) / 128, GY), dim3(256), GEMM_SMEM(8),
               (const __nv_bfloat16*)xq, (const __nv_bfloat16*)w1q, h1,
               att_s1, att_d1, as1, ad1, N_NODES, HC1, 64, 5, 64, 0);

    // agg1: NORMAL launch (full dependency) — anchors prep + carries CSR join.
    cudaStreamWaitEvent(0, ev_join, 0);
    gat_agg5<64><<<N_NODES, 96>>>(h1, as1, ad1, b1, o1);

    launch_pdl(gemm_att<8>, dim3((HC2 + 127) / 128, GY), dim3(256), GEMM_SMEM(8),
               (const __nv_bfloat16*)o1, (const __nv_bfloat16*)w2q, h2,
               att_s2, att_d2, as2, ad2, N_NODES, HC2, HC1, 5, 96, 1);
    launch_pdl(gat_agg5<96>, dim3(N_NODES), dim3(128), (size_t)0,
               (const __nv_bfloat16*)h2,
               (const float*)as2, (const float*)ad2, b2, o2);

    launch_pdl(gemm_att<2>, dim3(1, GY), dim3(256), GEMM_SMEM(2),
               (const __nv_bfloat16*)o2, (const __nv_bfloat16*)w3q, h3,
               att_s3, att_d3, as3, ad3, N_NODES, HC3, HC2, 1, 32, 1);
    launch_pdl(gat_agg1_pool, dim3((N_NODES + 7) / 8), dim3(256), (size_t)0,
               (const __nv_bfloat16*)h3, (const float*)as3, (const float*)ad3,
               b3, batch);

    launch_pdl(mlp_kernel, dim3(N_GRAPHS), dim3(256), (size_t)0,
               lin_w, lin_b, lin2_w, lin2_b, out);
}

// round 15
// speedup vs baseline: 1.2241x; 1.0122x over previous
#include <cuda_runtime.h>
#include <cuda_bf16.h>
#include <math.h>
#include <stdint.h>

// ---------------------------------------------------------------------------
// Problem constants
// ---------------------------------------------------------------------------
#define N_NODES 20000
#define N_EDGES 320000
#define TOT_E   (N_EDGES + N_NODES)
#define N_GRAPHS 128
#define NEG_SLOPE 0.2f
#define EPS_F 1e-16f

#define HC1 320   // H=5, C=64
#define HC2 480   // H=5, C=96
#define HC3 32    // H=1, C=32

#define N_BLK ((N_NODES + 255) / 256)   // 79

// ---------------------------------------------------------------------------
// Device scratch. g_zero (cnt+pool) is SELF-CLEANING.
// ---------------------------------------------------------------------------
__device__ __align__(16) __nv_bfloat16 g_xq[N_NODES * 64];
__device__ __align__(16) __nv_bfloat16 g_w1q[HC1 * 64];
__device__ __align__(16) __nv_bfloat16 g_w2q[HC2 * HC1];
__device__ __align__(16) __nv_bfloat16 g_w3q[HC3 * HC2];
__device__ __align__(16) __nv_bfloat16 g_h1[N_NODES * HC1];
__device__ __align__(16) __nv_bfloat16 g_o1[N_NODES * HC1];
__device__ __align__(16) __nv_bfloat16 g_h2[N_NODES * HC2];
__device__ __align__(16) __nv_bfloat16 g_o2[N_NODES * HC2];
__device__ __align__(16) __nv_bfloat16 g_h3[N_NODES * HC3];
__device__ float g_att[6 * N_NODES * 5];
__device__ int   g_zero[N_NODES + N_GRAPHS * 32];   // cnt | pool
__device__ int   g_rowptr[N_NODES + 1];
__device__ int   g_cursor[N_NODES];
__device__ int   g_csrc[TOT_E];
__device__ int   g_bsum[N_BLK];

__device__ __forceinline__ uint32_t pack_bf16x2(float lo, float hi) {
    __nv_bfloat162 h2 = __floats2bfloat162_rn(lo, hi);
    return *(uint32_t*)&h2;
}

// ---------------------------------------------------------------------------
// prep
// ---------------------------------------------------------------------------
#define W1Q4 (HC1 * 64 / 4)
#define W2Q4 (HC2 * HC1 / 4)
#define W3Q4 (HC3 * HC2 / 4)

__global__ void prep_kernel(const float* __restrict__ x,
                            const float* __restrict__ W1,
                            const float* __restrict__ W2,
                            const float* __restrict__ W3) {
    int i = blockIdx.x * 256 + threadIdx.x;
    if (i < N_NODES * 64 / 4) {
        float4 v = ((const float4*)x)[i];
        uint2 p;
        p.x = pack_bf16x2(v.x, v.y);
        p.y = pack_bf16x2(v.z, v.w);
        ((uint2*)g_xq)[i] = p;
    }
    if (2 * i < 6 * N_NODES * 5) {
        g_att[2 * i] = 0.f;
        if (2 * i + 1 < 6 * N_NODES * 5) g_att[2 * i + 1] = 0.f;
    }
    if (i < W1Q4 + W2Q4 + W3Q4) {
        const float4* src;
        uint2* dst;
        int j = i;
        if (j < W1Q4)                { src = (const float4*)W1; dst = (uint2*)g_w1q; }
        else if ((j -= W1Q4) < W2Q4) { src = (const float4*)W2; dst = (uint2*)g_w2q; }
        else { j -= W2Q4;              src = (const float4*)W3; dst = (uint2*)g_w3q; }
        float4 v = src[j];
        uint2 p;
        p.x = pack_bf16x2(v.x, v.y);
        p.y = pack_bf16x2(v.z, v.w);
        dst[j] = p;
    }
}

// ---------------------------------------------------------------------------
// CSR construction (2 edges per thread for atomic MLP=2)
// ---------------------------------------------------------------------------
__global__ void count_kernel(const int* __restrict__ ei) {
    int i = blockIdx.x * blockDim.x + threadIdx.x;
    if (i < N_EDGES / 2) {
        int2 d = ((const int2*)(ei + N_EDGES))[i];
        atomicAdd(&g_zero[d.x], 1);
        atomicAdd(&g_zero[d.y], 1);
    }
}

__global__ void scan1_kernel() {
    int i = blockIdx.x * 256 + threadIdx.x;
    int lane = threadIdx.x & 31, w = threadIdx.x >> 5;
    int x = (i < N_NODES) ? (g_zero[i] + 1) : 0;
#pragma unroll
    for (int o = 1; o < 32; o <<= 1) {
        int t = __shfl_up_sync(0xffffffffu, x, o);
        if (lane >= o) x += t;
    }
    __shared__ int wsum[8];
    if (lane == 31) wsum[w] = x;
    __syncthreads();
    if (w == 0) {
        int s = (lane < 8) ? wsum[lane] : 0;
#pragma unroll
        for (int o = 1; o < 8; o <<= 1) {
            int t = __shfl_up_sync(0xffffffffu, s, o);
            if (lane >= o) s += t;
        }
        if (lane < 8) wsum[lane] = s;
    }
    __syncthreads();
    int incl = x + ((w > 0) ? wsum[w - 1] : 0);
    if (i < N_NODES) g_rowptr[i + 1] = incl;
    if (threadIdx.x == 255) g_bsum[blockIdx.x] = incl;
}

__global__ void scan3_kernel() {
    __shared__ int s_off;
    int tid = threadIdx.x, lane = tid & 31;
    if (tid < 32) {
        int off = 0;
        for (int j = lane; j < blockIdx.x; j += 32) off += g_bsum[j];
#pragma unroll
        for (int o = 16; o > 0; o >>= 1)
            off += __shfl_xor_sync(0xffffffffu, off, o);
        if (lane == 0) s_off = off;
    }
    __syncthreads();
    int i = blockIdx.x * 256 + tid;
    if (i == 0) g_rowptr[0] = 0;
    if (i < N_NODES) {
        int incl = g_rowptr[i + 1] + s_off;
        g_rowptr[i + 1] = incl;
        g_cursor[i] = incl - (g_zero[i] + 1);
        g_zero[i] = 0;                       // self-clean
    }
}

// 2 edges per thread; self loops appended
__global__ void scatter_kernel(const int* __restrict__ ei) {
    int i = blockIdx.x * blockDim.x + threadIdx.x;
    const int HALF = N_EDGES / 2;
    if (i < HALF) {
        int2 s = ((const int2*)ei)[i];
        int2 d = ((const int2*)(ei + N_EDGES))[i];
        int p0 = atomicAdd(&g_cursor[d.x], 1);
        int p1 = atomicAdd(&g_cursor[d.y], 1);
        g_csrc[p0] = s.x;
        g_csrc[p1] = s.y;
    } else if (i < HALF + N_NODES) {
        int v = i - HALF;
        int pos = atomicAdd(&g_cursor[v], 1);
        g_csrc[pos] = v;
    }
}

// ---------------------------------------------------------------------------
// bf16 GEMM, 3-stage cp.async pipeline + fused attention epilogue + PDL.
// NSUB=10 -> BN=160 (exact tiling for 320/480). NSUB=2 -> BN=32 (layer 3).
// ---------------------------------------------------------------------------
#define SROW 20
#define A_STAGE_U32 (128 * SROW)

__device__ __forceinline__ void cp16(uint32_t dst, const void* src, int bytes) {
    asm volatile("cp.async.cg.shared.global [%0], [%1], 16, %2;"
                 :: "r"(dst), "l"(src), "r"(bytes));
}
__device__ __forceinline__ void cp_commit() {
    asm volatile("cp.async.commit_group;");
}
template<int N>
__device__ __forceinline__ void cp_wait() {
    asm volatile("cp.async.wait_group %0;" :: "n"(N));
}

template<int NSUB>
__global__ void __launch_bounds__(256, 2)
gemm_att(const __nv_bfloat16* __restrict__ A, const __nv_bfloat16* __restrict__ B,
         __nv_bfloat16* __restrict__ C,
         const float* __restrict__ att_src, const float* __restrict__ att_dst,
         float* __restrict__ asrc, float* __restrict__ adst,
         int N, int M, int K, int H, int Cc, int prefetchB) {
    const int BN = NSUB * 16, BK = 32;
    const int B_STAGE_U32 = BN * SROW;
    extern __shared__ uint32_t dynsmem[];
    uint32_t* AsBase = dynsmem;
    uint32_t* BsBase = dynsmem + 3 * A_STAGE_U32;

    int tid  = threadIdx.x;
    int lane = tid & 31;
    int wid  = tid >> 5;
    int wr = (wid & 3) * 32;
    int wc = (wid >> 2) * (BN / 2);
    int gid = lane >> 2;
    int tig = lane & 3;

    int blockRow = blockIdx.y * 128;
    int blockCol = blockIdx.x * BN;

    int r0c = (tid + 0)   >> 2, q0 = (tid + 0)   & 3;
    int r1c = (tid + 256) >> 2, q1 = (tid + 256) & 3;

    uint32_t asm0 = (uint32_t)__cvta_generic_to_shared(AsBase);
    uint32_t bsm0 = (uint32_t)__cvta_generic_to_shared(BsBase);

    auto issueA = [&](int k0, int st) {
        uint32_t base = asm0 + st * (A_STAGE_U32 * 4);
        int ba0 = (blockRow + r0c < N) ? 16 : 0;
        int ba1 = (blockRow + r1c < N) ? 16 : 0;
        cp16(base + (r0c * SROW + q0 * 4) * 4,
             A + (size_t)(blockRow + r0c) * K + k0 + q0 * 8, ba0);
        cp16(base + (r1c * SROW + q1 * 4) * 4,
             A + (size_t)(blockRow + r1c) * K + k0 + q1 * 8, ba1);
    };
    auto issueB = [&](int k0, int st) {
        uint32_t base = bsm0 + st * (B_STAGE_U32 * 4);
        for (int c = tid; c < BN * 4; c += 256) {
            int row = c >> 2, q = c & 3;
            int bb = (blockCol + row < M) ? 16 : 0;
            cp16(base + (row * SROW + q * 4) * 4,
                 B + (size_t)(blockCol + row) * K + k0 + q * 8, bb);
        }
    };

    float acc[2][NSUB][4];
#pragma unroll
    for (int mt = 0; mt < 2; mt++)
#pragma unroll
        for (int nt = 0; nt < NSUB; nt++)
#pragma unroll
            for (int i = 0; i < 4; i++) acc[mt][nt][i] = 0.f;

    int nIt = K / BK;

    if (prefetchB) issueB(0, 0);
    cudaGridDependencySynchronize();
    issueA(0, 0);
    if (!prefetchB) issueB(0, 0);
    cp_commit();
    if (nIt > 1) {
        issueA(BK, 1);
        issueB(BK, 1);
        cp_commit();
    }

    for (int it = 0; it < nIt; it++) {
        int buf = it % 3;
        if (it + 2 < nIt) {
            issueA((it + 2) * BK, (it + 2) % 3);
            issueB((it + 2) * BK, (it + 2) % 3);
            cp_commit();
            cp_wait<2>();
        } else if (it + 1 < nIt) {
            cp_wait<1>();
        } else {
            cp_wait<0>();
        }
        __syncthreads();

        const uint32_t* As = AsBase + buf * A_STAGE_U32;
        const uint32_t* Bs = BsBase + buf * B_STAGE_U32;

#pragma unroll
        for (int ks = 0; ks < 2; ks++) {
            int kb = ks * 8;
            uint32_t a[2][4], b[NSUB][2];
#pragma unroll
            for (int mt = 0; mt < 2; mt++) {
                int r0 = wr + mt * 16;
                a[mt][0] = As[(r0 + gid    ) * SROW + kb + tig    ];
                a[mt][1] = As[(r0 + gid + 8) * SROW + kb + tig    ];
                a[mt][2] = As[(r0 + gid    ) * SROW + kb + tig + 4];
                a[mt][3] = As[(r0 + gid + 8) * SROW + kb + tig + 4];
            }
#pragma unroll
            for (int nt = 0; nt < NSUB; nt++) {
                int n0 = wc + nt * 8 + gid;
                b[nt][0] = Bs[n0 * SROW + kb + tig    ];
                b[nt][1] = Bs[n0 * SROW + kb + tig + 4];
            }
#pragma unroll
            for (int mt = 0; mt < 2; mt++)
#pragma unroll
                for (int nt = 0; nt < NSUB; nt++) {
                    asm volatile(
                        "mma.sync.aligned.m16n8k16.row.col.f32.bf16.bf16.f32 "
                        "{%0,%1,%2,%3}, {%4,%5,%6,%7}, {%8,%9}, {%0,%1,%2,%3};"
                        : "+f"(acc[mt][nt][0]), "+f"(acc[mt][nt][1]),
                          "+f"(acc[mt][nt][2]), "+f"(acc[mt][nt][3])
                        : "r"(a[mt][0]), "r"(a[mt][1]), "r"(a[mt][2]), "r"(a[mt][3]),
                          "r"(b[nt][0]), "r"(b[nt][1]));
                }
        }
        __syncthreads();
    }

    int h_first = (blockCol + wc) / Cc;
    float psrc[2][2][2] = {};
    float pdst[2][2][2] = {};

#pragma unroll
    for (int mt = 0; mt < 2; mt++) {
#pragma unroll
        for (int nt = 0; nt < NSUB; nt++) {
            int r0 = blockRow + wr + mt * 16 + gid;
            int c0 = blockCol + wc + nt * 8 + tig * 2;
            if (c0 < M) {
                if (r0 < N)
                    *(uint32_t*)(C + (size_t)r0 * M + c0) =
                        pack_bf16x2(acc[mt][nt][0], acc[mt][nt][1]);
                if (r0 + 8 < N)
                    *(uint32_t*)(C + (size_t)(r0 + 8) * M + c0) =
                        pack_bf16x2(acc[mt][nt][2], acc[mt][nt][3]);
                int hb = (blockCol + wc + nt * 8) / Cc - h_first;
                float a0 = att_src[c0], a1 = att_src[c0 + 1];
                float d0 = att_dst[c0], d1 = att_dst[c0 + 1];
                psrc[mt][0][hb] += acc[mt][nt][0] * a0 + acc[mt][nt][1] * a1;
                psrc[mt][1][hb] += acc[mt][nt][2] * a0 + acc[mt][nt][3] * a1;
                pdst[mt][0][hb] += acc[mt][nt][0] * d0 + acc[mt][nt][1] * d1;
                pdst[mt][1][hb] += acc[mt][nt][2] * d0 + acc[mt][nt][3] * d1;
            }
        }
    }
#pragma unroll
    for (int mt = 0; mt < 2; mt++)
#pragma unroll
        for (int hf = 0; hf < 2; hf++)
#pragma unroll
            for (int bk = 0; bk < 2; bk++) {
                float s = psrc[mt][hf][bk], d = pdst[mt][hf][bk];
                s += __shfl_xor_sync(0xffffffffu, s, 1);
                s += __shfl_xor_sync(0xffffffffu, s, 2);
                d += __shfl_xor_sync(0xffffffffu, d, 1);
                d += __shfl_xor_sync(0xffffffffu, d, 2);
                psrc[mt][hf][bk] = s; pdst[mt][hf][bk] = d;
            }
    if (tig == 0) {
#pragma unroll
        for (int mt = 0; mt < 2; mt++)
#pragma unroll
            for (int hf = 0; hf < 2; hf++) {
                int row = blockRow + wr + mt * 16 + gid + hf * 8;
                if (row >= N) continue;
#pragma unroll
                for (int bk = 0; bk < 2; bk++) {
                    int hidx = h_first + bk;
                    if (hidx < H) {
                        atomicAdd(&asrc[row * H + hidx], psrc[mt][hf][bk]);
                        atomicAdd(&adst[row * H + hidx], pdst[mt][hf][bk]);
                    }
                }
            }
    }
}

// ---------------------------------------------------------------------------
// GAT aggregation, H=5. Warp 0 softmax (all heads), gather unroll 4.
// ---------------------------------------------------------------------------
template<int C>
__global__ void __launch_bounds__(128)
gat_agg5(const __nv_bfloat16* __restrict__ hfeat,
         const float* __restrict__ asrc,
         const float* __restrict__ adst,
         const float* __restrict__ bias,
         __nv_bfloat16* __restrict__ out) {
    const int HC = 5 * C, NC4 = HC / 4;
    const int EMAX = 128;
    __shared__ float s_e[EMAX * 5];
    __shared__ int   s_src[EMAX];
    __shared__ float s_m[5], s_iz[5];

    cudaGridDependencySynchronize();

    int v = blockIdx.x;
    int tid = threadIdx.x, lane = tid & 31, wid = tid >> 5;
    int base = g_rowptr[v];
    int deg = g_rowptr[v + 1] - base;

    float4 acc = make_float4(0.f, 0.f, 0.f, 0.f);
    int head = (tid * 4) / C;

    if (deg <= 32) {
        if (wid == 0) {
            int s = 0;
            float e[5];
            if (lane < deg) {
                s = g_csrc[base + lane];
                s_src[lane] = s;
#pragma unroll
                for (int h = 0; h < 5; h++) {
                    float t = asrc[s * 5 + h] + adst[v * 5 + h];
                    e[h] = (t > 0.f) ? t : NEG_SLOPE * t;
                }
            } else {
#pragma unroll
                for (int h = 0; h < 5; h++) e[h] = -INFINITY;
            }
#pragma unroll
            for (int h = 0; h < 5; h++) {
                float m = e[h];
#pragma unroll
                for (int o = 16; o > 0; o >>= 1)
                    m = fmaxf(m, __shfl_xor_sync(0xffffffffu, m, o));
                float ex = (lane < deg) ? __expf(e[h] - m) : 0.f;
                float z = ex;
#pragma unroll
                for (int o = 16; o > 0; o >>= 1)
                    z += __shfl_xor_sync(0xffffffffu, z, o);
                if (lane < deg) s_e[lane * 5 + h] = ex / (z + EPS_F);
            }
        }
        __syncthreads();
        if (tid < NC4) {
#pragma unroll 4
            for (int j = 0; j < deg; j++) {
                const uint2* hp = (const uint2*)(hfeat + (size_t)s_src[j] * HC);
                float w = s_e[j * 5 + head];
                uint2 hv = hp[tid];
                float2 lo = __bfloat1622float2(*(__nv_bfloat162*)&hv.x);
                float2 hi = __bfloat1622float2(*(__nv_bfloat162*)&hv.y);
                acc.x += w * lo.x; acc.y += w * lo.y;
                acc.z += w * hi.x; acc.w += w * hi.y;
            }
        }
    } else {
        if (wid == 0) {
#pragma unroll
            for (int h = 0; h < 5; h++) {
                float ad = adst[v * 5 + h];
                float m = -INFINITY;
                for (int j = lane; j < deg; j += 32) {
                    int s = g_csrc[base + j];
                    float e = asrc[s * 5 + h] + ad;
                    e = (e > 0.f) ? e : NEG_SLOPE * e;
                    m = fmaxf(m, e);
                }
#pragma unroll
                for (int o = 16; o > 0; o >>= 1)
                    m = fmaxf(m, __shfl_xor_sync(0xffffffffu, m, o));
                float z = 0.f;
                for (int j = lane; j < deg; j += 32) {
                    int s = g_csrc[base + j];
                    float e = asrc[s * 5 + h] + ad;
                    e = (e > 0.f) ? e : NEG_SLOPE * e;
                    z += __expf(e - m);
                }
#pragma unroll
                for (int o = 16; o > 0; o >>= 1)
                    z += __shfl_xor_sync(0xffffffffu, z, o);
                if (lane == 0) { s_m[h] = m; s_iz[h] = 1.f / (z + EPS_F); }
            }
        }
        __syncthreads();
        for (int j0 = 0; j0 < deg; j0 += EMAX) {
            int ch = min(EMAX, deg - j0);
            for (int idx = tid; idx < ch * 5; idx += blockDim.x) {
                int j = idx / 5, hh = idx - j * 5;
                int s = g_csrc[base + j0 + j];
                if (hh == 0) s_src[j] = s;
                float e = asrc[s * 5 + hh] + adst[v * 5 + hh];
                e = (e > 0.f) ? e : NEG_SLOPE * e;
                s_e[j * 5 + hh] = __expf(e - s_m[hh]) * s_iz[hh];
            }
            __syncthreads();
            if (tid < NC4) {
                for (int j = 0; j < ch; j++) {
                    const uint2* hp = (const uint2*)(hfeat + (size_t)s_src[j] * HC);
                    float w = s_e[j * 5 + head];
                    uint2 hv = hp[tid];
                    float2 lo = __bfloat1622float2(*(__nv_bfloat162*)&hv.x);
                    float2 hi = __bfloat1622float2(*(__nv_bfloat162*)&hv.y);
                    acc.x += w * lo.x; acc.y += w * lo.y;
                    acc.z += w * hi.x; acc.w += w * hi.y;
                }
            }
            __syncthreads();
        }
    }

    if (tid < NC4) {
        float4 b = ((const float4*)bias)[tid];
        uint2 o;
        o.x = pack_bf16x2(fmaxf(acc.x + b.x, 0.f), fmaxf(acc.y + b.y, 0.f));
        o.y = pack_bf16x2(fmaxf(acc.z + b.z, 0.f), fmaxf(acc.w + b.w, 0.f));
        ((uint2*)(out + (size_t)v * HC))[tid] = o;
    }
}

// ---------------------------------------------------------------------------
// GAT aggregation, H=1, C=32 + fused pool. warp per node.
// ---------------------------------------------------------------------------
__global__ void __launch_bounds__(256)
gat_agg1_pool(const __nv_bfloat16* __restrict__ hfeat,
              const float* __restrict__ asrc,
              const float* __restrict__ adst,
              const float* __restrict__ bias,
              const int* __restrict__ batch) {
    cudaGridDependencySynchronize();

    int wid = threadIdx.x >> 5, lane = threadIdx.x & 31;
    int v = blockIdx.x * 8 + wid;
    if (v >= N_NODES) return;
    int base = g_rowptr[v];
    int deg = g_rowptr[v + 1] - base;
    float ad = adst[v];
    float* pool = (float*)(g_zero + N_NODES);
    float acc = 0.f;

    if (deg <= 32) {
        int s_j = 0;
        float e = -INFINITY;
        if (lane < deg) {
            s_j = g_csrc[base + lane];
            e = asrc[s_j] + ad;
            e = (e > 0.f) ? e : NEG_SLOPE * e;
        }
        float m = e;
#pragma unroll
        for (int o = 16; o > 0; o >>= 1)
            m = fmaxf(m, __shfl_xor_sync(0xffffffffu, m, o));
        float ex = (lane < deg) ? __expf(e - m) : 0.f;
        float z = ex;
#pragma unroll
        for (int o = 16; o > 0; o >>= 1)
            z += __shfl_xor_sync(0xffffffffu, z, o);
        float wn = ex / (z + EPS_F);

#pragma unroll 4
        for (int j = 0; j < deg; j++) {
            float w = __shfl_sync(0xffffffffu, wn, j);
            int s  = __shfl_sync(0xffffffffu, s_j, j);
            acc += w * __bfloat162float(hfeat[(size_t)s * 32 + lane]);
        }
    } else {
        float m = -INFINITY;
        for (int j = lane; j < deg; j += 32) {
            int s = g_csrc[base + j];
            float e = asrc[s] + ad;
            e = (e > 0.f) ? e : NEG_SLOPE * e;
            m = fmaxf(m, e);
        }
#pragma unroll
        for (int o = 16; o > 0; o >>= 1)
            m = fmaxf(m, __shfl_xor_sync(0xffffffffu, m, o));
        float z = 0.f;
        for (int j = lane; j < deg; j += 32) {
            int s = g_csrc[base + j];
            float e = asrc[s] + ad;
            e = (e > 0.f) ? e : NEG_SLOPE * e;
            z += __expf(e - m);
        }
#pragma unroll
        for (int o = 16; o > 0; o >>= 1)
            z += __shfl_xor_sync(0xffffffffu, z, o);
        float iz = 1.f / (z + EPS_F);

#pragma unroll 2
        for (int j = 0; j < deg; j++) {
            int s = g_csrc[base + j];
            float e = asrc[s] + ad;
            e = (e > 0.f) ? e : NEG_SLOPE * e;
            float w = __expf(e - m) * iz;
            acc += w * __bfloat162float(hfeat[(size_t)s * 32 + lane]);
        }
    }

    float o = fmaxf(acc + bias[lane], 0.f);
    atomicAdd(&pool[batch[v] * 32 + lane], o);
}

// ---------------------------------------------------------------------------
// MLP head (self-cleans pool)
// ---------------------------------------------------------------------------
__global__ void mlp_kernel(const float* __restrict__ lin_w,
                           const float* __restrict__ lin_b,
                           const float* __restrict__ lin2_w,
                           const float* __restrict__ lin2_b,
                           float* __restrict__ out) {
    cudaGridDependencySynchronize();

    int g = blockIdx.x;
    __shared__ float sg[32];
    __shared__ float sred[256];
    int tid = threadIdx.x;
    float* pool = (float*)(g_zero + N_NODES);
    if (tid < 32) {
        sg[tid] = pool[g * 32 + tid];
        pool[g * 32 + tid] = 0.f;
    }
    __syncthreads();
    float partial = 0.f;
    for (int u = tid; u < 1024; u += 256) {
        float d = lin_b[u];
        const float* wr = lin_w + u * 32;
#pragma unroll
        for (int c = 0; c < 32; c++) d += sg[c] * wr[c];
        d = fmaxf(d, 0.f);
        partial += d * lin2_w[u];
    }
    sred[tid] = partial;
    __syncthreads();
    for (int s = 128; s > 0; s >>= 1) {
        if (tid < s) sred[tid] += sred[tid + s];
        __syncthreads();
    }
    if (tid == 0) {
        float v = sred[0] + lin2_b[0];
        out[g] = 1.f / (1.f + __expf(-v));
    }
}

// ---------------------------------------------------------------------------
// PDL launch helper
// ---------------------------------------------------------------------------
template<typename Kern, typename... Args>
static inline void launch_pdl(Kern k, dim3 grid, dim3 block, size_t smem,
                              Args... args) {
    cudaLaunchConfig_t cfg = {};
    cfg.gridDim = grid;
    cfg.blockDim = block;
    cfg.dynamicSmemBytes = smem;
    cfg.stream = 0;
    cudaLaunchAttribute attr[1];
    attr[0].id = cudaLaunchAttributeProgrammaticStreamSerialization;
    attr[0].val.programmaticStreamSerializationAllowed = 1;
    cfg.attrs = attr;
    cfg.numAttrs = 1;
    cudaLaunchKernelEx(&cfg, k, args...);
}

#define GEMM_SMEM(NSUB) ((3 * A_STAGE_U32 + 3 * (NSUB) * 16 * SROW) * 4)

// ---------------------------------------------------------------------------
// launch
// ---------------------------------------------------------------------------
extern "C" void kernel_launch(void* const* d_in, const int* in_sizes, int n_in,
                              void* d_out, int out_size) {
    const float* x        = (const float*)d_in[0];
    const float* W1       = (const float*)d_in[1];
    const float* att_s1   = (const float*)d_in[2];
    const float* att_d1   = (const float*)d_in[3];
    const float* b1       = (const float*)d_in[4];
    const float* W2       = (const float*)d_in[5];
    const float* att_s2   = (const float*)d_in[6];
    const float* att_d2   = (const float*)d_in[7];
    const float* b2       = (const float*)d_in[8];
    const float* W3       = (const float*)d_in[9];
    const float* att_s3   = (const float*)d_in[10];
    const float* att_d3   = (const float*)d_in[11];
    const float* b3       = (const float*)d_in[12];
    const float* lin_w    = (const float*)d_in[13];
    const float* lin_b    = (const float*)d_in[14];
    const float* lin2_w   = (const float*)d_in[15];
    const float* lin2_b   = (const float*)d_in[16];
    const int*   ei       = (const int*)d_in[17];
    const int*   batch    = (const int*)d_in[18];
    float* out = (float*)d_out;

    __nv_bfloat16 *xq, *w1q, *w2q, *w3q, *h1, *o1, *h2, *o2, *h3;
    float *attbuf;
    cudaGetSymbolAddress((void**)&xq, g_xq);
    cudaGetSymbolAddress((void**)&w1q, g_w1q);
    cudaGetSymbolAddress((void**)&w2q, g_w2q);
    cudaGetSymbolAddress((void**)&w3q, g_w3q);
    cudaGetSymbolAddress((void**)&h1, g_h1);
    cudaGetSymbolAddress((void**)&o1, g_o1);
    cudaGetSymbolAddress((void**)&h2, g_h2);
    cudaGetSymbolAddress((void**)&o2, g_o2);
    cudaGetSymbolAddress((void**)&h3, g_h3);
    cudaGetSymbolAddress((void**)&attbuf, g_att);

    float* as1 = attbuf;                    float* ad1 = attbuf + N_NODES * 5;
    float* as2 = attbuf + 2 * N_NODES * 5;  float* ad2 = attbuf + 3 * N_NODES * 5;
    float* as3 = attbuf + 4 * N_NODES * 5;  float* ad3 = attbuf + 5 * N_NODES * 5;

    static cudaStream_t s_cs = nullptr;
    static cudaEvent_t ev_fork = nullptr, ev_join = nullptr;
    if (!s_cs) {
        cudaStreamCreateWithFlags(&s_cs, cudaStreamNonBlocking);
        cudaEventCreateWithFlags(&ev_fork, cudaEventDisableTiming);
        cudaEventCreateWithFlags(&ev_join, cudaEventDisableTiming);
        cudaFuncSetAttribute(gemm_att<10>,
                             cudaFuncAttributeMaxDynamicSharedMemorySize,
                             GEMM_SMEM(10));
        cudaFuncSetAttribute(gemm_att<2>,
                             cudaFuncAttributeMaxDynamicSharedMemorySize,
                             GEMM_SMEM(2));
    }

    // ---- fork: CSR build on side stream ----
    cudaEventRecord(ev_fork, 0);
    cudaStreamWaitEvent(s_cs, ev_fork, 0);
    count_kernel<<<(N_EDGES / 2 + 255) / 256, 256, 0, s_cs>>>(ei);
    scan1_kernel<<<N_BLK, 256, 0, s_cs>>>();
    scan3_kernel<<<N_BLK, 256, 0, s_cs>>>();
    scatter_kernel<<<(N_EDGES / 2 + N_NODES + 255) / 256, 256, 0, s_cs>>>(ei);
    cudaEventRecord(ev_join, s_cs);

    // ---- main chain ----
    prep_kernel<<<(N_NODES * 64 / 4 + 255) / 256, 256>>>(x, W1, W2, W3);

    const int GY = (N_NODES + 127) / 128;

    launch_pdl(gemm_att<10>, dim3(HC1 / 160, GY), dim3(256), GEMM_SMEM(10),
               (const __nv_bfloat16*)xq, (const __nv_bfloat16*)w1q, h1,
               att_s1, att_d1, as1, ad1, N_NODES, HC1, 64, 5, 64, 0);

    // agg1: NORMAL launch (full dependency) — anchors prep + carries CSR join.
    cudaStreamWaitEvent(0, ev_join, 0);
    gat_agg5<64><<<N_NODES, 96>>>(h1, as1, ad1, b1, o1);

    launch_pdl(gemm_att<10>, dim3(HC2 / 160, GY), dim3(256), GEMM_SMEM(10),
               (const __nv_bfloat16*)o1, (const __nv_bfloat16*)w2q, h2,
               att_s2, att_d2, as2, ad2, N_NODES, HC2, HC1, 5, 96, 1);
    launch_pdl(gat_agg5<96>, dim3(N_NODES), dim3(128), (size_t)0,
               (const __nv_bfloat16*)h2,
               (const float*)as2, (const float*)ad2, b2, o2);

    launch_pdl(gemm_att<2>, dim3(1, GY), dim3(256), GEMM_SMEM(2),
               (const __nv_bfloat16*)o2, (const __nv_bfloat16*)w3q, h3,
               att_s3, att_d3, as3, ad3, N_NODES, HC3, HC2, 1, 32, 1);
    launch_pdl(gat_agg1_pool, dim3((N_NODES + 7) / 8), dim3(256), (size_t)0,
               (const __nv_bfloat16*)h3, (const float*)as3, (const float*)ad3,
               b3, batch);

    launch_pdl(mlp_kernel, dim3(N_GRAPHS), dim3(256), (size_t)0,
               lin_w, lin_b, lin2_w, lin2_b, out);
}

// round 16
// speedup vs baseline: 1.2372x; 1.0107x over previous
#include <cuda_runtime.h>
#include <cuda_bf16.h>
#include <math.h>
#include <stdint.h>

// ---------------------------------------------------------------------------
// Problem constants
// ---------------------------------------------------------------------------
#define N_NODES 20000
#define N_EDGES 320000
#define TOT_E   (N_EDGES + N_NODES)
#define N_GRAPHS 128
#define NEG_SLOPE 0.2f
#define EPS_F 1e-16f

#define HC1 320   // H=5, C=64
#define HC2 480   // H=5, C=96
#define HC3 32    // H=1, C=32

#define N_BLK ((N_NODES + 255) / 256)   // 79

// ---------------------------------------------------------------------------
// Device scratch. g_zero (cnt+pool) is SELF-CLEANING.
// ---------------------------------------------------------------------------
__device__ __align__(16) __nv_bfloat16 g_xq[N_NODES * 64];
__device__ __align__(16) __nv_bfloat16 g_w1q[HC1 * 64];
__device__ __align__(16) __nv_bfloat16 g_w2q[HC2 * HC1];
__device__ __align__(16) __nv_bfloat16 g_w3q[HC3 * HC2];
__device__ __align__(16) __nv_bfloat16 g_h1[N_NODES * HC1];
__device__ __align__(16) __nv_bfloat16 g_o1[N_NODES * HC1];
__device__ __align__(16) __nv_bfloat16 g_h2[N_NODES * HC2];
__device__ __align__(16) __nv_bfloat16 g_o2[N_NODES * HC2];
__device__ __align__(16) __nv_bfloat16 g_h3[N_NODES * HC3];
__device__ float g_att[6 * N_NODES * 5];
__device__ int   g_zero[N_NODES + N_GRAPHS * 32];   // cnt | pool
__device__ int   g_rowptr[N_NODES + 1];
__device__ int   g_cursor[N_NODES];
__device__ int   g_csrc[TOT_E];
__device__ int   g_bsum[N_BLK];

__device__ __forceinline__ uint32_t pack_bf16x2(float lo, float hi) {
    __nv_bfloat162 h2 = __floats2bfloat162_rn(lo, hi);
    return *(uint32_t*)&h2;
}

// ---------------------------------------------------------------------------
// prep: x->bf16, W->bf16, zero att. NO grid-dep sync: runs under PDL fully
// overlapped with count_kernel (disjoint buffers).
// ---------------------------------------------------------------------------
#define W1Q4 (HC1 * 64 / 4)
#define W2Q4 (HC2 * HC1 / 4)
#define W3Q4 (HC3 * HC2 / 4)

__global__ void prep_kernel(const float* __restrict__ x,
                            const float* __restrict__ W1,
                            const float* __restrict__ W2,
                            const float* __restrict__ W3) {
    int i = blockIdx.x * 256 + threadIdx.x;
    if (i < N_NODES * 64 / 4) {
        float4 v = ((const float4*)x)[i];
        uint2 p;
        p.x = pack_bf16x2(v.x, v.y);
        p.y = pack_bf16x2(v.z, v.w);
        ((uint2*)g_xq)[i] = p;
    }
    if (2 * i < 6 * N_NODES * 5) {
        g_att[2 * i] = 0.f;
        if (2 * i + 1 < 6 * N_NODES * 5) g_att[2 * i + 1] = 0.f;
    }
    if (i < W1Q4 + W2Q4 + W3Q4) {
        const float4* src;
        uint2* dst;
        int j = i;
        if (j < W1Q4)                { src = (const float4*)W1; dst = (uint2*)g_w1q; }
        else if ((j -= W1Q4) < W2Q4) { src = (const float4*)W2; dst = (uint2*)g_w2q; }
        else { j -= W2Q4;              src = (const float4*)W3; dst = (uint2*)g_w3q; }
        float4 v = src[j];
        uint2 p;
        p.x = pack_bf16x2(v.x, v.y);
        p.y = pack_bf16x2(v.z, v.w);
        dst[j] = p;
    }
}

// ---------------------------------------------------------------------------
// CSR construction. 4 edges per thread (atomic MLP=4, latency-bound path).
// ---------------------------------------------------------------------------
__global__ void count_kernel(const int* __restrict__ ei) {
    int i = blockIdx.x * blockDim.x + threadIdx.x;
    if (i < N_EDGES / 4) {
        int4 d = ((const int4*)(ei + N_EDGES))[i];
        atomicAdd(&g_zero[d.x], 1);
        atomicAdd(&g_zero[d.y], 1);
        atomicAdd(&g_zero[d.z], 1);
        atomicAdd(&g_zero[d.w], 1);
    }
}

__global__ void scan1_kernel() {
    int i = blockIdx.x * 256 + threadIdx.x;
    int lane = threadIdx.x & 31, w = threadIdx.x >> 5;
    int x = (i < N_NODES) ? (g_zero[i] + 1) : 0;
#pragma unroll
    for (int o = 1; o < 32; o <<= 1) {
        int t = __shfl_up_sync(0xffffffffu, x, o);
        if (lane >= o) x += t;
    }
    __shared__ int wsum[8];
    if (lane == 31) wsum[w] = x;
    __syncthreads();
    if (w == 0) {
        int s = (lane < 8) ? wsum[lane] : 0;
#pragma unroll
        for (int o = 1; o < 8; o <<= 1) {
            int t = __shfl_up_sync(0xffffffffu, s, o);
            if (lane >= o) s += t;
        }
        if (lane < 8) wsum[lane] = s;
    }
    __syncthreads();
    int incl = x + ((w > 0) ? wsum[w - 1] : 0);
    if (i < N_NODES) g_rowptr[i + 1] = incl;
    if (threadIdx.x == 255) g_bsum[blockIdx.x] = incl;
}

__global__ void scan3_kernel() {
    __shared__ int s_off;
    int tid = threadIdx.x, lane = tid & 31;
    if (tid < 32) {
        int off = 0;
        for (int j = lane; j < blockIdx.x; j += 32) off += g_bsum[j];
#pragma unroll
        for (int o = 16; o > 0; o >>= 1)
            off += __shfl_xor_sync(0xffffffffu, off, o);
        if (lane == 0) s_off = off;
    }
    __syncthreads();
    int i = blockIdx.x * 256 + tid;
    if (i == 0) g_rowptr[0] = 0;
    if (i < N_NODES) {
        int incl = g_rowptr[i + 1] + s_off;
        g_rowptr[i + 1] = incl;
        g_cursor[i] = incl - (g_zero[i] + 1);
        g_zero[i] = 0;                       // self-clean
    }
}

// 4 edges per thread; self loops appended
__global__ void scatter_kernel(const int* __restrict__ ei) {
    int i = blockIdx.x * blockDim.x + threadIdx.x;
    const int Q = N_EDGES / 4;
    if (i < Q) {
        int4 s = ((const int4*)ei)[i];
        int4 d = ((const int4*)(ei + N_EDGES))[i];
        int p0 = atomicAdd(&g_cursor[d.x], 1);
        int p1 = atomicAdd(&g_cursor[d.y], 1);
        int p2 = atomicAdd(&g_cursor[d.z], 1);
        int p3 = atomicAdd(&g_cursor[d.w], 1);
        g_csrc[p0] = s.x;
        g_csrc[p1] = s.y;
        g_csrc[p2] = s.z;
        g_csrc[p3] = s.w;
    } else if (i < Q + N_NODES) {
        int v = i - Q;
        int pos = atomicAdd(&g_cursor[v], 1);
        g_csrc[pos] = v;
    }
}

// ---------------------------------------------------------------------------
// bf16 GEMM, 3-stage cp.async pipeline + fused attention epilogue + PDL.
// NSUB=10 -> BN=160 (exact tiling for 320/480). NSUB=2 -> BN=32 (layer 3).
// ---------------------------------------------------------------------------
#define SROW 20
#define A_STAGE_U32 (128 * SROW)

__device__ __forceinline__ void cp16(uint32_t dst, const void* src, int bytes) {
    asm volatile("cp.async.cg.shared.global [%0], [%1], 16, %2;"
                 :: "r"(dst), "l"(src), "r"(bytes));
}
__device__ __forceinline__ void cp_commit() {
    asm volatile("cp.async.commit_group;");
}
template<int N>
__device__ __forceinline__ void cp_wait() {
    asm volatile("cp.async.wait_group %0;" :: "n"(N));
}

template<int NSUB>
__global__ void __launch_bounds__(256, 2)
gemm_att(const __nv_bfloat16* __restrict__ A, const __nv_bfloat16* __restrict__ B,
         __nv_bfloat16* __restrict__ C,
         const float* __restrict__ att_src, const float* __restrict__ att_dst,
         float* __restrict__ asrc, float* __restrict__ adst,
         int N, int M, int K, int H, int Cc, int prefetchB) {
    const int BN = NSUB * 16, BK = 32;
    const int B_STAGE_U32 = BN * SROW;
    extern __shared__ uint32_t dynsmem[];
    uint32_t* AsBase = dynsmem;
    uint32_t* BsBase = dynsmem + 3 * A_STAGE_U32;

    int tid  = threadIdx.x;
    int lane = tid & 31;
    int wid  = tid >> 5;
    int wr = (wid & 3) * 32;
    int wc = (wid >> 2) * (BN / 2);
    int gid = lane >> 2;
    int tig = lane & 3;

    int blockRow = blockIdx.y * 128;
    int blockCol = blockIdx.x * BN;

    int r0c = (tid + 0)   >> 2, q0 = (tid + 0)   & 3;
    int r1c = (tid + 256) >> 2, q1 = (tid + 256) & 3;

    uint32_t asm0 = (uint32_t)__cvta_generic_to_shared(AsBase);
    uint32_t bsm0 = (uint32_t)__cvta_generic_to_shared(BsBase);

    auto issueA = [&](int k0, int st) {
        uint32_t base = asm0 + st * (A_STAGE_U32 * 4);
        int ba0 = (blockRow + r0c < N) ? 16 : 0;
        int ba1 = (blockRow + r1c < N) ? 16 : 0;
        cp16(base + (r0c * SROW + q0 * 4) * 4,
             A + (size_t)(blockRow + r0c) * K + k0 + q0 * 8, ba0);
        cp16(base + (r1c * SROW + q1 * 4) * 4,
             A + (size_t)(blockRow + r1c) * K + k0 + q1 * 8, ba1);
    };
    auto issueB = [&](int k0, int st) {
        uint32_t base = bsm0 + st * (B_STAGE_U32 * 4);
        for (int c = tid; c < BN * 4; c += 256) {
            int row = c >> 2, q = c & 3;
            int bb = (blockCol + row < M) ? 16 : 0;
            cp16(base + (row * SROW + q * 4) * 4,
                 B + (size_t)(blockCol + row) * K + k0 + q * 8, bb);
        }
    };

    float acc[2][NSUB][4];
#pragma unroll
    for (int mt = 0; mt < 2; mt++)
#pragma unroll
        for (int nt = 0; nt < NSUB; nt++)
#pragma unroll
            for (int i = 0; i < 4; i++) acc[mt][nt][i] = 0.f;

    int nIt = K / BK;

    if (prefetchB) issueB(0, 0);
    cudaGridDependencySynchronize();
    issueA(0, 0);
    if (!prefetchB) issueB(0, 0);
    cp_commit();
    if (nIt > 1) {
        issueA(BK, 1);
        issueB(BK, 1);
        cp_commit();
    }

    for (int it = 0; it < nIt; it++) {
        int buf = it % 3;
        if (it + 2 < nIt) {
            issueA((it + 2) * BK, (it + 2) % 3);
            issueB((it + 2) * BK, (it + 2) % 3);
            cp_commit();
            cp_wait<2>();
        } else if (it + 1 < nIt) {
            cp_wait<1>();
        } else {
            cp_wait<0>();
        }
        __syncthreads();

        const uint32_t* As = AsBase + buf * A_STAGE_U32;
        const uint32_t* Bs = BsBase + buf * B_STAGE_U32;

#pragma unroll
        for (int ks = 0; ks < 2; ks++) {
            int kb = ks * 8;
            uint32_t a[2][4], b[NSUB][2];
#pragma unroll
            for (int mt = 0; mt < 2; mt++) {
                int r0 = wr + mt * 16;
                a[mt][0] = As[(r0 + gid    ) * SROW + kb + tig    ];
                a[mt][1] = As[(r0 + gid + 8) * SROW + kb + tig    ];
                a[mt][2] = As[(r0 + gid    ) * SROW + kb + tig + 4];
                a[mt][3] = As[(r0 + gid + 8) * SROW + kb + tig + 4];
            }
#pragma unroll
            for (int nt = 0; nt < NSUB; nt++) {
                int n0 = wc + nt * 8 + gid;
                b[nt][0] = Bs[n0 * SROW + kb + tig    ];
                b[nt][1] = Bs[n0 * SROW + kb + tig + 4];
            }
#pragma unroll
            for (int mt = 0; mt < 2; mt++)
#pragma unroll
                for (int nt = 0; nt < NSUB; nt++) {
                    asm volatile(
                        "mma.sync.aligned.m16n8k16.row.col.f32.bf16.bf16.f32 "
                        "{%0,%1,%2,%3}, {%4,%5,%6,%7}, {%8,%9}, {%0,%1,%2,%3};"
                        : "+f"(acc[mt][nt][0]), "+f"(acc[mt][nt][1]),
                          "+f"(acc[mt][nt][2]), "+f"(acc[mt][nt][3])
                        : "r"(a[mt][0]), "r"(a[mt][1]), "r"(a[mt][2]), "r"(a[mt][3]),
                          "r"(b[nt][0]), "r"(b[nt][1]));
                }
        }
        __syncthreads();
    }

    int h_first = (blockCol + wc) / Cc;
    float psrc[2][2][2] = {};
    float pdst[2][2][2] = {};

#pragma unroll
    for (int mt = 0; mt < 2; mt++) {
#pragma unroll
        for (int nt = 0; nt < NSUB; nt++) {
            int r0 = blockRow + wr + mt * 16 + gid;
            int c0 = blockCol + wc + nt * 8 + tig * 2;
            if (c0 < M) {
                if (r0 < N)
                    *(uint32_t*)(C + (size_t)r0 * M + c0) =
                        pack_bf16x2(acc[mt][nt][0], acc[mt][nt][1]);
                if (r0 + 8 < N)
                    *(uint32_t*)(C + (size_t)(r0 + 8) * M + c0) =
                        pack_bf16x2(acc[mt][nt][2], acc[mt][nt][3]);
                int hb = (blockCol + wc + nt * 8) / Cc - h_first;
                float a0 = att_src[c0], a1 = att_src[c0 + 1];
                float d0 = att_dst[c0], d1 = att_dst[c0 + 1];
                psrc[mt][0][hb] += acc[mt][nt][0] * a0 + acc[mt][nt][1] * a1;
                psrc[mt][1][hb] += acc[mt][nt][2] * a0 + acc[mt][nt][3] * a1;
                pdst[mt][0][hb] += acc[mt][nt][0] * d0 + acc[mt][nt][1] * d1;
                pdst[mt][1][hb] += acc[mt][nt][2] * d0 + acc[mt][nt][3] * d1;
            }
        }
    }
#pragma unroll
    for (int mt = 0; mt < 2; mt++)
#pragma unroll
        for (int hf = 0; hf < 2; hf++)
#pragma unroll
            for (int bk = 0; bk < 2; bk++) {
                float s = psrc[mt][hf][bk], d = pdst[mt][hf][bk];
                s += __shfl_xor_sync(0xffffffffu, s, 1);
                s += __shfl_xor_sync(0xffffffffu, s, 2);
                d += __shfl_xor_sync(0xffffffffu, d, 1);
                d += __shfl_xor_sync(0xffffffffu, d, 2);
                psrc[mt][hf][bk] = s; pdst[mt][hf][bk] = d;
            }
    if (tig == 0) {
#pragma unroll
        for (int mt = 0; mt < 2; mt++)
#pragma unroll
            for (int hf = 0; hf < 2; hf++) {
                int row = blockRow + wr + mt * 16 + gid + hf * 8;
                if (row >= N) continue;
#pragma unroll
                for (int bk = 0; bk < 2; bk++) {
                    int hidx = h_first + bk;
                    if (hidx < H) {
                        atomicAdd(&asrc[row * H + hidx], psrc[mt][hf][bk]);
                        atomicAdd(&adst[row * H + hidx], pdst[mt][hf][bk]);
                    }
                }
            }
    }
}

// ---------------------------------------------------------------------------
// GAT aggregation, H=5. Warp 0 softmax (all heads), gather unroll 4.
// ---------------------------------------------------------------------------
template<int C>
__global__ void __launch_bounds__(128)
gat_agg5(const __nv_bfloat16* __restrict__ hfeat,
         const float* __restrict__ asrc,
         const float* __restrict__ adst,
         const float* __restrict__ bias,
         __nv_bfloat16* __restrict__ out) {
    const int HC = 5 * C, NC4 = HC / 4;
    const int EMAX = 128;
    __shared__ float s_e[EMAX * 5];
    __shared__ int   s_src[EMAX];
    __shared__ float s_m[5], s_iz[5];

    cudaGridDependencySynchronize();

    int v = blockIdx.x;
    int tid = threadIdx.x, lane = tid & 31, wid = tid >> 5;
    int base = g_rowptr[v];
    int deg = g_rowptr[v + 1] - base;

    float4 acc = make_float4(0.f, 0.f, 0.f, 0.f);
    int head = (tid * 4) / C;

    if (deg <= 32) {
        if (wid == 0) {
            int s = 0;
            float e[5];
            if (lane < deg) {
                s = g_csrc[base + lane];
                s_src[lane] = s;
#pragma unroll
                for (int h = 0; h < 5; h++) {
                    float t = asrc[s * 5 + h] + adst[v * 5 + h];
                    e[h] = (t > 0.f) ? t : NEG_SLOPE * t;
                }
            } else {
#pragma unroll
                for (int h = 0; h < 5; h++) e[h] = -INFINITY;
            }
#pragma unroll
            for (int h = 0; h < 5; h++) {
                float m = e[h];
#pragma unroll
                for (int o = 16; o > 0; o >>= 1)
                    m = fmaxf(m, __shfl_xor_sync(0xffffffffu, m, o));
                float ex = (lane < deg) ? __expf(e[h] - m) : 0.f;
                float z = ex;
#pragma unroll
                for (int o = 16; o > 0; o >>= 1)
                    z += __shfl_xor_sync(0xffffffffu, z, o);
                if (lane < deg) s_e[lane * 5 + h] = ex / (z + EPS_F);
            }
        }
        __syncthreads();
        if (tid < NC4) {
#pragma unroll 4
            for (int j = 0; j < deg; j++) {
                const uint2* hp = (const uint2*)(hfeat + (size_t)s_src[j] * HC);
                float w = s_e[j * 5 + head];
                uint2 hv = hp[tid];
                float2 lo = __bfloat1622float2(*(__nv_bfloat162*)&hv.x);
                float2 hi = __bfloat1622float2(*(__nv_bfloat162*)&hv.y);
                acc.x += w * lo.x; acc.y += w * lo.y;
                acc.z += w * hi.x; acc.w += w * hi.y;
            }
        }
    } else {
        if (wid == 0) {
#pragma unroll
            for (int h = 0; h < 5; h++) {
                float ad = adst[v * 5 + h];
                float m = -INFINITY;
                for (int j = lane; j < deg; j += 32) {
                    int s = g_csrc[base + j];
                    float e = asrc[s * 5 + h] + ad;
                    e = (e > 0.f) ? e : NEG_SLOPE * e;
                    m = fmaxf(m, e);
                }
#pragma unroll
                for (int o = 16; o > 0; o >>= 1)
                    m = fmaxf(m, __shfl_xor_sync(0xffffffffu, m, o));
                float z = 0.f;
                for (int j = lane; j < deg; j += 32) {
                    int s = g_csrc[base + j];
                    float e = asrc[s * 5 + h] + ad;
                    e = (e > 0.f) ? e : NEG_SLOPE * e;
                    z += __expf(e - m);
                }
#pragma unroll
                for (int o = 16; o > 0; o >>= 1)
                    z += __shfl_xor_sync(0xffffffffu, z, o);
                if (lane == 0) { s_m[h] = m; s_iz[h] = 1.f / (z + EPS_F); }
            }
        }
        __syncthreads();
        for (int j0 = 0; j0 < deg; j0 += EMAX) {
            int ch = min(EMAX, deg - j0);
            for (int idx = tid; idx < ch * 5; idx += blockDim.x) {
                int j = idx / 5, hh = idx - j * 5;
                int s = g_csrc[base + j0 + j];
                if (hh == 0) s_src[j] = s;
                float e = asrc[s * 5 + hh] + adst[v * 5 + hh];
                e = (e > 0.f) ? e : NEG_SLOPE * e;
                s_e[j * 5 + hh] = __expf(e - s_m[hh]) * s_iz[hh];
            }
            __syncthreads();
            if (tid < NC4) {
                for (int j = 0; j < ch; j++) {
                    const uint2* hp = (const uint2*)(hfeat + (size_t)s_src[j] * HC);
                    float w = s_e[j * 5 + head];
                    uint2 hv = hp[tid];
                    float2 lo = __bfloat1622float2(*(__nv_bfloat162*)&hv.x);
                    float2 hi = __bfloat1622float2(*(__nv_bfloat162*)&hv.y);
                    acc.x += w * lo.x; acc.y += w * lo.y;
                    acc.z += w * hi.x; acc.w += w * hi.y;
                }
            }
            __syncthreads();
        }
    }

    if (tid < NC4) {
        float4 b = ((const float4*)bias)[tid];
        uint2 o;
        o.x = pack_bf16x2(fmaxf(acc.x + b.x, 0.f), fmaxf(acc.y + b.y, 0.f));
        o.y = pack_bf16x2(fmaxf(acc.z + b.z, 0.f), fmaxf(acc.w + b.w, 0.f));
        ((uint2*)(out + (size_t)v * HC))[tid] = o;
    }
}

// ---------------------------------------------------------------------------
// GAT aggregation, H=1, C=32 + fused pool. warp per node.
// ---------------------------------------------------------------------------
__global__ void __launch_bounds__(256)
gat_agg1_pool(const __nv_bfloat16* __restrict__ hfeat,
              const float* __restrict__ asrc,
              const float* __restrict__ adst,
              const float* __restrict__ bias,
              const int* __restrict__ batch) {
    cudaGridDependencySynchronize();

    int wid = threadIdx.x >> 5, lane = threadIdx.x & 31;
    int v = blockIdx.x * 8 + wid;
    if (v >= N_NODES) return;
    int base = g_rowptr[v];
    int deg = g_rowptr[v + 1] - base;
    float ad = adst[v];
    float* pool = (float*)(g_zero + N_NODES);
    float acc = 0.f;

    if (deg <= 32) {
        int s_j = 0;
        float e = -INFINITY;
        if (lane < deg) {
            s_j = g_csrc[base + lane];
            e = asrc[s_j] + ad;
            e = (e > 0.f) ? e : NEG_SLOPE * e;
        }
        float m = e;
#pragma unroll
        for (int o = 16; o > 0; o >>= 1)
            m = fmaxf(m, __shfl_xor_sync(0xffffffffu, m, o));
        float ex = (lane < deg) ? __expf(e - m) : 0.f;
        float z = ex;
#pragma unroll
        for (int o = 16; o > 0; o >>= 1)
            z += __shfl_xor_sync(0xffffffffu, z, o);
        float wn = ex / (z + EPS_F);

#pragma unroll 4
        for (int j = 0; j < deg; j++) {
            float w = __shfl_sync(0xffffffffu, wn, j);
            int s  = __shfl_sync(0xffffffffu, s_j, j);
            acc += w * __bfloat162float(hfeat[(size_t)s * 32 + lane]);
        }
    } else {
        float m = -INFINITY;
        for (int j = lane; j < deg; j += 32) {
            int s = g_csrc[base + j];
            float e = asrc[s] + ad;
            e = (e > 0.f) ? e : NEG_SLOPE * e;
            m = fmaxf(m, e);
        }
#pragma unroll
        for (int o = 16; o > 0; o >>= 1)
            m = fmaxf(m, __shfl_xor_sync(0xffffffffu, m, o));
        float z = 0.f;
        for (int j = lane; j < deg; j += 32) {
            int s = g_csrc[base + j];
            float e = asrc[s] + ad;
            e = (e > 0.f) ? e : NEG_SLOPE * e;
            z += __expf(e - m);
        }
#pragma unroll
        for (int o = 16; o > 0; o >>= 1)
            z += __shfl_xor_sync(0xffffffffu, z, o);
        float iz = 1.f / (z + EPS_F);

#pragma unroll 2
        for (int j = 0; j < deg; j++) {
            int s = g_csrc[base + j];
            float e = asrc[s] + ad;
            e = (e > 0.f) ? e : NEG_SLOPE * e;
            float w = __expf(e - m) * iz;
            acc += w * __bfloat162float(hfeat[(size_t)s * 32 + lane]);
        }
    }

    float o = fmaxf(acc + bias[lane], 0.f);
    atomicAdd(&pool[batch[v] * 32 + lane], o);
}

// ---------------------------------------------------------------------------
// MLP head (self-cleans pool)
// ---------------------------------------------------------------------------
__global__ void mlp_kernel(const float* __restrict__ lin_w,
                           const float* __restrict__ lin_b,
                           const float* __restrict__ lin2_w,
                           const float* __restrict__ lin2_b,
                           float* __restrict__ out) {
    cudaGridDependencySynchronize();

    int g = blockIdx.x;
    __shared__ float sg[32];
    __shared__ float sred[256];
    int tid = threadIdx.x;
    float* pool = (float*)(g_zero + N_NODES);
    if (tid < 32) {
        sg[tid] = pool[g * 32 + tid];
        pool[g * 32 + tid] = 0.f;
    }
    __syncthreads();
    float partial = 0.f;
    for (int u = tid; u < 1024; u += 256) {
        float d = lin_b[u];
        const float* wr = lin_w + u * 32;
#pragma unroll
        for (int c = 0; c < 32; c++) d += sg[c] * wr[c];
        d = fmaxf(d, 0.f);
        partial += d * lin2_w[u];
    }
    sred[tid] = partial;
    __syncthreads();
    for (int s = 128; s > 0; s >>= 1) {
        if (tid < s) sred[tid] += sred[tid + s];
        __syncthreads();
    }
    if (tid == 0) {
        float v = sred[0] + lin2_b[0];
        out[g] = 1.f / (1.f + __expf(-v));
    }
}

// ---------------------------------------------------------------------------
// PDL launch helper
// ---------------------------------------------------------------------------
template<typename Kern, typename... Args>
static inline void launch_pdl(Kern k, dim3 grid, dim3 block, size_t smem,
                              Args... args) {
    cudaLaunchConfig_t cfg = {};
    cfg.gridDim = grid;
    cfg.blockDim = block;
    cfg.dynamicSmemBytes = smem;
    cfg.stream = 0;
    cudaLaunchAttribute attr[1];
    attr[0].id = cudaLaunchAttributeProgrammaticStreamSerialization;
    attr[0].val.programmaticStreamSerializationAllowed = 1;
    cfg.attrs = attr;
    cfg.numAttrs = 1;
    cudaLaunchKernelEx(&cfg, k, args...);
}

#define GEMM_SMEM(NSUB) ((3 * A_STAGE_U32 + 3 * (NSUB) * 16 * SROW) * 4)

// ---------------------------------------------------------------------------
// launch
// ---------------------------------------------------------------------------
extern "C" void kernel_launch(void* const* d_in, const int* in_sizes, int n_in,
                              void* d_out, int out_size) {
    const float* x        = (const float*)d_in[0];
    const float* W1       = (const float*)d_in[1];
    const float* att_s1   = (const float*)d_in[2];
    const float* att_d1   = (const float*)d_in[3];
    const float* b1       = (const float*)d_in[4];
    const float* W2       = (const float*)d_in[5];
    const float* att_s2   = (const float*)d_in[6];
    const float* att_d2   = (const float*)d_in[7];
    const float* b2       = (const float*)d_in[8];
    const float* W3       = (const float*)d_in[9];
    const float* att_s3   = (const float*)d_in[10];
    const float* att_d3   = (const float*)d_in[11];
    const float* b3       = (const float*)d_in[12];
    const float* lin_w    = (const float*)d_in[13];
    const float* lin_b    = (const float*)d_in[14];
    const float* lin2_w   = (const float*)d_in[15];
    const float* lin2_b   = (const float*)d_in[16];
    const int*   ei       = (const int*)d_in[17];
    const int*   batch    = (const int*)d_in[18];
    float* out = (float*)d_out;

    __nv_bfloat16 *xq, *w1q, *w2q, *w3q, *h1, *o1, *h2, *o2, *h3;
    float *attbuf;
    cudaGetSymbolAddress((void**)&xq, g_xq);
    cudaGetSymbolAddress((void**)&w1q, g_w1q);
    cudaGetSymbolAddress((void**)&w2q, g_w2q);
    cudaGetSymbolAddress((void**)&w3q, g_w3q);
    cudaGetSymbolAddress((void**)&h1, g_h1);
    cudaGetSymbolAddress((void**)&o1, g_o1);
    cudaGetSymbolAddress((void**)&h2, g_h2);
    cudaGetSymbolAddress((void**)&o2, g_o2);
    cudaGetSymbolAddress((void**)&h3, g_h3);
    cudaGetSymbolAddress((void**)&attbuf, g_att);

    float* as1 = attbuf;                    float* ad1 = attbuf + N_NODES * 5;
    float* as2 = attbuf + 2 * N_NODES * 5;  float* ad2 = attbuf + 3 * N_NODES * 5;
    float* as3 = attbuf + 4 * N_NODES * 5;  float* ad3 = attbuf + 5 * N_NODES * 5;

    static cudaStream_t s_cs = nullptr;
    static cudaEvent_t ev_cnt = nullptr, ev_join = nullptr;
    if (!s_cs) {
        cudaStreamCreateWithFlags(&s_cs, cudaStreamNonBlocking);
        cudaEventCreateWithFlags(&ev_cnt, cudaEventDisableTiming);
        cudaEventCreateWithFlags(&ev_join, cudaEventDisableTiming);
        cudaFuncSetAttribute(gemm_att<10>,
                             cudaFuncAttributeMaxDynamicSharedMemorySize,
                             GEMM_SMEM(10));
        cudaFuncSetAttribute(gemm_att<2>,
                             cudaFuncAttributeMaxDynamicSharedMemorySize,
                             GEMM_SMEM(2));
    }

    // ---- main stream: count first, then prep overlapped via PDL ----
    count_kernel<<<(N_EDGES / 4 + 255) / 256, 256>>>(ei);
    cudaEventRecord(ev_cnt, 0);

    // prep is independent of count (disjoint buffers) — PDL launch with NO
    // internal grid-sync lets it fully overlap count's execution.
    launch_pdl(prep_kernel, dim3((N_NODES * 64 / 4 + 255) / 256), dim3(256),
               (size_t)0, x, W1, W2, W3);

    // ---- side stream: scans + scatter after count ----
    cudaStreamWaitEvent(s_cs, ev_cnt, 0);
    scan1_kernel<<<N_BLK, 256, 0, s_cs>>>();
    scan3_kernel<<<N_BLK, 256, 0, s_cs>>>();
    scatter_kernel<<<(N_EDGES / 4 + N_NODES + 255) / 256, 256, 0, s_cs>>>(ei);
    cudaEventRecord(ev_join, s_cs);

    const int GY = (N_NODES + 127) / 128;

    launch_pdl(gemm_att<10>, dim3(HC1 / 160, GY), dim3(256), GEMM_SMEM(10),
               (const __nv_bfloat16*)xq, (const __nv_bfloat16*)w1q, h1,
               att_s1, att_d1, as1, ad1, N_NODES, HC1, 64, 5, 64, 0);

    // agg1: NORMAL launch (full dependency) — anchors prep + carries CSR join.
    cudaStreamWaitEvent(0, ev_join, 0);
    gat_agg5<64><<<N_NODES, 96>>>(h1, as1, ad1, b1, o1);

    launch_pdl(gemm_att<10>, dim3(HC2 / 160, GY), dim3(256), GEMM_SMEM(10),
               (const __nv_bfloat16*)o1, (const __nv_bfloat16*)w2q, h2,
               att_s2, att_d2, as2, ad2, N_NODES, HC2, HC1, 5, 96, 1);
    launch_pdl(gat_agg5<96>, dim3(N_NODES), dim3(128), (size_t)0,
               (const __nv_bfloat16*)h2,
               (const float*)as2, (const float*)ad2, b2, o2);

    launch_pdl(gemm_att<2>, dim3(1, GY), dim3(256), GEMM_SMEM(2),
               (const __nv_bfloat16*)o2, (const __nv_bfloat16*)w3q, h3,
               att_s3, att_d3, as3, ad3, N_NODES, HC3, HC2, 1, 32, 1);
    launch_pdl(gat_agg1_pool, dim3((N_NODES + 7) / 8), dim3(256), (size_t)0,
               (const __nv_bfloat16*)h3, (const float*)as3, (const float*)ad3,
               b3, batch);

    launch_pdl(mlp_kernel, dim3(N_GRAPHS), dim3(256), (size_t)0,
               lin_w, lin_b, lin2_w, lin2_b, out);
}

// round 17
// speedup vs baseline: 1.2374x; 1.0001x over previous
#include <cuda_runtime.h>
#include <cuda_bf16.h>
#include <math.h>
#include <stdint.h>

// ---------------------------------------------------------------------------
// Problem constants
// ---------------------------------------------------------------------------
#define N_NODES 20000
#define N_EDGES 320000
#define TOT_E   (N_EDGES + N_NODES)
#define N_GRAPHS 128
#define NEG_SLOPE 0.2f
#define EPS_F 1e-16f

#define HC1 320   // H=5, C=64
#define HC2 480   // H=5, C=96
#define HC3 32    // H=1, C=32

#define N_BLK ((N_NODES + 255) / 256)   // 79

// ---------------------------------------------------------------------------
// Device scratch. g_zero (cnt+pool) is SELF-CLEANING.
// ---------------------------------------------------------------------------
__device__ __align__(16) __nv_bfloat16 g_xq[N_NODES * 64];
__device__ __align__(16) __nv_bfloat16 g_w1q[HC1 * 64];
__device__ __align__(16) __nv_bfloat16 g_w2q[HC2 * HC1];
__device__ __align__(16) __nv_bfloat16 g_w3q[HC3 * HC2];
__device__ __align__(16) __nv_bfloat16 g_h1[N_NODES * HC1];
__device__ __align__(16) __nv_bfloat16 g_o1[N_NODES * HC1];
__device__ __align__(16) __nv_bfloat16 g_h2[N_NODES * HC2];
__device__ __align__(16) __nv_bfloat16 g_o2[N_NODES * HC2];
__device__ __align__(16) __nv_bfloat16 g_h3[N_NODES * HC3];
__device__ float g_att[6 * N_NODES * 5];
__device__ int   g_zero[N_NODES + N_GRAPHS * 32];   // cnt | pool
__device__ int   g_rowptr[N_NODES + 1];
__device__ int   g_cursor[N_NODES];
__device__ int   g_csrc[TOT_E];
__device__ int   g_bsum[N_BLK];

__device__ __forceinline__ uint32_t pack_bf16x2(float lo, float hi) {
    __nv_bfloat162 h2 = __floats2bfloat162_rn(lo, hi);
    return *(uint32_t*)&h2;
}

// ---------------------------------------------------------------------------
// prep: x->bf16, W->bf16, zero att. NO grid-dep sync: runs under PDL fully
// overlapped with count_kernel (disjoint buffers).
// ---------------------------------------------------------------------------
#define W1Q4 (HC1 * 64 / 4)
#define W2Q4 (HC2 * HC1 / 4)
#define W3Q4 (HC3 * HC2 / 4)

__global__ void prep_kernel(const float* __restrict__ x,
                            const float* __restrict__ W1,
                            const float* __restrict__ W2,
                            const float* __restrict__ W3) {
    int i = blockIdx.x * 256 + threadIdx.x;
    if (i < N_NODES * 64 / 4) {
        float4 v = ((const float4*)x)[i];
        uint2 p;
        p.x = pack_bf16x2(v.x, v.y);
        p.y = pack_bf16x2(v.z, v.w);
        ((uint2*)g_xq)[i] = p;
    }
    if (2 * i < 6 * N_NODES * 5) {
        g_att[2 * i] = 0.f;
        if (2 * i + 1 < 6 * N_NODES * 5) g_att[2 * i + 1] = 0.f;
    }
    if (i < W1Q4 + W2Q4 + W3Q4) {
        const float4* src;
        uint2* dst;
        int j = i;
        if (j < W1Q4)                { src = (const float4*)W1; dst = (uint2*)g_w1q; }
        else if ((j -= W1Q4) < W2Q4) { src = (const float4*)W2; dst = (uint2*)g_w2q; }
        else { j -= W2Q4;              src = (const float4*)W3; dst = (uint2*)g_w3q; }
        float4 v = src[j];
        uint2 p;
        p.x = pack_bf16x2(v.x, v.y);
        p.y = pack_bf16x2(v.z, v.w);
        dst[j] = p;
    }
}

// ---------------------------------------------------------------------------
// CSR construction. 4 edges per thread (atomic MLP=4, latency-bound path).
// ---------------------------------------------------------------------------
__global__ void count_kernel(const int* __restrict__ ei) {
    int i = blockIdx.x * blockDim.x + threadIdx.x;
    if (i < N_EDGES / 4) {
        int4 d = ((const int4*)(ei + N_EDGES))[i];
        atomicAdd(&g_zero[d.x], 1);
        atomicAdd(&g_zero[d.y], 1);
        atomicAdd(&g_zero[d.z], 1);
        atomicAdd(&g_zero[d.w], 1);
    }
}

__global__ void scan1_kernel() {
    int i = blockIdx.x * 256 + threadIdx.x;
    int lane = threadIdx.x & 31, w = threadIdx.x >> 5;
    int x = (i < N_NODES) ? (g_zero[i] + 1) : 0;
#pragma unroll
    for (int o = 1; o < 32; o <<= 1) {
        int t = __shfl_up_sync(0xffffffffu, x, o);
        if (lane >= o) x += t;
    }
    __shared__ int wsum[8];
    if (lane == 31) wsum[w] = x;
    __syncthreads();
    if (w == 0) {
        int s = (lane < 8) ? wsum[lane] : 0;
#pragma unroll
        for (int o = 1; o < 8; o <<= 1) {
            int t = __shfl_up_sync(0xffffffffu, s, o);
            if (lane >= o) s += t;
        }
        if (lane < 8) wsum[lane] = s;
    }
    __syncthreads();
    int incl = x + ((w > 0) ? wsum[w - 1] : 0);
    if (i < N_NODES) g_rowptr[i + 1] = incl;
    if (threadIdx.x == 255) g_bsum[blockIdx.x] = incl;
}

__global__ void scan3_kernel() {
    __shared__ int s_off;
    int tid = threadIdx.x, lane = tid & 31;
    if (tid < 32) {
        int off = 0;
        for (int j = lane; j < blockIdx.x; j += 32) off += g_bsum[j];
#pragma unroll
        for (int o = 16; o > 0; o >>= 1)
            off += __shfl_xor_sync(0xffffffffu, off, o);
        if (lane == 0) s_off = off;
    }
    __syncthreads();
    int i = blockIdx.x * 256 + tid;
    if (i == 0) g_rowptr[0] = 0;
    if (i < N_NODES) {
        int incl = g_rowptr[i + 1] + s_off;
        g_rowptr[i + 1] = incl;
        g_cursor[i] = incl - (g_zero[i] + 1);
        g_zero[i] = 0;                       // self-clean
    }
}

// 4 edges per thread; self loops appended
__global__ void scatter_kernel(const int* __restrict__ ei) {
    int i = blockIdx.x * blockDim.x + threadIdx.x;
    const int Q = N_EDGES / 4;
    if (i < Q) {
        int4 s = ((const int4*)ei)[i];
        int4 d = ((const int4*)(ei + N_EDGES))[i];
        int p0 = atomicAdd(&g_cursor[d.x], 1);
        int p1 = atomicAdd(&g_cursor[d.y], 1);
        int p2 = atomicAdd(&g_cursor[d.z], 1);
        int p3 = atomicAdd(&g_cursor[d.w], 1);
        g_csrc[p0] = s.x;
        g_csrc[p1] = s.y;
        g_csrc[p2] = s.z;
        g_csrc[p3] = s.w;
    } else if (i < Q + N_NODES) {
        int v = i - Q;
        int pos = atomicAdd(&g_cursor[v], 1);
        g_csrc[pos] = v;
    }
}

// ---------------------------------------------------------------------------
// bf16 GEMM, 3-stage cp.async pipeline + fused attention epilogue + PDL.
// NSUB=10 -> BN=160 (exact tiling for 320/480). NSUB=2 -> BN=32 (layer 3).
// ---------------------------------------------------------------------------
#define SROW 20
#define A_STAGE_U32 (128 * SROW)

__device__ __forceinline__ void cp16(uint32_t dst, const void* src, int bytes) {
    asm volatile("cp.async.cg.shared.global [%0], [%1], 16, %2;"
                 :: "r"(dst), "l"(src), "r"(bytes));
}
__device__ __forceinline__ void cp_commit() {
    asm volatile("cp.async.commit_group;");
}
template<int N>
__device__ __forceinline__ void cp_wait() {
    asm volatile("cp.async.wait_group %0;" :: "n"(N));
}

template<int NSUB>
__global__ void __launch_bounds__(256, 2)
gemm_att(const __nv_bfloat16* __restrict__ A, const __nv_bfloat16* __restrict__ B,
         __nv_bfloat16* __restrict__ C,
         const float* __restrict__ att_src, const float* __restrict__ att_dst,
         float* __restrict__ asrc, float* __restrict__ adst,
         int N, int M, int K, int H, int Cc, int prefetchB) {
    const int BN = NSUB * 16, BK = 32;
    const int B_STAGE_U32 = BN * SROW;
    extern __shared__ uint32_t dynsmem[];
    uint32_t* AsBase = dynsmem;
    uint32_t* BsBase = dynsmem + 3 * A_STAGE_U32;

    int tid  = threadIdx.x;
    int lane = tid & 31;
    int wid  = tid >> 5;
    int wr = (wid & 3) * 32;
    int wc = (wid >> 2) * (BN / 2);
    int gid = lane >> 2;
    int tig = lane & 3;

    int blockRow = blockIdx.y * 128;
    int blockCol = blockIdx.x * BN;

    int r0c = (tid + 0)   >> 2, q0 = (tid + 0)   & 3;
    int r1c = (tid + 256) >> 2, q1 = (tid + 256) & 3;

    uint32_t asm0 = (uint32_t)__cvta_generic_to_shared(AsBase);
    uint32_t bsm0 = (uint32_t)__cvta_generic_to_shared(BsBase);

    auto issueA = [&](int k0, int st) {
        uint32_t base = asm0 + st * (A_STAGE_U32 * 4);
        int ba0 = (blockRow + r0c < N) ? 16 : 0;
        int ba1 = (blockRow + r1c < N) ? 16 : 0;
        cp16(base + (r0c * SROW + q0 * 4) * 4,
             A + (size_t)(blockRow + r0c) * K + k0 + q0 * 8, ba0);
        cp16(base + (r1c * SROW + q1 * 4) * 4,
             A + (size_t)(blockRow + r1c) * K + k0 + q1 * 8, ba1);
    };
    auto issueB = [&](int k0, int st) {
        uint32_t base = bsm0 + st * (B_STAGE_U32 * 4);
        for (int c = tid; c < BN * 4; c += 256) {
            int row = c >> 2, q = c & 3;
            int bb = (blockCol + row < M) ? 16 : 0;
            cp16(base + (row * SROW + q * 4) * 4,
                 B + (size_t)(blockCol + row) * K + k0 + q * 8, bb);
        }
    };

    float acc[2][NSUB][4];
#pragma unroll
    for (int mt = 0; mt < 2; mt++)
#pragma unroll
        for (int nt = 0; nt < NSUB; nt++)
#pragma unroll
            for (int i = 0; i < 4; i++) acc[mt][nt][i] = 0.f;

    int nIt = K / BK;

    if (prefetchB) issueB(0, 0);
    cudaGridDependencySynchronize();
    issueA(0, 0);
    if (!prefetchB) issueB(0, 0);
    cp_commit();
    if (nIt > 1) {
        issueA(BK, 1);
        issueB(BK, 1);
        cp_commit();
    }

    for (int it = 0; it < nIt; it++) {
        int buf = it % 3;
        if (it + 2 < nIt) {
            issueA((it + 2) * BK, (it + 2) % 3);
            issueB((it + 2) * BK, (it + 2) % 3);
            cp_commit();
            cp_wait<2>();
        } else if (it + 1 < nIt) {
            cp_wait<1>();
        } else {
            cp_wait<0>();
        }
        __syncthreads();

        const uint32_t* As = AsBase + buf * A_STAGE_U32;
        const uint32_t* Bs = BsBase + buf * B_STAGE_U32;

#pragma unroll
        for (int ks = 0; ks < 2; ks++) {
            int kb = ks * 8;
            uint32_t a[2][4], b[NSUB][2];
#pragma unroll
            for (int mt = 0; mt < 2; mt++) {
                int r0 = wr + mt * 16;
                a[mt][0] = As[(r0 + gid    ) * SROW + kb + tig    ];
                a[mt][1] = As[(r0 + gid + 8) * SROW + kb + tig    ];
                a[mt][2] = As[(r0 + gid    ) * SROW + kb + tig + 4];
                a[mt][3] = As[(r0 + gid + 8) * SROW + kb + tig + 4];
            }
#pragma unroll
            for (int nt = 0; nt < NSUB; nt++) {
                int n0 = wc + nt * 8 + gid;
                b[nt][0] = Bs[n0 * SROW + kb + tig    ];
                b[nt][1] = Bs[n0 * SROW + kb + tig + 4];
            }
#pragma unroll
            for (int mt = 0; mt < 2; mt++)
#pragma unroll
                for (int nt = 0; nt < NSUB; nt++) {
                    asm volatile(
                        "mma.sync.aligned.m16n8k16.row.col.f32.bf16.bf16.f32 "
                        "{%0,%1,%2,%3}, {%4,%5,%6,%7}, {%8,%9}, {%0,%1,%2,%3};"
                        : "+f"(acc[mt][nt][0]), "+f"(acc[mt][nt][1]),
                          "+f"(acc[mt][nt][2]), "+f"(acc[mt][nt][3])
                        : "r"(a[mt][0]), "r"(a[mt][1]), "r"(a[mt][2]), "r"(a[mt][3]),
                          "r"(b[nt][0]), "r"(b[nt][1]));
                }
        }
        __syncthreads();
    }

    int h_first = (blockCol + wc) / Cc;
    float psrc[2][2][2] = {};
    float pdst[2][2][2] = {};

#pragma unroll
    for (int mt = 0; mt < 2; mt++) {
#pragma unroll
        for (int nt = 0; nt < NSUB; nt++) {
            int r0 = blockRow + wr + mt * 16 + gid;
            int c0 = blockCol + wc + nt * 8 + tig * 2;
            if (c0 < M) {
                if (r0 < N)
                    *(uint32_t*)(C + (size_t)r0 * M + c0) =
                        pack_bf16x2(acc[mt][nt][0], acc[mt][nt][1]);
                if (r0 + 8 < N)
                    *(uint32_t*)(C + (size_t)(r0 + 8) * M + c0) =
                        pack_bf16x2(acc[mt][nt][2], acc[mt][nt][3]);
                int hb = (blockCol + wc + nt * 8) / Cc - h_first;
                float a0 = att_src[c0], a1 = att_src[c0 + 1];
                float d0 = att_dst[c0], d1 = att_dst[c0 + 1];
                psrc[mt][0][hb] += acc[mt][nt][0] * a0 + acc[mt][nt][1] * a1;
                psrc[mt][1][hb] += acc[mt][nt][2] * a0 + acc[mt][nt][3] * a1;
                pdst[mt][0][hb] += acc[mt][nt][0] * d0 + acc[mt][nt][1] * d1;
                pdst[mt][1][hb] += acc[mt][nt][2] * d0 + acc[mt][nt][3] * d1;
            }
        }
    }
#pragma unroll
    for (int mt = 0; mt < 2; mt++)
#pragma unroll
        for (int hf = 0; hf < 2; hf++)
#pragma unroll
            for (int bk = 0; bk < 2; bk++) {
                float s = psrc[mt][hf][bk], d = pdst[mt][hf][bk];
                s += __shfl_xor_sync(0xffffffffu, s, 1);
                s += __shfl_xor_sync(0xffffffffu, s, 2);
                d += __shfl_xor_sync(0xffffffffu, d, 1);
                d += __shfl_xor_sync(0xffffffffu, d, 2);
                psrc[mt][hf][bk] = s; pdst[mt][hf][bk] = d;
            }
    if (tig == 0) {
#pragma unroll
        for (int mt = 0; mt < 2; mt++)
#pragma unroll
            for (int hf = 0; hf < 2; hf++) {
                int row = blockRow + wr + mt * 16 + gid + hf * 8;
                if (row >= N) continue;
#pragma unroll
                for (int bk = 0; bk < 2; bk++) {
                    int hidx = h_first + bk;
                    if (hidx < H) {
                        atomicAdd(&asrc[row * H + hidx], psrc[mt][hf][bk]);
                        atomicAdd(&adst[row * H + hidx], pdst[mt][hf][bk]);
                    }
                }
            }
    }
}

// ---------------------------------------------------------------------------
// GAT aggregation, H=5. Warp 0 softmax (all heads), gather unroll 4.
// ---------------------------------------------------------------------------
template<int C>
__global__ void __launch_bounds__(128)
gat_agg5(const __nv_bfloat16* __restrict__ hfeat,
         const float* __restrict__ asrc,
         const float* __restrict__ adst,
         const float* __restrict__ bias,
         __nv_bfloat16* __restrict__ out) {
    const int HC = 5 * C, NC4 = HC / 4;
    const int EMAX = 128;
    __shared__ float s_e[EMAX * 5];
    __shared__ int   s_src[EMAX];
    __shared__ float s_m[5], s_iz[5];

    cudaGridDependencySynchronize();

    int v = blockIdx.x;
    int tid = threadIdx.x, lane = tid & 31, wid = tid >> 5;
    int base = g_rowptr[v];
    int deg = g_rowptr[v + 1] - base;

    float4 acc = make_float4(0.f, 0.f, 0.f, 0.f);
    int head = (tid * 4) / C;

    if (deg <= 32) {
        if (wid == 0) {
            int s = 0;
            float e[5];
            if (lane < deg) {
                s = g_csrc[base + lane];
                s_src[lane] = s;
#pragma unroll
                for (int h = 0; h < 5; h++) {
                    float t = asrc[s * 5 + h] + adst[v * 5 + h];
                    e[h] = (t > 0.f) ? t : NEG_SLOPE * t;
                }
            } else {
#pragma unroll
                for (int h = 0; h < 5; h++) e[h] = -INFINITY;
            }
#pragma unroll
            for (int h = 0; h < 5; h++) {
                float m = e[h];
#pragma unroll
                for (int o = 16; o > 0; o >>= 1)
                    m = fmaxf(m, __shfl_xor_sync(0xffffffffu, m, o));
                float ex = (lane < deg) ? __expf(e[h] - m) : 0.f;
                float z = ex;
#pragma unroll
                for (int o = 16; o > 0; o >>= 1)
                    z += __shfl_xor_sync(0xffffffffu, z, o);
                if (lane < deg) s_e[lane * 5 + h] = ex / (z + EPS_F);
            }
        }
        __syncthreads();
        if (tid < NC4) {
#pragma unroll 4
            for (int j = 0; j < deg; j++) {
                const uint2* hp = (const uint2*)(hfeat + (size_t)s_src[j] * HC);
                float w = s_e[j * 5 + head];
                uint2 hv = hp[tid];
                float2 lo = __bfloat1622float2(*(__nv_bfloat162*)&hv.x);
                float2 hi = __bfloat1622float2(*(__nv_bfloat162*)&hv.y);
                acc.x += w * lo.x; acc.y += w * lo.y;
                acc.z += w * hi.x; acc.w += w * hi.y;
            }
        }
    } else {
        if (wid == 0) {
#pragma unroll
            for (int h = 0; h < 5; h++) {
                float ad = adst[v * 5 + h];
                float m = -INFINITY;
                for (int j = lane; j < deg; j += 32) {
                    int s = g_csrc[base + j];
                    float e = asrc[s * 5 + h] + ad;
                    e = (e > 0.f) ? e : NEG_SLOPE * e;
                    m = fmaxf(m, e);
                }
#pragma unroll
                for (int o = 16; o > 0; o >>= 1)
                    m = fmaxf(m, __shfl_xor_sync(0xffffffffu, m, o));
                float z = 0.f;
                for (int j = lane; j < deg; j += 32) {
                    int s = g_csrc[base + j];
                    float e = asrc[s * 5 + h] + ad;
                    e = (e > 0.f) ? e : NEG_SLOPE * e;
                    z += __expf(e - m);
                }
#pragma unroll
                for (int o = 16; o > 0; o >>= 1)
                    z += __shfl_xor_sync(0xffffffffu, z, o);
                if (lane == 0) { s_m[h] = m; s_iz[h] = 1.f / (z + EPS_F); }
            }
        }
        __syncthreads();
        for (int j0 = 0; j0 < deg; j0 += EMAX) {
            int ch = min(EMAX, deg - j0);
            for (int idx = tid; idx < ch * 5; idx += blockDim.x) {
                int j = idx / 5, hh = idx - j * 5;
                int s = g_csrc[base + j0 + j];
                if (hh == 0) s_src[j] = s;
                float e = asrc[s * 5 + hh] + adst[v * 5 + hh];
                e = (e > 0.f) ? e : NEG_SLOPE * e;
                s_e[j * 5 + hh] = __expf(e - s_m[hh]) * s_iz[hh];
            }
            __syncthreads();
            if (tid < NC4) {
                for (int j = 0; j < ch; j++) {
                    const uint2* hp = (const uint2*)(hfeat + (size_t)s_src[j] * HC);
                    float w = s_e[j * 5 + head];
                    uint2 hv = hp[tid];
                    float2 lo = __bfloat1622float2(*(__nv_bfloat162*)&hv.x);
                    float2 hi = __bfloat1622float2(*(__nv_bfloat162*)&hv.y);
                    acc.x += w * lo.x; acc.y += w * lo.y;
                    acc.z += w * hi.x; acc.w += w * hi.y;
                }
            }
            __syncthreads();
        }
    }

    if (tid < NC4) {
        float4 b = ((const float4*)bias)[tid];
        uint2 o;
        o.x = pack_bf16x2(fmaxf(acc.x + b.x, 0.f), fmaxf(acc.y + b.y, 0.f));
        o.y = pack_bf16x2(fmaxf(acc.z + b.z, 0.f), fmaxf(acc.w + b.w, 0.f));
        ((uint2*)(out + (size_t)v * HC))[tid] = o;
    }
}

// ---------------------------------------------------------------------------
// GAT aggregation, H=1, C=32 + fused pool. warp per node.
// ---------------------------------------------------------------------------
__global__ void __launch_bounds__(256)
gat_agg1_pool(const __nv_bfloat16* __restrict__ hfeat,
              const float* __restrict__ asrc,
              const float* __restrict__ adst,
              const float* __restrict__ bias,
              const int* __restrict__ batch) {
    cudaGridDependencySynchronize();

    int wid = threadIdx.x >> 5, lane = threadIdx.x & 31;
    int v = blockIdx.x * 8 + wid;
    if (v >= N_NODES) return;
    int base = g_rowptr[v];
    int deg = g_rowptr[v + 1] - base;
    float ad = adst[v];
    float* pool = (float*)(g_zero + N_NODES);
    float acc = 0.f;

    if (deg <= 32) {
        int s_j = 0;
        float e = -INFINITY;
        if (lane < deg) {
            s_j = g_csrc[base + lane];
            e = asrc[s_j] + ad;
            e = (e > 0.f) ? e : NEG_SLOPE * e;
        }
        float m = e;
#pragma unroll
        for (int o = 16; o > 0; o >>= 1)
            m = fmaxf(m, __shfl_xor_sync(0xffffffffu, m, o));
        float ex = (lane < deg) ? __expf(e - m) : 0.f;
        float z = ex;
#pragma unroll
        for (int o = 16; o > 0; o >>= 1)
            z += __shfl_xor_sync(0xffffffffu, z, o);
        float wn = ex / (z + EPS_F);

#pragma unroll 4
        for (int j = 0; j < deg; j++) {
            float w = __shfl_sync(0xffffffffu, wn, j);
            int s  = __shfl_sync(0xffffffffu, s_j, j);
            acc += w * __bfloat162float(hfeat[(size_t)s * 32 + lane]);
        }
    } else {
        float m = -INFINITY;
        for (int j = lane; j < deg; j += 32) {
            int s = g_csrc[base + j];
            float e = asrc[s] + ad;
            e = (e > 0.f) ? e : NEG_SLOPE * e;
            m = fmaxf(m, e);
        }
#pragma unroll
        for (int o = 16; o > 0; o >>= 1)
            m = fmaxf(m, __shfl_xor_sync(0xffffffffu, m, o));
        float z = 0.f;
        for (int j = lane; j < deg; j += 32) {
            int s = g_csrc[base + j];
            float e = asrc[s] + ad;
            e = (e > 0.f) ? e : NEG_SLOPE * e;
            z += __expf(e - m);
        }
#pragma unroll
        for (int o = 16; o > 0; o >>= 1)
            z += __shfl_xor_sync(0xffffffffu, z, o);
        float iz = 1.f / (z + EPS_F);

#pragma unroll 2
        for (int j = 0; j < deg; j++) {
            int s = g_csrc[base + j];
            float e = asrc[s] + ad;
            e = (e > 0.f) ? e : NEG_SLOPE * e;
            float w = __expf(e - m) * iz;
            acc += w * __bfloat162float(hfeat[(size_t)s * 32 + lane]);
        }
    }

    float o = fmaxf(acc + bias[lane], 0.f);
    atomicAdd(&pool[batch[v] * 32 + lane], o);
}

// ---------------------------------------------------------------------------
// MLP head (self-cleans pool)
// ---------------------------------------------------------------------------
__global__ void mlp_kernel(const float* __restrict__ lin_w,
                           const float* __restrict__ lin_b,
                           const float* __restrict__ lin2_w,
                           const float* __restrict__ lin2_b,
                           float* __restrict__ out) {
    cudaGridDependencySynchronize();

    int g = blockIdx.x;
    __shared__ float sg[32];
    __shared__ float sred[256];
    int tid = threadIdx.x;
    float* pool = (float*)(g_zero + N_NODES);
    if (tid < 32) {
        sg[tid] = pool[g * 32 + tid];
        pool[g * 32 + tid] = 0.f;
    }
    __syncthreads();
    float partial = 0.f;
    for (int u = tid; u < 1024; u += 256) {
        float d = lin_b[u];
        const float* wr = lin_w + u * 32;
#pragma unroll
        for (int c = 0; c < 32; c++) d += sg[c] * wr[c];
        d = fmaxf(d, 0.f);
        partial += d * lin2_w[u];
    }
    sred[tid] = partial;
    __syncthreads();
    for (int s = 128; s > 0; s >>= 1) {
        if (tid < s) sred[tid] += sred[tid + s];
        __syncthreads();
    }
    if (tid == 0) {
        float v = sred[0] + lin2_b[0];
        out[g] = 1.f / (1.f + __expf(-v));
    }
}

// ---------------------------------------------------------------------------
// PDL launch helper
// ---------------------------------------------------------------------------
template<typename Kern, typename... Args>
static inline void launch_pdl(Kern k, dim3 grid, dim3 block, size_t smem,
                              Args... args) {
    cudaLaunchConfig_t cfg = {};
    cfg.gridDim = grid;
    cfg.blockDim = block;
    cfg.dynamicSmemBytes = smem;
    cfg.stream = 0;
    cudaLaunchAttribute attr[1];
    attr[0].id = cudaLaunchAttributeProgrammaticStreamSerialization;
    attr[0].val.programmaticStreamSerializationAllowed = 1;
    cfg.attrs = attr;
    cfg.numAttrs = 1;
    cudaLaunchKernelEx(&cfg, k, args...);
}

#define GEMM_SMEM(NSUB) ((3 * A_STAGE_U32 + 3 * (NSUB) * 16 * SROW) * 4)

// ---------------------------------------------------------------------------
// launch
// ---------------------------------------------------------------------------
extern "C" void kernel_launch(void* const* d_in, const int* in_sizes, int n_in,
                              void* d_out, int out_size) {
    const float* x        = (const float*)d_in[0];
    const float* W1       = (const float*)d_in[1];
    const float* att_s1   = (const float*)d_in[2];
    const float* att_d1   = (const float*)d_in[3];
    const float* b1       = (const float*)d_in[4];
    const float* W2       = (const float*)d_in[5];
    const float* att_s2   = (const float*)d_in[6];
    const float* att_d2   = (const float*)d_in[7];
    const float* b2       = (const float*)d_in[8];
    const float* W3       = (const float*)d_in[9];
    const float* att_s3   = (const float*)d_in[10];
    const float* att_d3   = (const float*)d_in[11];
    const float* b3       = (const float*)d_in[12];
    const float* lin_w    = (const float*)d_in[13];
    const float* lin_b    = (const float*)d_in[14];
    const float* lin2_w   = (const float*)d_in[15];
    const float* lin2_b   = (const float*)d_in[16];
    const int*   ei       = (const int*)d_in[17];
    const int*   batch    = (const int*)d_in[18];
    float* out = (float*)d_out;

    __nv_bfloat16 *xq, *w1q, *w2q, *w3q, *h1, *o1, *h2, *o2, *h3;
    float *attbuf;
    cudaGetSymbolAddress((void**)&xq, g_xq);
    cudaGetSymbolAddress((void**)&w1q, g_w1q);
    cudaGetSymbolAddress((void**)&w2q, g_w2q);
    cudaGetSymbolAddress((void**)&w3q, g_w3q);
    cudaGetSymbolAddress((void**)&h1, g_h1);
    cudaGetSymbolAddress((void**)&o1, g_o1);
    cudaGetSymbolAddress((void**)&h2, g_h2);
    cudaGetSymbolAddress((void**)&o2, g_o2);
    cudaGetSymbolAddress((void**)&h3, g_h3);
    cudaGetSymbolAddress((void**)&attbuf, g_att);

    float* as1 = attbuf;                    float* ad1 = attbuf + N_NODES * 5;
    float* as2 = attbuf + 2 * N_NODES * 5;  float* ad2 = attbuf + 3 * N_NODES * 5;
    float* as3 = attbuf + 4 * N_NODES * 5;  float* ad3 = attbuf + 5 * N_NODES * 5;

    static cudaStream_t s_cs = nullptr;
    static cudaEvent_t ev_cnt = nullptr, ev_join = nullptr;
    if (!s_cs) {
        cudaStreamCreateWithFlags(&s_cs, cudaStreamNonBlocking);
        cudaEventCreateWithFlags(&ev_cnt, cudaEventDisableTiming);
        cudaEventCreateWithFlags(&ev_join, cudaEventDisableTiming);
        cudaFuncSetAttribute(gemm_att<10>,
                             cudaFuncAttributeMaxDynamicSharedMemorySize,
                             GEMM_SMEM(10));
        cudaFuncSetAttribute(gemm_att<2>,
                             cudaFuncAttributeMaxDynamicSharedMemorySize,
                             GEMM_SMEM(2));
    }

    // ---- main stream: count first, then prep overlapped via PDL ----
    count_kernel<<<(N_EDGES / 4 + 255) / 256, 256>>>(ei);
    cudaEventRecord(ev_cnt, 0);

    // prep is independent of count (disjoint buffers) — PDL launch with NO
    // internal grid-sync lets it fully overlap count's execution.
    launch_pdl(prep_kernel, dim3((N_NODES * 64 / 4 + 255) / 256), dim3(256),
               (size_t)0, x, W1, W2, W3);

    // ---- side stream: scans + scatter after count ----
    cudaStreamWaitEvent(s_cs, ev_cnt, 0);
    scan1_kernel<<<N_BLK, 256, 0, s_cs>>>();
    scan3_kernel<<<N_BLK, 256, 0, s_cs>>>();
    scatter_kernel<<<(N_EDGES / 4 + N_NODES + 255) / 256, 256, 0, s_cs>>>(ei);
    cudaEventRecord(ev_join, s_cs);

    const int GY = (N_NODES + 127) / 128;

    launch_pdl(gemm_att<10>, dim3(HC1 / 160, GY), dim3(256), GEMM_SMEM(10),
               (const __nv_bfloat16*)xq, (const __nv_bfloat16*)w1q, h1,
               att_s1, att_d1, as1, ad1, N_NODES, HC1, 64, 5, 64, 0);

    // agg1: NORMAL launch (full dependency) — anchors prep + carries CSR join.
    cudaStreamWaitEvent(0, ev_join, 0);
    gat_agg5<64><<<N_NODES, 96>>>(h1, as1, ad1, b1, o1);

    launch_pdl(gemm_att<10>, dim3(HC2 / 160, GY), dim3(256), GEMM_SMEM(10),
               (const __nv_bfloat16*)o1, (const __nv_bfloat16*)w2q, h2,
               att_s2, att_d2, as2, ad2, N_NODES, HC2, HC1, 5, 96, 1);
    launch_pdl(gat_agg5<96>, dim3(N_NODES), dim3(128), (size_t)0,
               (const __nv_bfloat16*)h2,
               (const float*)as2, (const float*)ad2, b2, o2);

    launch_pdl(gemm_att<2>, dim3(1, GY), dim3(256), GEMM_SMEM(2),
               (const __nv_bfloat16*)o2, (const __nv_bfloat16*)w3q, h3,
               att_s3, att_d3, as3, ad3, N_NODES, HC3, HC2, 1, 32, 1);
    launch_pdl(gat_agg1_pool, dim3((N_NODES + 7) / 8), dim3(256), (size_t)0,
               (const __nv_bfloat16*)h3, (const float*)as3, (const float*)ad3,
               b3, batch);

    launch_pdl(mlp_kernel, dim3(N_GRAPHS), dim3(256), (size_t)0,
               lin_w, lin_b, lin2_w, lin2_b, out);
}